// round 1
// baseline (speedup 1.0000x reference)
#include <cuda_runtime.h>

#define Bn 32
#define Ln 512
#define Hn 256
#define NHn 4
#define DHn 64

// ---------------- scratch (device globals; no allocation) ----------------
__device__ float g_q[Bn * Ln * Hn];
__device__ float g_k[Bn * Ln * Hn];
__device__ float g_v[Bn * Ln * Hn];
__device__ float g_tq[Bn * Ln * Hn];
__device__ float g_gate[Bn * Ln * Ln];   // sigmoid(decay_gate)/sqrt(DH)
__device__ float g_ctx[Bn * Ln * Hn];

#define FMA16(a4, b4, acc)                                        \
    do {                                                          \
        float _ar[4] = {(a4).x, (a4).y, (a4).z, (a4).w};          \
        float _br[4] = {(b4).x, (b4).y, (b4).z, (b4).w};          \
        _Pragma("unroll") for (int _i = 0; _i < 4; ++_i)          \
            _Pragma("unroll") for (int _j = 0; _j < 4; ++_j)      \
                acc[_i][_j] += _ar[_i] * _br[_j];                 \
    } while (0)

// ---------------- K0: fused Q/K/V/TQ projection -------------------------
// C(16384, 1024) = x(16384,256) @ [Wq;Wk;Wv;Wtq]^T + bias, split to 4 outputs.
__global__ __launch_bounds__(256) void proj_kernel(
    const float* __restrict__ x,
    const float* __restrict__ Wq, const float* __restrict__ bq,
    const float* __restrict__ Wk, const float* __restrict__ bk,
    const float* __restrict__ Wv, const float* __restrict__ bv,
    const float* __restrict__ Wtq, const float* __restrict__ btq)
{
    __shared__ float As[16][68];
    __shared__ float Bs[16][68];
    const int t = threadIdx.x;
    const int tx = t & 15, ty = t >> 4;
    const int m0 = blockIdx.x * 64;
    const int by = blockIdx.y;
    const int wsel = by >> 2;
    const int n0 = (by & 3) * 64;

    const float* W;
    const float* bias;
    float* out;
    if (wsel == 0)      { W = Wq;  bias = bq;  out = g_q;  }
    else if (wsel == 1) { W = Wk;  bias = bk;  out = g_k;  }
    else if (wsel == 2) { W = Wv;  bias = bv;  out = g_v;  }
    else                { W = Wtq; bias = btq; out = g_tq; }

    float acc[4][4] = {};
    const int lr = t >> 2;        // 0..63
    const int lk = (t & 3) * 4;   // 0,4,8,12

    for (int k0 = 0; k0 < Hn; k0 += 16) {
        float4 av = *(const float4*)&x[(size_t)(m0 + lr) * Hn + k0 + lk];
        float4 wv = *(const float4*)&W[(size_t)(n0 + lr) * Hn + k0 + lk];
        As[lk + 0][lr] = av.x; As[lk + 1][lr] = av.y;
        As[lk + 2][lr] = av.z; As[lk + 3][lr] = av.w;
        Bs[lk + 0][lr] = wv.x; Bs[lk + 1][lr] = wv.y;
        Bs[lk + 2][lr] = wv.z; Bs[lk + 3][lr] = wv.w;
        __syncthreads();
#pragma unroll
        for (int kk = 0; kk < 16; ++kk) {
            float4 a4 = *(const float4*)&As[kk][4 * ty];
            float4 b4 = *(const float4*)&Bs[kk][4 * tx];
            FMA16(a4, b4, acc);
        }
        __syncthreads();
    }
#pragma unroll
    for (int i = 0; i < 4; ++i)
#pragma unroll
        for (int j = 0; j < 4; ++j) {
            int n = n0 + 4 * tx + j;
            out[(size_t)(m0 + 4 * ty + i) * Hn + n] = acc[i][j] + bias[n];
        }
}

// ---------------- K1: time-decay gate ------------------------------------
// per batch: tqk = tq @ x^T ; gate = sigmoid(tow1*tanh(log1p|dt|*tw1+tb1)
//                                           + tow2*tanh(tqk) + tob) / 8
__global__ __launch_bounds__(256) void gate_kernel(
    const float* __restrict__ x, const float* __restrict__ tseq,
    const float* __restrict__ tw1, const float* __restrict__ tb1,
    const float* __restrict__ tow1, const float* __restrict__ tow2,
    const float* __restrict__ tob)
{
    __shared__ float As[16][68];
    __shared__ float Bs[16][68];
    const int t = threadIdx.x;
    const int tx = t & 15, ty = t >> 4;
    const int b = blockIdx.z;
    const int m0 = blockIdx.x * 64;   // query rows
    const int n0 = blockIdx.y * 64;   // key cols
    const float* A = g_tq + (size_t)b * Ln * Hn;
    const float* Bm = x + (size_t)b * Ln * Hn;

    float acc[4][4] = {};
    const int lr = t >> 2;
    const int lk = (t & 3) * 4;
    for (int k0 = 0; k0 < Hn; k0 += 16) {
        float4 av = *(const float4*)&A[(size_t)(m0 + lr) * Hn + k0 + lk];
        float4 bv = *(const float4*)&Bm[(size_t)(n0 + lr) * Hn + k0 + lk];
        As[lk + 0][lr] = av.x; As[lk + 1][lr] = av.y;
        As[lk + 2][lr] = av.z; As[lk + 3][lr] = av.w;
        Bs[lk + 0][lr] = bv.x; Bs[lk + 1][lr] = bv.y;
        Bs[lk + 2][lr] = bv.z; Bs[lk + 3][lr] = bv.w;
        __syncthreads();
#pragma unroll
        for (int kk = 0; kk < 16; ++kk) {
            float4 a4 = *(const float4*)&As[kk][4 * ty];
            float4 b4 = *(const float4*)&Bs[kk][4 * tx];
            FMA16(a4, b4, acc);
        }
        __syncthreads();
    }

    float tr[4], tc[4];
#pragma unroll
    for (int i = 0; i < 4; ++i) tr[i] = tseq[b * Ln + m0 + 4 * ty + i];
#pragma unroll
    for (int j = 0; j < 4; ++j) tc[j] = tseq[b * Ln + n0 + 4 * tx + j];

#pragma unroll
    for (int i = 0; i < 4; ++i) {
        int r = m0 + 4 * ty + i;
#pragma unroll
        for (int j = 0; j < 4; ++j) {
            int c = n0 + 4 * tx + j;
            size_t idx = (size_t)r * Ln + c;
            float tqk = tanhf(acc[i][j]);
            float dt = fabsf(tr[i] - tc[j]);
            float decay = tanhf(log1pf(dt) * tw1[idx] + tb1[idx]);
            float gv = tow1[idx] * decay + tow2[idx] * tqk + tob[idx];
            float sg = 1.0f / (1.0f + expf(-gv));
            g_gate[(size_t)b * Ln * Ln + idx] = sg * 0.125f; // /sqrt(DH)
        }
    }
}

// ---------------- K2: fused attention (flash-style) ----------------------
__global__ __launch_bounds__(256) void attn_kernel(const float* __restrict__ mask)
{
    __shared__ float Qs[64][68];   // [d][row]
    __shared__ float KVs[16][68];  // K slice [d][col]  /  V slice [c][d]
    __shared__ float Ps[64][68];   // [c][row]

    const int t = threadIdx.x;
    const int tx = t & 15, ty = t >> 4;
    const int qt = blockIdx.x, h = blockIdx.y, b = blockIdx.z;
    const int q0 = qt * 64;

    const float* qptr = g_q + (size_t)b * Ln * Hn + h * DHn;
    const float* kptr = g_k + (size_t)b * Ln * Hn + h * DHn;
    const float* vptr = g_v + (size_t)b * Ln * Hn + h * DHn;
    const float* gptr = g_gate + (size_t)b * Ln * Ln;
    const float* mptr = mask + (size_t)b * Ln * Ln;

    // load Q tile, transposed to [d][row]
#pragma unroll
    for (int u = 0; u < 4; ++u) {
        int vi = t + 256 * u;
        int row = vi >> 4;
        int dq = (vi & 15) * 4;
        float4 qv = *(const float4*)&qptr[(size_t)(q0 + row) * Hn + dq];
        Qs[dq + 0][row] = qv.x; Qs[dq + 1][row] = qv.y;
        Qs[dq + 2][row] = qv.z; Qs[dq + 3][row] = qv.w;
    }

    float o[4][4] = {};
    float m_i[4], l_i[4] = {};
#pragma unroll
    for (int i = 0; i < 4; ++i) m_i[i] = -1e30f;

    for (int kb = 0; kb < 8; ++kb) {
        const int c0 = kb * 64;
        float s[4][4] = {};

        // ---- S = Q @ K^T  over d in 4 slices of 16 ----
        for (int ds = 0; ds < 4; ++ds) {
            __syncthreads();
            {
                int cl = t >> 2;
                int dq = (t & 3) * 4;
                float4 kv = *(const float4*)&kptr[(size_t)(c0 + cl) * Hn + ds * 16 + dq];
                KVs[dq + 0][cl] = kv.x; KVs[dq + 1][cl] = kv.y;
                KVs[dq + 2][cl] = kv.z; KVs[dq + 3][cl] = kv.w;
            }
            __syncthreads();
#pragma unroll
            for (int kk = 0; kk < 16; ++kk) {
                float4 a4 = *(const float4*)&Qs[ds * 16 + kk][4 * ty];
                float4 b4 = *(const float4*)&KVs[kk][4 * tx];
                FMA16(a4, b4, s);
            }
        }

        // ---- gate * s + mask ----
#pragma unroll
        for (int i = 0; i < 4; ++i) {
            int r = q0 + 4 * ty + i;
#pragma unroll
            for (int j = 0; j < 4; ++j) {
                int c = c0 + 4 * tx + j;
                size_t idx = (size_t)r * Ln + c;
                s[i][j] = s[i][j] * gptr[idx] + mptr[idx];
            }
        }

        // ---- online softmax (row groups of 16 lanes, tx dimension) ----
#pragma unroll
        for (int i = 0; i < 4; ++i) {
            float mx = fmaxf(fmaxf(s[i][0], s[i][1]), fmaxf(s[i][2], s[i][3]));
#pragma unroll
            for (int off = 1; off < 16; off <<= 1)
                mx = fmaxf(mx, __shfl_xor_sync(0xffffffffu, mx, off));
            float mnew = fmaxf(m_i[i], mx);
            float scale = __expf(m_i[i] - mnew);
            m_i[i] = mnew;
            float rs = 0.f;
#pragma unroll
            for (int j = 0; j < 4; ++j) {
                float p = __expf(s[i][j] - mnew);
                s[i][j] = p;
                rs += p;
            }
#pragma unroll
            for (int off = 1; off < 16; off <<= 1)
                rs += __shfl_xor_sync(0xffffffffu, rs, off);
            l_i[i] = l_i[i] * scale + rs;
#pragma unroll
            for (int j = 0; j < 4; ++j) o[i][j] *= scale;
        }

        // ---- write P transposed into smem ----
        __syncthreads();
#pragma unroll
        for (int i = 0; i < 4; ++i)
#pragma unroll
            for (int j = 0; j < 4; ++j)
                Ps[4 * tx + j][4 * ty + i] = s[i][j];

        // ---- O += P @ V  over c in 4 slices of 16 ----
        for (int cs = 0; cs < 4; ++cs) {
            __syncthreads();
            {
                int cl = t >> 4;          // 0..15
                int dq = (t & 15) * 4;    // 0..60
                float4 vv = *(const float4*)&vptr[(size_t)(c0 + cs * 16 + cl) * Hn + dq];
                *(float4*)&KVs[cl][dq] = vv;
            }
            __syncthreads();
#pragma unroll
            for (int kk = 0; kk < 16; ++kk) {
                float4 a4 = *(const float4*)&Ps[cs * 16 + kk][4 * ty];
                float4 b4 = *(const float4*)&KVs[kk][4 * tx];
                FMA16(a4, b4, o);
            }
        }
    }

    // ---- write ctx ----
#pragma unroll
    for (int i = 0; i < 4; ++i) {
        float inv = 1.0f / l_i[i];
#pragma unroll
        for (int j = 0; j < 4; ++j) {
            g_ctx[(size_t)b * Ln * Hn + (size_t)(q0 + 4 * ty + i) * Hn + h * DHn + 4 * tx + j]
                = o[i][j] * inv;
        }
    }
}

// ---------------- K3: output projection + residual + layernorm ------------
__global__ __launch_bounds__(256) void outln_kernel(
    const float* __restrict__ x,
    const float* __restrict__ Wd, const float* __restrict__ bd,
    const float* __restrict__ lng, const float* __restrict__ lnb,
    float* __restrict__ out)
{
    __shared__ float As[16][36];
    __shared__ float Bs[16][260];
    const int t = threadIdx.x;
    const int tx = t & 31, ty = t >> 5;  // 8 x 32
    const int m0 = blockIdx.x * 32;

    float acc[4][8] = {};
    for (int k0 = 0; k0 < Hn; k0 += 16) {
        if (t < 128) {
            int row = t >> 2;
            int kq = (t & 3) * 4;
            float4 av = *(const float4*)&g_ctx[(size_t)(m0 + row) * Hn + k0 + kq];
            As[kq + 0][row] = av.x; As[kq + 1][row] = av.y;
            As[kq + 2][row] = av.z; As[kq + 3][row] = av.w;
        }
#pragma unroll
        for (int u = 0; u < 4; ++u) {
            int vi = t + 256 * u;
            int n = vi >> 2;
            int kq = (vi & 3) * 4;
            float4 wv = *(const float4*)&Wd[(size_t)n * Hn + k0 + kq];
            Bs[kq + 0][n] = wv.x; Bs[kq + 1][n] = wv.y;
            Bs[kq + 2][n] = wv.z; Bs[kq + 3][n] = wv.w;
        }
        __syncthreads();
#pragma unroll
        for (int kk = 0; kk < 16; ++kk) {
            float a[4];
#pragma unroll
            for (int i = 0; i < 4; ++i) a[i] = As[kk][4 * ty + i];
            float bb[8];
#pragma unroll
            for (int j = 0; j < 8; ++j) bb[j] = Bs[kk][32 * j + tx];
#pragma unroll
            for (int i = 0; i < 4; ++i)
#pragma unroll
                for (int j = 0; j < 8; ++j) acc[i][j] += a[i] * bb[j];
        }
        __syncthreads();
    }

#pragma unroll
    for (int i = 0; i < 4; ++i) {
        const size_t r = (size_t)(m0 + 4 * ty + i);
        float v[8];
        float sum = 0.f;
#pragma unroll
        for (int j = 0; j < 8; ++j) {
            int c = 32 * j + tx;
            v[j] = acc[i][j] + bd[c] + x[r * Hn + c];
            sum += v[j];
        }
#pragma unroll
        for (int off = 16; off >= 1; off >>= 1)
            sum += __shfl_xor_sync(0xffffffffu, sum, off);
        float mu = sum * (1.0f / Hn);
        float vs = 0.f;
#pragma unroll
        for (int j = 0; j < 8; ++j) {
            float d = v[j] - mu;
            vs += d * d;
        }
#pragma unroll
        for (int off = 16; off >= 1; off >>= 1)
            vs += __shfl_xor_sync(0xffffffffu, vs, off);
        float inv = rsqrtf(vs * (1.0f / Hn) + 1e-12f);
#pragma unroll
        for (int j = 0; j < 8; ++j) {
            int c = 32 * j + tx;
            out[r * Hn + c] = (v[j] - mu) * inv * lng[c] + lnb[c];
        }
    }
}

// ---------------- K4: interval prediction head ---------------------------
__global__ __launch_bounds__(256) void pred_kernel(
    const float* __restrict__ hs, const int* __restrict__ slen,
    const float* __restrict__ Wt, const float* __restrict__ bt,
    float* __restrict__ out)
{
    __shared__ float red[256];
    const int b = blockIdx.x;
    const int t = threadIdx.x;
    const int len = slen[b];
    const float* e1 = hs + ((size_t)b * Ln + (len - 1)) * Hn;
    const float* e2 = hs + ((size_t)b * Ln + (len - 2)) * Hn;
    red[t] = Wt[t] * e1[t] + Wt[Hn + t] * e2[t];
    __syncthreads();
    for (int s = 128; s > 0; s >>= 1) {
        if (t < s) red[t] += red[t + s];
        __syncthreads();
    }
    if (t == 0) out[(size_t)Bn * Ln * Hn + b] = red[0] + bt[0];
}

// ---------------- launch --------------------------------------------------
extern "C" void kernel_launch(void* const* d_in, const int* in_sizes, int n_in,
                              void* d_out, int out_size)
{
    const float* x    = (const float*)d_in[0];
    const float* tseq = (const float*)d_in[1];
    const float* mask = (const float*)d_in[2];
    const int*   slen = (const int*)d_in[3];
    const float* Wq   = (const float*)d_in[4];
    const float* bq   = (const float*)d_in[5];
    const float* Wk   = (const float*)d_in[6];
    const float* bk   = (const float*)d_in[7];
    const float* Wv   = (const float*)d_in[8];
    const float* bv   = (const float*)d_in[9];
    const float* Wd   = (const float*)d_in[10];
    const float* bd   = (const float*)d_in[11];
    const float* lng  = (const float*)d_in[12];
    const float* lnb  = (const float*)d_in[13];
    const float* Wtq  = (const float*)d_in[14];
    const float* btq  = (const float*)d_in[15];
    const float* tw1  = (const float*)d_in[16];
    const float* tb1  = (const float*)d_in[17];
    const float* tow1 = (const float*)d_in[18];
    const float* tow2 = (const float*)d_in[19];
    const float* tob  = (const float*)d_in[20];
    const float* Wt   = (const float*)d_in[21];
    const float* bt   = (const float*)d_in[22];
    float* out = (float*)d_out;

    proj_kernel<<<dim3(Bn * Ln / 64, 16), 256>>>(x, Wq, bq, Wk, bk, Wv, bv, Wtq, btq);
    gate_kernel<<<dim3(Ln / 64, Ln / 64, Bn), 256>>>(x, tseq, tw1, tb1, tow1, tow2, tob);
    attn_kernel<<<dim3(Ln / 64, NHn, Bn), 256>>>(mask);
    outln_kernel<<<dim3(Bn * Ln / 32), 256>>>(x, Wd, bd, lng, lnb, out);
    pred_kernel<<<dim3(Bn), 256>>>(out, slen, Wt, bt, out);
}

// round 2
// speedup vs baseline: 1.5612x; 1.5612x over previous
#include <cuda_runtime.h>

#define Bn 32
#define Ln 512
#define Hn 256
#define NHn 4
#define DHn 64

// ---------------- scratch (device globals; no allocation) ----------------
__device__ float g_q[Bn * Ln * Hn];
__device__ float g_k[Bn * Ln * Hn];
__device__ float g_v[Bn * Ln * Hn];
__device__ float g_tq[Bn * Ln * Hn];
__device__ float g_gate[Bn * Ln * Ln];   // sigmoid(decay_gate)/sqrt(DH)
__device__ float g_ctx[Bn * Ln * Hn];

// ---------------- mma helpers --------------------------------------------
__device__ __forceinline__ unsigned f2tf(float f) {
    unsigned u;
    asm("cvt.rna.tf32.f32 %0, %1;" : "=r"(u) : "f"(f));
    return u;
}

__device__ __forceinline__ void mma_tf32(float* c, const unsigned* a, const unsigned* b) {
    asm volatile(
        "mma.sync.aligned.m16n8k8.row.col.f32.tf32.tf32.f32 "
        "{%0,%1,%2,%3}, {%4,%5,%6,%7}, {%8,%9}, {%0,%1,%2,%3};\n"
        : "+f"(c[0]), "+f"(c[1]), "+f"(c[2]), "+f"(c[3])
        : "r"(a[0]), "r"(a[1]), "r"(a[2]), "r"(a[3]), "r"(b[0]), "r"(b[1]));
}

// ---------------- K0: fused Q/K/V/TQ projection (tensor) ------------------
// C(16384,1024) = x(16384,256) @ [Wq;Wk;Wv;Wtq]^T + bias
__global__ __launch_bounds__(128) void proj_mma(
    const float* __restrict__ x,
    const float* __restrict__ Wq, const float* __restrict__ bq,
    const float* __restrict__ Wk, const float* __restrict__ bk,
    const float* __restrict__ Wv, const float* __restrict__ bv,
    const float* __restrict__ Wtq, const float* __restrict__ btq)
{
    __shared__ float As[64][36];   // [m][k] chunk
    __shared__ float Bs[64][36];   // [n][k] chunk
    const int t = threadIdx.x;
    const int lane = t & 31, warp = t >> 5;
    const int gid = lane >> 2, tig = lane & 3;
    const int m0 = blockIdx.x * 64;
    const int by = blockIdx.y;
    const int wsel = by >> 2, n0 = (by & 3) * 64;
    const int wm = warp * 16;

    const float* W; const float* bias; float* out;
    if (wsel == 0)      { W = Wq;  bias = bq;  out = g_q;  }
    else if (wsel == 1) { W = Wk;  bias = bk;  out = g_k;  }
    else if (wsel == 2) { W = Wv;  bias = bv;  out = g_v;  }
    else                { W = Wtq; bias = btq; out = g_tq; }

    float c[8][4] = {};

    for (int k0 = 0; k0 < Hn; k0 += 32) {
        __syncthreads();
#pragma unroll
        for (int u = 0; u < 4; ++u) {
            int f = t + 128 * u;          // 0..511
            int row = f >> 3;             // 0..63
            int kq = (f & 7) * 4;         // 0..28
            *(float4*)&As[row][kq] = *(const float4*)&x[(size_t)(m0 + row) * Hn + k0 + kq];
            *(float4*)&Bs[row][kq] = *(const float4*)&W[(size_t)(n0 + row) * Hn + k0 + kq];
        }
        __syncthreads();
#pragma unroll
        for (int ks = 0; ks < 32; ks += 8) {
            unsigned a[4];
            a[0] = f2tf(As[wm + gid][ks + tig]);
            a[1] = f2tf(As[wm + gid + 8][ks + tig]);
            a[2] = f2tf(As[wm + gid][ks + tig + 4]);
            a[3] = f2tf(As[wm + gid + 8][ks + tig + 4]);
#pragma unroll
            for (int nt = 0; nt < 8; ++nt) {
                unsigned b[2];
                b[0] = f2tf(Bs[nt * 8 + gid][ks + tig]);
                b[1] = f2tf(Bs[nt * 8 + gid][ks + tig + 4]);
                mma_tf32(c[nt], a, b);
            }
        }
    }
#pragma unroll
    for (int nt = 0; nt < 8; ++nt) {
        int cc = n0 + nt * 8 + 2 * tig;
        float2 bb = *(const float2*)&bias[cc];
        size_t r0 = (size_t)(m0 + wm + gid) * Hn;
        size_t r1 = (size_t)(m0 + wm + gid + 8) * Hn;
        *(float2*)&out[r0 + cc] = make_float2(c[nt][0] + bb.x, c[nt][1] + bb.y);
        *(float2*)&out[r1 + cc] = make_float2(c[nt][2] + bb.x, c[nt][3] + bb.y);
    }
}

// ---------------- K1: time-decay gate (tensor GEMM + epilogue) ------------
__global__ __launch_bounds__(128) void gate_mma(
    const float* __restrict__ x, const float* __restrict__ tseq,
    const float* __restrict__ tw1, const float* __restrict__ tb1,
    const float* __restrict__ tow1, const float* __restrict__ tow2,
    const float* __restrict__ tob)
{
    __shared__ float As[64][36];
    __shared__ float Bs[64][36];
    const int t = threadIdx.x;
    const int lane = t & 31, warp = t >> 5;
    const int gid = lane >> 2, tig = lane & 3;
    const int b = blockIdx.z;
    const int m0 = blockIdx.x * 64;
    const int n0 = blockIdx.y * 64;
    const int wm = warp * 16;
    const float* A = g_tq + (size_t)b * Ln * Hn;
    const float* Bm = x + (size_t)b * Ln * Hn;

    float c[8][4] = {};
    for (int k0 = 0; k0 < Hn; k0 += 32) {
        __syncthreads();
#pragma unroll
        for (int u = 0; u < 4; ++u) {
            int f = t + 128 * u;
            int row = f >> 3;
            int kq = (f & 7) * 4;
            *(float4*)&As[row][kq] = *(const float4*)&A[(size_t)(m0 + row) * Hn + k0 + kq];
            *(float4*)&Bs[row][kq] = *(const float4*)&Bm[(size_t)(n0 + row) * Hn + k0 + kq];
        }
        __syncthreads();
#pragma unroll
        for (int ks = 0; ks < 32; ks += 8) {
            unsigned a[4];
            a[0] = f2tf(As[wm + gid][ks + tig]);
            a[1] = f2tf(As[wm + gid + 8][ks + tig]);
            a[2] = f2tf(As[wm + gid][ks + tig + 4]);
            a[3] = f2tf(As[wm + gid + 8][ks + tig + 4]);
#pragma unroll
            for (int nt = 0; nt < 8; ++nt) {
                unsigned bfr[2];
                bfr[0] = f2tf(Bs[nt * 8 + gid][ks + tig]);
                bfr[1] = f2tf(Bs[nt * 8 + gid][ks + tig + 4]);
                mma_tf32(c[nt], a, bfr);
            }
        }
    }

    const int rl = m0 + wm + gid, rh = rl + 8;
    const float t_lo = tseq[b * Ln + rl];
    const float t_hi = tseq[b * Ln + rh];
    float* gout = g_gate + (size_t)b * Ln * Ln;

#pragma unroll
    for (int nt = 0; nt < 8; ++nt) {
        int cc = n0 + nt * 8 + 2 * tig;
        float2 tc = *(const float2*)&tseq[b * Ln + cc];
#pragma unroll
        for (int half = 0; half < 2; ++half) {
            int r = half ? rh : rl;
            float tr = half ? t_hi : t_lo;
            size_t idx = (size_t)r * Ln + cc;
            float2 w1 = *(const float2*)&tw1[idx];
            float2 b1 = *(const float2*)&tb1[idx];
            float2 o1 = *(const float2*)&tow1[idx];
            float2 o2 = *(const float2*)&tow2[idx];
            float2 ob = *(const float2*)&tob[idx];
            float s0 = c[nt][half * 2 + 0], s1 = c[nt][half * 2 + 1];
            float tqk0 = tanhf(s0), tqk1 = tanhf(s1);
            float d0 = tanhf(log1pf(fabsf(tr - tc.x)) * w1.x + b1.x);
            float d1 = tanhf(log1pf(fabsf(tr - tc.y)) * w1.y + b1.y);
            float g0 = o1.x * d0 + o2.x * tqk0 + ob.x;
            float g1 = o1.y * d1 + o2.y * tqk1 + ob.y;
            g0 = 0.125f / (1.0f + __expf(-g0));
            g1 = 0.125f / (1.0f + __expf(-g1));
            *(float2*)&gout[idx] = make_float2(g0, g1);
        }
    }
}

// ---------------- K2: fused attention (tensor, flash-style) ---------------
__global__ __launch_bounds__(128) void attn_mma(const float* __restrict__ mask)
{
    __shared__ float QPs[64][68];  // Q tile [q][d], later P per-warp [16][68]
    __shared__ float KVs[64][68];  // K tile [key][d], later V^T [d][key]

    const int t = threadIdx.x;
    const int lane = t & 31, warp = t >> 5;
    const int gid = lane >> 2, tig = lane & 3;
    const int qt = blockIdx.x, h = blockIdx.y, b = blockIdx.z;
    const int q0 = qt * 64;
    const int wm = warp * 16;

    const float* qptr = g_q + (size_t)b * Ln * Hn + h * DHn;
    const float* kptr = g_k + (size_t)b * Ln * Hn + h * DHn;
    const float* vptr = g_v + (size_t)b * Ln * Hn + h * DHn;
    const float* gptr = g_gate + (size_t)b * Ln * Ln;
    const float* mptr = mask + (size_t)b * Ln * Ln;

    // load Q tile [64 rows][64 dh]
#pragma unroll
    for (int u = 0; u < 8; ++u) {
        int f = t + 128 * u;
        int row = f >> 4;
        int kq = (f & 15) * 4;
        *(float4*)&QPs[row][kq] = *(const float4*)&qptr[(size_t)(q0 + row) * Hn + kq];
    }
    __syncthreads();

    // extract Q A-fragments (held all kernel)
    unsigned qf[8][4];
#pragma unroll
    for (int ks = 0; ks < 8; ++ks) {
        int kk = ks * 8;
        qf[ks][0] = f2tf(QPs[wm + gid][kk + tig]);
        qf[ks][1] = f2tf(QPs[wm + gid + 8][kk + tig]);
        qf[ks][2] = f2tf(QPs[wm + gid][kk + tig + 4]);
        qf[ks][3] = f2tf(QPs[wm + gid + 8][kk + tig + 4]);
    }

    float o[8][4] = {};
    float m_lo = -1e30f, m_hi = -1e30f, l_lo = 0.f, l_hi = 0.f;
    float* Pw = &QPs[wm][0];   // this warp's P region [16][68]

    const int rl = q0 + wm + gid, rh = rl + 8;

    for (int kb = 0; kb < 8; ++kb) {
        const int c0 = kb * 64;
        __syncthreads();   // KVs free
        // load K tile [key][d]
#pragma unroll
        for (int u = 0; u < 8; ++u) {
            int f = t + 128 * u;
            int row = f >> 4;
            int kq = (f & 15) * 4;
            *(float4*)&KVs[row][kq] = *(const float4*)&kptr[(size_t)(c0 + row) * Hn + kq];
        }
        __syncthreads();

        // S = Q @ K^T
        float s[8][4] = {};
#pragma unroll
        for (int ks = 0; ks < 8; ++ks) {
            int kk = ks * 8;
#pragma unroll
            for (int nt = 0; nt < 8; ++nt) {
                unsigned bfr[2];
                bfr[0] = f2tf(KVs[nt * 8 + gid][kk + tig]);
                bfr[1] = f2tf(KVs[nt * 8 + gid][kk + tig + 4]);
                mma_tf32(s[nt], qf[ks], bfr);
            }
        }

        // epilogue: s*gate + mask
#pragma unroll
        for (int nt = 0; nt < 8; ++nt) {
            int cc = c0 + nt * 8 + 2 * tig;
            size_t il = (size_t)rl * Ln + cc;
            size_t ih = (size_t)rh * Ln + cc;
            float2 gl = *(const float2*)&gptr[il];
            float2 ml = *(const float2*)&mptr[il];
            float2 gh = *(const float2*)&gptr[ih];
            float2 mh = *(const float2*)&mptr[ih];
            s[nt][0] = s[nt][0] * gl.x + ml.x;
            s[nt][1] = s[nt][1] * gl.y + ml.y;
            s[nt][2] = s[nt][2] * gh.x + mh.x;
            s[nt][3] = s[nt][3] * gh.y + mh.y;
        }

        // online softmax (rows rl, rh; quad = lanes tig 0..3)
        float mx_lo = -1e30f, mx_hi = -1e30f;
#pragma unroll
        for (int nt = 0; nt < 8; ++nt) {
            mx_lo = fmaxf(mx_lo, fmaxf(s[nt][0], s[nt][1]));
            mx_hi = fmaxf(mx_hi, fmaxf(s[nt][2], s[nt][3]));
        }
        mx_lo = fmaxf(mx_lo, __shfl_xor_sync(0xffffffffu, mx_lo, 1));
        mx_lo = fmaxf(mx_lo, __shfl_xor_sync(0xffffffffu, mx_lo, 2));
        mx_hi = fmaxf(mx_hi, __shfl_xor_sync(0xffffffffu, mx_hi, 1));
        mx_hi = fmaxf(mx_hi, __shfl_xor_sync(0xffffffffu, mx_hi, 2));
        float mn_lo = fmaxf(m_lo, mx_lo), mn_hi = fmaxf(m_hi, mx_hi);
        float sc_lo = __expf(m_lo - mn_lo), sc_hi = __expf(m_hi - mn_hi);
        m_lo = mn_lo; m_hi = mn_hi;
        float rs_lo = 0.f, rs_hi = 0.f;
#pragma unroll
        for (int nt = 0; nt < 8; ++nt) {
            s[nt][0] = __expf(s[nt][0] - mn_lo);
            s[nt][1] = __expf(s[nt][1] - mn_lo);
            s[nt][2] = __expf(s[nt][2] - mn_hi);
            s[nt][3] = __expf(s[nt][3] - mn_hi);
            rs_lo += s[nt][0] + s[nt][1];
            rs_hi += s[nt][2] + s[nt][3];
        }
        rs_lo += __shfl_xor_sync(0xffffffffu, rs_lo, 1);
        rs_lo += __shfl_xor_sync(0xffffffffu, rs_lo, 2);
        rs_hi += __shfl_xor_sync(0xffffffffu, rs_hi, 1);
        rs_hi += __shfl_xor_sync(0xffffffffu, rs_hi, 2);
        l_lo = l_lo * sc_lo + rs_lo;
        l_hi = l_hi * sc_hi + rs_hi;
#pragma unroll
        for (int dt = 0; dt < 8; ++dt) {
            o[dt][0] *= sc_lo; o[dt][1] *= sc_lo;
            o[dt][2] *= sc_hi; o[dt][3] *= sc_hi;
        }

        __syncthreads();   // all warps done reading K from KVs
        // load V tile transposed: KVs[d][key]
#pragma unroll
        for (int u = 0; u < 8; ++u) {
            int f = t + 128 * u;
            int cl = f >> 4;
            int dq = (f & 15) * 4;
            float4 vv = *(const float4*)&vptr[(size_t)(c0 + cl) * Hn + dq];
            KVs[dq + 0][cl] = vv.x; KVs[dq + 1][cl] = vv.y;
            KVs[dq + 2][cl] = vv.z; KVs[dq + 3][cl] = vv.w;
        }
        // store P into own warp region
#pragma unroll
        for (int nt = 0; nt < 8; ++nt) {
            *(float2*)&Pw[(size_t)gid * 68 + nt * 8 + 2 * tig] = make_float2(s[nt][0], s[nt][1]);
            *(float2*)&Pw[(size_t)(gid + 8) * 68 + nt * 8 + 2 * tig] = make_float2(s[nt][2], s[nt][3]);
        }
        __syncthreads();

        // O += P @ V
#pragma unroll
        for (int ks = 0; ks < 8; ++ks) {
            int kk = ks * 8;
            unsigned pa[4];
            pa[0] = f2tf(Pw[(size_t)gid * 68 + kk + tig]);
            pa[1] = f2tf(Pw[(size_t)(gid + 8) * 68 + kk + tig]);
            pa[2] = f2tf(Pw[(size_t)gid * 68 + kk + tig + 4]);
            pa[3] = f2tf(Pw[(size_t)(gid + 8) * 68 + kk + tig + 4]);
#pragma unroll
            for (int dt = 0; dt < 8; ++dt) {
                unsigned bfr[2];
                bfr[0] = f2tf(KVs[dt * 8 + gid][kk + tig]);
                bfr[1] = f2tf(KVs[dt * 8 + gid][kk + tig + 4]);
                mma_tf32(o[dt], pa, bfr);
            }
        }
    }

    // write ctx
    float inv_lo = 1.0f / l_lo, inv_hi = 1.0f / l_hi;
    float* cbase = g_ctx + (size_t)b * Ln * Hn + h * DHn;
#pragma unroll
    for (int dt = 0; dt < 8; ++dt) {
        int dd = dt * 8 + 2 * tig;
        *(float2*)&cbase[(size_t)rl * Hn + dd] = make_float2(o[dt][0] * inv_lo, o[dt][1] * inv_lo);
        *(float2*)&cbase[(size_t)rh * Hn + dd] = make_float2(o[dt][2] * inv_hi, o[dt][3] * inv_hi);
    }
}

// ---------------- K3: output projection + residual + layernorm ------------
__global__ __launch_bounds__(256) void outln_mma(
    const float* __restrict__ x,
    const float* __restrict__ Wd, const float* __restrict__ bd,
    const float* __restrict__ lng, const float* __restrict__ lnb,
    float* __restrict__ out)
{
    __shared__ float As[64][36];    // ctx chunk [m][k]
    __shared__ float Bs[256][36];   // Wd chunk [n][k]
    __shared__ float red[64][4];    // row sums / sumsq per half

    const int t = threadIdx.x;
    const int lane = t & 31, warp = t >> 5;
    const int gid = lane >> 2, tig = lane & 3;
    const int m0 = blockIdx.x * 64;
    const int mg = warp >> 1;        // 0..3 : 16-row group
    const int nh = warp & 1;         // 0/1 : 128-col half
    const int wm = mg * 16;
    const int wn = nh * 128;

    float c[16][4] = {};
    for (int k0 = 0; k0 < Hn; k0 += 32) {
        __syncthreads();
#pragma unroll
        for (int u = 0; u < 2; ++u) {
            int f = t + 256 * u;
            int row = f >> 3;
            int kq = (f & 7) * 4;
            *(float4*)&As[row][kq] = *(const float4*)&g_ctx[(size_t)(m0 + row) * Hn + k0 + kq];
        }
#pragma unroll
        for (int u = 0; u < 8; ++u) {
            int f = t + 256 * u;
            int row = f >> 3;
            int kq = (f & 7) * 4;
            *(float4*)&Bs[row][kq] = *(const float4*)&Wd[(size_t)row * Hn + k0 + kq];
        }
        __syncthreads();
#pragma unroll
        for (int ks = 0; ks < 32; ks += 8) {
            unsigned a[4];
            a[0] = f2tf(As[wm + gid][ks + tig]);
            a[1] = f2tf(As[wm + gid + 8][ks + tig]);
            a[2] = f2tf(As[wm + gid][ks + tig + 4]);
            a[3] = f2tf(As[wm + gid + 8][ks + tig + 4]);
#pragma unroll
            for (int nt = 0; nt < 16; ++nt) {
                unsigned bfr[2];
                bfr[0] = f2tf(Bs[wn + nt * 8 + gid][ks + tig]);
                bfr[1] = f2tf(Bs[wn + nt * 8 + gid][ks + tig + 4]);
                mma_tf32(c[nt], a, bfr);
            }
        }
    }

    // v = c + bd + x ; accumulate sum and sumsq
    const int lrl = wm + gid, lrh = lrl + 8;      // block-local rows
    const size_t rl = m0 + lrl, rh = m0 + lrh;    // global rows
    float s_lo = 0.f, s_hi = 0.f, q_lo = 0.f, q_hi = 0.f;
#pragma unroll
    for (int nt = 0; nt < 16; ++nt) {
        int cc = wn + nt * 8 + 2 * tig;
        float2 bb = *(const float2*)&bd[cc];
        float2 xl = *(const float2*)&x[rl * Hn + cc];
        float2 xh = *(const float2*)&x[rh * Hn + cc];
        c[nt][0] += bb.x + xl.x; c[nt][1] += bb.y + xl.y;
        c[nt][2] += bb.x + xh.x; c[nt][3] += bb.y + xh.y;
        s_lo += c[nt][0] + c[nt][1];
        s_hi += c[nt][2] + c[nt][3];
        q_lo += c[nt][0] * c[nt][0] + c[nt][1] * c[nt][1];
        q_hi += c[nt][2] * c[nt][2] + c[nt][3] * c[nt][3];
    }
    s_lo += __shfl_xor_sync(0xffffffffu, s_lo, 1);
    s_lo += __shfl_xor_sync(0xffffffffu, s_lo, 2);
    s_hi += __shfl_xor_sync(0xffffffffu, s_hi, 1);
    s_hi += __shfl_xor_sync(0xffffffffu, s_hi, 2);
    q_lo += __shfl_xor_sync(0xffffffffu, q_lo, 1);
    q_lo += __shfl_xor_sync(0xffffffffu, q_lo, 2);
    q_hi += __shfl_xor_sync(0xffffffffu, q_hi, 1);
    q_hi += __shfl_xor_sync(0xffffffffu, q_hi, 2);
    if (tig == 0) {
        red[lrl][nh] = s_lo; red[lrl][2 + nh] = q_lo;
        red[lrh][nh] = s_hi; red[lrh][2 + nh] = q_hi;
    }
    __syncthreads();
    float mu_lo = (red[lrl][0] + red[lrl][1]) * (1.0f / Hn);
    float mu_hi = (red[lrh][0] + red[lrh][1]) * (1.0f / Hn);
    float ex_lo = (red[lrl][2] + red[lrl][3]) * (1.0f / Hn);
    float ex_hi = (red[lrh][2] + red[lrh][3]) * (1.0f / Hn);
    float iv_lo = rsqrtf(ex_lo - mu_lo * mu_lo + 1e-12f);
    float iv_hi = rsqrtf(ex_hi - mu_hi * mu_hi + 1e-12f);

#pragma unroll
    for (int nt = 0; nt < 16; ++nt) {
        int cc = wn + nt * 8 + 2 * tig;
        float2 g = *(const float2*)&lng[cc];
        float2 be = *(const float2*)&lnb[cc];
        *(float2*)&out[rl * Hn + cc] = make_float2(
            (c[nt][0] - mu_lo) * iv_lo * g.x + be.x,
            (c[nt][1] - mu_lo) * iv_lo * g.y + be.y);
        *(float2*)&out[rh * Hn + cc] = make_float2(
            (c[nt][2] - mu_hi) * iv_hi * g.x + be.x,
            (c[nt][3] - mu_hi) * iv_hi * g.y + be.y);
    }
}

// ---------------- K4: interval prediction head ---------------------------
__global__ __launch_bounds__(256) void pred_kernel(
    const float* __restrict__ hs, const int* __restrict__ slen,
    const float* __restrict__ Wt, const float* __restrict__ bt,
    float* __restrict__ out)
{
    __shared__ float red[256];
    const int b = blockIdx.x;
    const int t = threadIdx.x;
    const int len = slen[b];
    const float* e1 = hs + ((size_t)b * Ln + (len - 1)) * Hn;
    const float* e2 = hs + ((size_t)b * Ln + (len - 2)) * Hn;
    red[t] = Wt[t] * e1[t] + Wt[Hn + t] * e2[t];
    __syncthreads();
    for (int s = 128; s > 0; s >>= 1) {
        if (t < s) red[t] += red[t + s];
        __syncthreads();
    }
    if (t == 0) out[(size_t)Bn * Ln * Hn + b] = red[0] + bt[0];
}

// ---------------- launch --------------------------------------------------
extern "C" void kernel_launch(void* const* d_in, const int* in_sizes, int n_in,
                              void* d_out, int out_size)
{
    const float* x    = (const float*)d_in[0];
    const float* tseq = (const float*)d_in[1];
    const float* mask = (const float*)d_in[2];
    const int*   slen = (const int*)d_in[3];
    const float* Wq   = (const float*)d_in[4];
    const float* bq   = (const float*)d_in[5];
    const float* Wk   = (const float*)d_in[6];
    const float* bk   = (const float*)d_in[7];
    const float* Wv   = (const float*)d_in[8];
    const float* bv   = (const float*)d_in[9];
    const float* Wd   = (const float*)d_in[10];
    const float* bd   = (const float*)d_in[11];
    const float* lng  = (const float*)d_in[12];
    const float* lnb  = (const float*)d_in[13];
    const float* Wtq  = (const float*)d_in[14];
    const float* btq  = (const float*)d_in[15];
    const float* tw1  = (const float*)d_in[16];
    const float* tb1  = (const float*)d_in[17];
    const float* tow1 = (const float*)d_in[18];
    const float* tow2 = (const float*)d_in[19];
    const float* tob  = (const float*)d_in[20];
    const float* Wt   = (const float*)d_in[21];
    const float* bt   = (const float*)d_in[22];
    float* out = (float*)d_out;

    proj_mma<<<dim3(Bn * Ln / 64, 16), 128>>>(x, Wq, bq, Wk, bk, Wv, bv, Wtq, btq);
    gate_mma<<<dim3(Ln / 64, Ln / 64, Bn), 128>>>(x, tseq, tw1, tb1, tow1, tow2, tob);
    attn_mma<<<dim3(Ln / 64, NHn, Bn), 128>>>(mask);
    outln_mma<<<dim3(Bn * Ln / 64), 256>>>(x, Wd, bd, lng, lnb, out);
    pred_kernel<<<dim3(Bn), 256>>>(out, slen, Wt, bt, out);
}

// round 4
// speedup vs baseline: 2.3517x; 1.5063x over previous
#include <cuda_runtime.h>

#define Bn 32
#define Ln 512
#define Hn 256
#define NHn 4
#define DHn 64

// ---------------- scratch (device globals; no allocation) ----------------
__device__ float g_q[Bn * Ln * Hn];
__device__ float g_k[Bn * Ln * Hn];
__device__ float g_v[Bn * Ln * Hn];
__device__ float g_tq[Bn * Ln * Hn];
__device__ float g_gate[Bn * Ln * Ln];   // sigmoid(decay_gate)/sqrt(DH)
__device__ float g_ctx[Bn * Ln * Hn];

// ---------------- helpers --------------------------------------------
__device__ __forceinline__ unsigned f2tf(float f) {
    unsigned u;
    asm("cvt.rna.tf32.f32 %0, %1;" : "=r"(u) : "f"(f));
    return u;
}
__device__ __forceinline__ float tanh_ap(float x) {
    float y;
    asm("tanh.approx.f32 %0, %1;" : "=f"(y) : "f"(x));
    return y;
}
__device__ __forceinline__ uint4 cvt4(float4 v) {
    return make_uint4(f2tf(v.x), f2tf(v.y), f2tf(v.z), f2tf(v.w));
}

__device__ __forceinline__ void mma_tf32(float* c, const unsigned* a, const unsigned* b) {
    asm volatile(
        "mma.sync.aligned.m16n8k8.row.col.f32.tf32.tf32.f32 "
        "{%0,%1,%2,%3}, {%4,%5,%6,%7}, {%8,%9}, {%0,%1,%2,%3};\n"
        : "+f"(c[0]), "+f"(c[1]), "+f"(c[2]), "+f"(c[3])
        : "r"(a[0]), "r"(a[1]), "r"(a[2]), "r"(a[3]), "r"(b[0]), "r"(b[1]));
}

// ---------------- K0: fused Q/K/V/TQ projection (tensor) ------------------
__global__ __launch_bounds__(128) void proj_mma(
    const float* __restrict__ x,
    const float* __restrict__ Wq, const float* __restrict__ bq,
    const float* __restrict__ Wk, const float* __restrict__ bk,
    const float* __restrict__ Wv, const float* __restrict__ bv,
    const float* __restrict__ Wtq, const float* __restrict__ btq)
{
    __shared__ unsigned As[64][36];
    __shared__ unsigned Bs[64][36];
    const int t = threadIdx.x;
    const int lane = t & 31, warp = t >> 5;
    const int gid = lane >> 2, tig = lane & 3;
    const int m0 = blockIdx.x * 64;
    const int by = blockIdx.y;
    const int wsel = by >> 2, n0 = (by & 3) * 64;
    const int wm = warp * 16;

    const float* W; const float* bias; float* out;
    if (wsel == 0)      { W = Wq;  bias = bq;  out = g_q;  }
    else if (wsel == 1) { W = Wk;  bias = bk;  out = g_k;  }
    else if (wsel == 2) { W = Wv;  bias = bv;  out = g_v;  }
    else                { W = Wtq; bias = btq; out = g_tq; }

    float c[8][4] = {};

    for (int k0 = 0; k0 < Hn; k0 += 32) {
        __syncthreads();
#pragma unroll
        for (int u = 0; u < 4; ++u) {
            int f = t + 128 * u;
            int row = f >> 3;
            int kq = (f & 7) * 4;
            *(uint4*)&As[row][kq] = cvt4(*(const float4*)&x[(size_t)(m0 + row) * Hn + k0 + kq]);
            *(uint4*)&Bs[row][kq] = cvt4(*(const float4*)&W[(size_t)(n0 + row) * Hn + k0 + kq]);
        }
        __syncthreads();
#pragma unroll
        for (int ks = 0; ks < 32; ks += 8) {
            unsigned a[4];
            a[0] = As[wm + gid][ks + tig];
            a[1] = As[wm + gid + 8][ks + tig];
            a[2] = As[wm + gid][ks + tig + 4];
            a[3] = As[wm + gid + 8][ks + tig + 4];
#pragma unroll
            for (int nt = 0; nt < 8; ++nt) {
                unsigned b[2];
                b[0] = Bs[nt * 8 + gid][ks + tig];
                b[1] = Bs[nt * 8 + gid][ks + tig + 4];
                mma_tf32(c[nt], a, b);
            }
        }
    }
#pragma unroll
    for (int nt = 0; nt < 8; ++nt) {
        int cc = n0 + nt * 8 + 2 * tig;
        float2 bb = *(const float2*)&bias[cc];
        size_t r0 = (size_t)(m0 + wm + gid) * Hn;
        size_t r1 = (size_t)(m0 + wm + gid + 8) * Hn;
        *(float2*)&out[r0 + cc] = make_float2(c[nt][0] + bb.x, c[nt][1] + bb.y);
        *(float2*)&out[r1 + cc] = make_float2(c[nt][2] + bb.x, c[nt][3] + bb.y);
    }
}

// ---------------- K1: time-decay gate (tensor GEMM + fast epilogue) -------
__global__ __launch_bounds__(128) void gate_mma(
    const float* __restrict__ x, const float* __restrict__ tseq,
    const float* __restrict__ tw1, const float* __restrict__ tb1,
    const float* __restrict__ tow1, const float* __restrict__ tow2,
    const float* __restrict__ tob)
{
    __shared__ unsigned As[64][36];
    __shared__ unsigned Bs[64][36];
    const int t = threadIdx.x;
    const int lane = t & 31, warp = t >> 5;
    const int gid = lane >> 2, tig = lane & 3;
    const int b = blockIdx.z;
    const int m0 = blockIdx.x * 64;
    const int n0 = blockIdx.y * 64;
    const int wm = warp * 16;
    const float* A = g_tq + (size_t)b * Ln * Hn;
    const float* Bm = x + (size_t)b * Ln * Hn;

    float c[8][4] = {};
    for (int k0 = 0; k0 < Hn; k0 += 32) {
        __syncthreads();
#pragma unroll
        for (int u = 0; u < 4; ++u) {
            int f = t + 128 * u;
            int row = f >> 3;
            int kq = (f & 7) * 4;
            *(uint4*)&As[row][kq] = cvt4(*(const float4*)&A[(size_t)(m0 + row) * Hn + k0 + kq]);
            *(uint4*)&Bs[row][kq] = cvt4(*(const float4*)&Bm[(size_t)(n0 + row) * Hn + k0 + kq]);
        }
        __syncthreads();
#pragma unroll
        for (int ks = 0; ks < 32; ks += 8) {
            unsigned a[4];
            a[0] = As[wm + gid][ks + tig];
            a[1] = As[wm + gid + 8][ks + tig];
            a[2] = As[wm + gid][ks + tig + 4];
            a[3] = As[wm + gid + 8][ks + tig + 4];
#pragma unroll
            for (int nt = 0; nt < 8; ++nt) {
                unsigned bfr[2];
                bfr[0] = Bs[nt * 8 + gid][ks + tig];
                bfr[1] = Bs[nt * 8 + gid][ks + tig + 4];
                mma_tf32(c[nt], a, bfr);
            }
        }
    }

    const int rl = m0 + wm + gid, rh = rl + 8;
    const float t_lo = tseq[b * Ln + rl];
    const float t_hi = tseq[b * Ln + rh];
    float* gout = g_gate + (size_t)b * Ln * Ln;

#pragma unroll
    for (int nt = 0; nt < 8; ++nt) {
        int cc = n0 + nt * 8 + 2 * tig;
        float2 tc = *(const float2*)&tseq[b * Ln + cc];
#pragma unroll
        for (int half = 0; half < 2; ++half) {
            int r = half ? rh : rl;
            float tr = half ? t_hi : t_lo;
            size_t idx = (size_t)r * Ln + cc;
            float2 w1 = *(const float2*)&tw1[idx];
            float2 b1 = *(const float2*)&tb1[idx];
            float2 o1 = *(const float2*)&tow1[idx];
            float2 o2 = *(const float2*)&tow2[idx];
            float2 ob = *(const float2*)&tob[idx];
            float s0 = c[nt][half * 2 + 0], s1 = c[nt][half * 2 + 1];
            float tqk0 = tanh_ap(s0), tqk1 = tanh_ap(s1);
            float d0 = tanh_ap(__logf(1.0f + fabsf(tr - tc.x)) * w1.x + b1.x);
            float d1 = tanh_ap(__logf(1.0f + fabsf(tr - tc.y)) * w1.y + b1.y);
            float g0 = o1.x * d0 + o2.x * tqk0 + ob.x;
            float g1 = o1.y * d1 + o2.y * tqk1 + ob.y;
            g0 = 0.125f / (1.0f + __expf(-g0));
            g1 = 0.125f / (1.0f + __expf(-g1));
            *(float2*)&gout[idx] = make_float2(g0, g1);
        }
    }
}

// ---------------- K2: fused attention (tensor, flash-style) ---------------
__global__ __launch_bounds__(128) void attn_mma(const float* __restrict__ mask)
{
    __shared__ unsigned QPs[64][68];  // Q tile [q][d] tf32; later per-warp P [16][68]
    __shared__ unsigned Ks[64][68];   // K tile [key][d] tf32
    __shared__ unsigned Vs[64][72];   // V tile [key][d] tf32 (stride 72: conflict-free row=tig)

    const int t = threadIdx.x;
    const int lane = t & 31, warp = t >> 5;
    const int gid = lane >> 2, tig = lane & 3;
    const int qt = blockIdx.x, h = blockIdx.y, b = blockIdx.z;
    const int q0 = qt * 64;
    const int wm = warp * 16;

    const float* qptr = g_q + (size_t)b * Ln * Hn + h * DHn;
    const float* kptr = g_k + (size_t)b * Ln * Hn + h * DHn;
    const float* vptr = g_v + (size_t)b * Ln * Hn + h * DHn;
    const float* gptr = g_gate + (size_t)b * Ln * Ln;
    const float* mptr = mask + (size_t)b * Ln * Ln;

    // load Q tile [64][64]
#pragma unroll
    for (int u = 0; u < 8; ++u) {
        int f = t + 128 * u;
        int row = f >> 4;
        int kq = (f & 15) * 4;
        *(uint4*)&QPs[row][kq] = cvt4(*(const float4*)&qptr[(size_t)(q0 + row) * Hn + kq]);
    }
    __syncthreads();

    // extract Q A-fragments (held all kernel)
    unsigned qf[8][4];
#pragma unroll
    for (int ks = 0; ks < 8; ++ks) {
        int kk = ks * 8;
        qf[ks][0] = QPs[wm + gid][kk + tig];
        qf[ks][1] = QPs[wm + gid + 8][kk + tig];
        qf[ks][2] = QPs[wm + gid][kk + tig + 4];
        qf[ks][3] = QPs[wm + gid + 8][kk + tig + 4];
    }

    float o[8][4] = {};
    float m_lo = -1e30f, m_hi = -1e30f, l_lo = 0.f, l_hi = 0.f;
    unsigned* Pw = &QPs[wm][0];   // this warp's private P region [16][68]

    const int rl = q0 + wm + gid, rh = rl + 8;

    for (int kb = 0; kb < 8; ++kb) {
        const int c0 = kb * 64;
        __syncthreads();   // previous K/V fully consumed
        // load K and V tiles [key][d]
#pragma unroll
        for (int u = 0; u < 8; ++u) {
            int f = t + 128 * u;
            int row = f >> 4;
            int kq = (f & 15) * 4;
            *(uint4*)&Ks[row][kq] = cvt4(*(const float4*)&kptr[(size_t)(c0 + row) * Hn + kq]);
            *(uint4*)&Vs[row][kq] = cvt4(*(const float4*)&vptr[(size_t)(c0 + row) * Hn + kq]);
        }
        __syncthreads();

        // S = Q @ K^T
        float s[8][4] = {};
#pragma unroll
        for (int ks = 0; ks < 8; ++ks) {
            int kk = ks * 8;
#pragma unroll
            for (int nt = 0; nt < 8; ++nt) {
                unsigned bfr[2];
                bfr[0] = Ks[nt * 8 + gid][kk + tig];
                bfr[1] = Ks[nt * 8 + gid][kk + tig + 4];
                mma_tf32(s[nt], qf[ks], bfr);
            }
        }

        // epilogue: s*gate + mask
#pragma unroll
        for (int nt = 0; nt < 8; ++nt) {
            int cc = c0 + nt * 8 + 2 * tig;
            size_t il = (size_t)rl * Ln + cc;
            size_t ih = (size_t)rh * Ln + cc;
            float2 gl = *(const float2*)&gptr[il];
            float2 ml = *(const float2*)&mptr[il];
            float2 gh = *(const float2*)&gptr[ih];
            float2 mh = *(const float2*)&mptr[ih];
            s[nt][0] = s[nt][0] * gl.x + ml.x;
            s[nt][1] = s[nt][1] * gl.y + ml.y;
            s[nt][2] = s[nt][2] * gh.x + mh.x;
            s[nt][3] = s[nt][3] * gh.y + mh.y;
        }

        // online softmax (rows rl, rh; reduce over quad lanes tig)
        float mx_lo = -1e30f, mx_hi = -1e30f;
#pragma unroll
        for (int nt = 0; nt < 8; ++nt) {
            mx_lo = fmaxf(mx_lo, fmaxf(s[nt][0], s[nt][1]));
            mx_hi = fmaxf(mx_hi, fmaxf(s[nt][2], s[nt][3]));
        }
        mx_lo = fmaxf(mx_lo, __shfl_xor_sync(0xffffffffu, mx_lo, 1));
        mx_lo = fmaxf(mx_lo, __shfl_xor_sync(0xffffffffu, mx_lo, 2));
        mx_hi = fmaxf(mx_hi, __shfl_xor_sync(0xffffffffu, mx_hi, 1));
        mx_hi = fmaxf(mx_hi, __shfl_xor_sync(0xffffffffu, mx_hi, 2));
        float mn_lo = fmaxf(m_lo, mx_lo), mn_hi = fmaxf(m_hi, mx_hi);
        float sc_lo = __expf(m_lo - mn_lo), sc_hi = __expf(m_hi - mn_hi);
        m_lo = mn_lo; m_hi = mn_hi;
        float rs_lo = 0.f, rs_hi = 0.f;
#pragma unroll
        for (int nt = 0; nt < 8; ++nt) {
            s[nt][0] = __expf(s[nt][0] - mn_lo);
            s[nt][1] = __expf(s[nt][1] - mn_lo);
            s[nt][2] = __expf(s[nt][2] - mn_hi);
            s[nt][3] = __expf(s[nt][3] - mn_hi);
            rs_lo += s[nt][0] + s[nt][1];
            rs_hi += s[nt][2] + s[nt][3];
        }
        rs_lo += __shfl_xor_sync(0xffffffffu, rs_lo, 1);
        rs_lo += __shfl_xor_sync(0xffffffffu, rs_lo, 2);
        rs_hi += __shfl_xor_sync(0xffffffffu, rs_hi, 1);
        rs_hi += __shfl_xor_sync(0xffffffffu, rs_hi, 2);
        l_lo = l_lo * sc_lo + rs_lo;
        l_hi = l_hi * sc_hi + rs_hi;
#pragma unroll
        for (int dt = 0; dt < 8; ++dt) {
            o[dt][0] *= sc_lo; o[dt][1] *= sc_lo;
            o[dt][2] *= sc_hi; o[dt][3] *= sc_hi;
        }

        // store P (tf32) into warp-private region — no block sync needed
#pragma unroll
        for (int nt = 0; nt < 8; ++nt) {
            *(uint2*)&Pw[(size_t)gid * 68 + nt * 8 + 2 * tig] =
                make_uint2(f2tf(s[nt][0]), f2tf(s[nt][1]));
            *(uint2*)&Pw[(size_t)(gid + 8) * 68 + nt * 8 + 2 * tig] =
                make_uint2(f2tf(s[nt][2]), f2tf(s[nt][3]));
        }
        __syncwarp();

        // O += P @ V   (V read directly as col-major B: B(k=key,n=d)=V[key][d])
#pragma unroll
        for (int ks = 0; ks < 8; ++ks) {
            int kk = ks * 8;
            unsigned pa[4];
            pa[0] = Pw[(size_t)gid * 68 + kk + tig];
            pa[1] = Pw[(size_t)(gid + 8) * 68 + kk + tig];
            pa[2] = Pw[(size_t)gid * 68 + kk + tig + 4];
            pa[3] = Pw[(size_t)(gid + 8) * 68 + kk + tig + 4];
#pragma unroll
            for (int dt = 0; dt < 8; ++dt) {
                unsigned bfr[2];
                bfr[0] = Vs[kk + tig][dt * 8 + gid];
                bfr[1] = Vs[kk + tig + 4][dt * 8 + gid];
                mma_tf32(o[dt], pa, bfr);
            }
        }
        __syncwarp();
    }

    // write ctx
    float inv_lo = 1.0f / l_lo, inv_hi = 1.0f / l_hi;
    float* cbase = g_ctx + (size_t)b * Ln * Hn + h * DHn;
#pragma unroll
    for (int dt = 0; dt < 8; ++dt) {
        int dd = dt * 8 + 2 * tig;
        *(float2*)&cbase[(size_t)rl * Hn + dd] = make_float2(o[dt][0] * inv_lo, o[dt][1] * inv_lo);
        *(float2*)&cbase[(size_t)rh * Hn + dd] = make_float2(o[dt][2] * inv_hi, o[dt][3] * inv_hi);
    }
}

// ---------------- K3: output projection + residual + layernorm ------------
__global__ __launch_bounds__(256) void outln_mma(
    const float* __restrict__ x,
    const float* __restrict__ Wd, const float* __restrict__ bd,
    const float* __restrict__ lng, const float* __restrict__ lnb,
    float* __restrict__ out)
{
    __shared__ unsigned As[32][36];    // ctx chunk [m][k]
    __shared__ unsigned Bs[256][36];   // Wd chunk [n][k]
    __shared__ float redS[32][4];
    __shared__ float redQ[32][4];

    const int t = threadIdx.x;
    const int lane = t & 31, warp = t >> 5;
    const int gid = lane >> 2, tig = lane & 3;
    const int m0 = blockIdx.x * 32;
    const int mg = warp >> 2;        // 0..1 : 16-row group
    const int nq = warp & 3;         // 0..3 : 64-col quarter
    const int wm = mg * 16;
    const int wn = nq * 64;

    float c[8][4] = {};
    for (int k0 = 0; k0 < Hn; k0 += 32) {
        __syncthreads();
        {
            int row = t >> 3;
            int kq = (t & 7) * 4;
            if (t < 256)
                *(uint4*)&As[row & 31][kq] = cvt4(
                    *(const float4*)&g_ctx[(size_t)(m0 + (row & 31)) * Hn + k0 + kq]);
        }
#pragma unroll
        for (int u = 0; u < 8; ++u) {
            int f = t + 256 * u;
            int row = f >> 3;
            int kq = (f & 7) * 4;
            *(uint4*)&Bs[row][kq] = cvt4(*(const float4*)&Wd[(size_t)row * Hn + k0 + kq]);
        }
        __syncthreads();
#pragma unroll
        for (int ks = 0; ks < 32; ks += 8) {
            unsigned a[4];
            a[0] = As[wm + gid][ks + tig];
            a[1] = As[wm + gid + 8][ks + tig];
            a[2] = As[wm + gid][ks + tig + 4];
            a[3] = As[wm + gid + 8][ks + tig + 4];
#pragma unroll
            for (int nt = 0; nt < 8; ++nt) {
                unsigned bfr[2];
                bfr[0] = Bs[wn + nt * 8 + gid][ks + tig];
                bfr[1] = Bs[wn + nt * 8 + gid][ks + tig + 4];
                mma_tf32(c[nt], a, bfr);
            }
        }
    }

    // v = c + bd + x ; accumulate sum and sumsq
    const int lrl = wm + gid, lrh = lrl + 8;
    const size_t rl = m0 + lrl, rh = m0 + lrh;
    float s_lo = 0.f, s_hi = 0.f, q_lo = 0.f, q_hi = 0.f;
#pragma unroll
    for (int nt = 0; nt < 8; ++nt) {
        int cc = wn + nt * 8 + 2 * tig;
        float2 bb = *(const float2*)&bd[cc];
        float2 xl = *(const float2*)&x[rl * Hn + cc];
        float2 xh = *(const float2*)&x[rh * Hn + cc];
        c[nt][0] += bb.x + xl.x; c[nt][1] += bb.y + xl.y;
        c[nt][2] += bb.x + xh.x; c[nt][3] += bb.y + xh.y;
        s_lo += c[nt][0] + c[nt][1];
        s_hi += c[nt][2] + c[nt][3];
        q_lo += c[nt][0] * c[nt][0] + c[nt][1] * c[nt][1];
        q_hi += c[nt][2] * c[nt][2] + c[nt][3] * c[nt][3];
    }
    s_lo += __shfl_xor_sync(0xffffffffu, s_lo, 1);
    s_lo += __shfl_xor_sync(0xffffffffu, s_lo, 2);
    s_hi += __shfl_xor_sync(0xffffffffu, s_hi, 1);
    s_hi += __shfl_xor_sync(0xffffffffu, s_hi, 2);
    q_lo += __shfl_xor_sync(0xffffffffu, q_lo, 1);
    q_lo += __shfl_xor_sync(0xffffffffu, q_lo, 2);
    q_hi += __shfl_xor_sync(0xffffffffu, q_hi, 1);
    q_hi += __shfl_xor_sync(0xffffffffu, q_hi, 2);
    __syncthreads();
    if (tig == 0) {
        redS[lrl][nq] = s_lo; redQ[lrl][nq] = q_lo;
        redS[lrh][nq] = s_hi; redQ[lrh][nq] = q_hi;
    }
    __syncthreads();
    float mu_lo = (redS[lrl][0] + redS[lrl][1] + redS[lrl][2] + redS[lrl][3]) * (1.0f / Hn);
    float mu_hi = (redS[lrh][0] + redS[lrh][1] + redS[lrh][2] + redS[lrh][3]) * (1.0f / Hn);
    float ex_lo = (redQ[lrl][0] + redQ[lrl][1] + redQ[lrl][2] + redQ[lrl][3]) * (1.0f / Hn);
    float ex_hi = (redQ[lrh][0] + redQ[lrh][1] + redQ[lrh][2] + redQ[lrh][3]) * (1.0f / Hn);
    float iv_lo = rsqrtf(ex_lo - mu_lo * mu_lo + 1e-12f);
    float iv_hi = rsqrtf(ex_hi - mu_hi * mu_hi + 1e-12f);

#pragma unroll
    for (int nt = 0; nt < 8; ++nt) {
        int cc = wn + nt * 8 + 2 * tig;
        float2 g = *(const float2*)&lng[cc];
        float2 be = *(const float2*)&lnb[cc];
        *(float2*)&out[rl * Hn + cc] = make_float2(
            (c[nt][0] - mu_lo) * iv_lo * g.x + be.x,
            (c[nt][1] - mu_lo) * iv_lo * g.y + be.y);
        *(float2*)&out[rh * Hn + cc] = make_float2(
            (c[nt][2] - mu_hi) * iv_hi * g.x + be.x,
            (c[nt][3] - mu_hi) * iv_hi * g.y + be.y);
    }
}

// ---------------- K4: interval prediction head ---------------------------
__global__ __launch_bounds__(256) void pred_kernel(
    const float* __restrict__ hs, const int* __restrict__ slen,
    const float* __restrict__ Wt, const float* __restrict__ bt,
    float* __restrict__ out)
{
    __shared__ float red[256];
    const int b = blockIdx.x;
    const int t = threadIdx.x;
    const int len = slen[b];
    const float* e1 = hs + ((size_t)b * Ln + (len - 1)) * Hn;
    const float* e2 = hs + ((size_t)b * Ln + (len - 2)) * Hn;
    red[t] = Wt[t] * e1[t] + Wt[Hn + t] * e2[t];
    __syncthreads();
    for (int s = 128; s > 0; s >>= 1) {
        if (t < s) red[t] += red[t + s];
        __syncthreads();
    }
    if (t == 0) out[(size_t)Bn * Ln * Hn + b] = red[0] + bt[0];
}

// ---------------- launch --------------------------------------------------
extern "C" void kernel_launch(void* const* d_in, const int* in_sizes, int n_in,
                              void* d_out, int out_size)
{
    const float* x    = (const float*)d_in[0];
    const float* tseq = (const float*)d_in[1];
    const float* mask = (const float*)d_in[2];
    const int*   slen = (const int*)d_in[3];
    const float* Wq   = (const float*)d_in[4];
    const float* bq   = (const float*)d_in[5];
    const float* Wk   = (const float*)d_in[6];
    const float* bk   = (const float*)d_in[7];
    const float* Wv   = (const float*)d_in[8];
    const float* bv   = (const float*)d_in[9];
    const float* Wd   = (const float*)d_in[10];
    const float* bd   = (const float*)d_in[11];
    const float* lng  = (const float*)d_in[12];
    const float* lnb  = (const float*)d_in[13];
    const float* Wtq  = (const float*)d_in[14];
    const float* btq  = (const float*)d_in[15];
    const float* tw1  = (const float*)d_in[16];
    const float* tb1  = (const float*)d_in[17];
    const float* tow1 = (const float*)d_in[18];
    const float* tow2 = (const float*)d_in[19];
    const float* tob  = (const float*)d_in[20];
    const float* Wt   = (const float*)d_in[21];
    const float* bt   = (const float*)d_in[22];
    float* out = (float*)d_out;

    proj_mma<<<dim3(Bn * Ln / 64, 16), 128>>>(x, Wq, bq, Wk, bk, Wv, bv, Wtq, btq);
    gate_mma<<<dim3(Ln / 64, Ln / 64, Bn), 128>>>(x, tseq, tw1, tb1, tow1, tow2, tob);
    attn_mma<<<dim3(Ln / 64, NHn, Bn), 128>>>(mask);
    outln_mma<<<dim3(Bn * Ln / 32), 256>>>(x, Wd, bd, lng, lnb, out);
    pred_kernel<<<dim3(Bn), 256>>>(out, slen, Wt, bt, out);
}

// round 5
// speedup vs baseline: 2.6002x; 1.1057x over previous
#include <cuda_runtime.h>
#include <cuda_bf16.h>

#define Bn 32
#define Ln 512
#define Hn 256
#define NHn 4
#define DHn 64

// ---------------- scratch (device globals; no allocation) ----------------
// q/k/v/tq/ctx hold tf32 bit patterns (pre-converted at producer)
__device__ unsigned g_q[Bn * Ln * Hn];
__device__ unsigned g_k[Bn * Ln * Hn];
__device__ unsigned g_v[Bn * Ln * Hn];
__device__ unsigned g_tq[Bn * Ln * Hn];
__device__ unsigned g_gm[Bn * Ln * Ln];    // bf16x2 {gate*0.125, mask}
__device__ unsigned g_ctx[Bn * Ln * Hn];

// ---------------- helpers --------------------------------------------
__device__ __forceinline__ unsigned f2tf(float f) {
    unsigned u;
    asm("cvt.rna.tf32.f32 %0, %1;" : "=r"(u) : "f"(f));
    return u;
}
__device__ __forceinline__ float tanh_ap(float x) {
    float y;
    asm("tanh.approx.f32 %0, %1;" : "=f"(y) : "f"(x));
    return y;
}
__device__ __forceinline__ uint4 cvt4(float4 v) {
    return make_uint4(f2tf(v.x), f2tf(v.y), f2tf(v.z), f2tf(v.w));
}

__device__ __forceinline__ void mma_tf32(float* c, const unsigned* a, const unsigned* b) {
    asm volatile(
        "mma.sync.aligned.m16n8k8.row.col.f32.tf32.tf32.f32 "
        "{%0,%1,%2,%3}, {%4,%5,%6,%7}, {%8,%9}, {%0,%1,%2,%3};\n"
        : "+f"(c[0]), "+f"(c[1]), "+f"(c[2]), "+f"(c[3])
        : "r"(a[0]), "r"(a[1]), "r"(a[2]), "r"(a[3]), "r"(b[0]), "r"(b[1]));
}

// ---------------- K0: fused Q/K/V/TQ projection (tensor) ------------------
__global__ __launch_bounds__(128) void proj_mma(
    const float* __restrict__ x,
    const float* __restrict__ Wq, const float* __restrict__ bq,
    const float* __restrict__ Wk, const float* __restrict__ bk,
    const float* __restrict__ Wv, const float* __restrict__ bv,
    const float* __restrict__ Wtq, const float* __restrict__ btq)
{
    __shared__ unsigned As[64][36];
    __shared__ unsigned Bs[64][36];
    const int t = threadIdx.x;
    const int lane = t & 31, warp = t >> 5;
    const int gid = lane >> 2, tig = lane & 3;
    const int m0 = blockIdx.x * 64;
    const int by = blockIdx.y;
    const int wsel = by >> 2, n0 = (by & 3) * 64;
    const int wm = warp * 16;

    const float* W; const float* bias; unsigned* out;
    if (wsel == 0)      { W = Wq;  bias = bq;  out = g_q;  }
    else if (wsel == 1) { W = Wk;  bias = bk;  out = g_k;  }
    else if (wsel == 2) { W = Wv;  bias = bv;  out = g_v;  }
    else                { W = Wtq; bias = btq; out = g_tq; }

    float c[8][4] = {};

    for (int k0 = 0; k0 < Hn; k0 += 32) {
        __syncthreads();
#pragma unroll
        for (int u = 0; u < 4; ++u) {
            int f = t + 128 * u;
            int row = f >> 3;
            int kq = (f & 7) * 4;
            *(uint4*)&As[row][kq] = cvt4(*(const float4*)&x[(size_t)(m0 + row) * Hn + k0 + kq]);
            *(uint4*)&Bs[row][kq] = cvt4(*(const float4*)&W[(size_t)(n0 + row) * Hn + k0 + kq]);
        }
        __syncthreads();
#pragma unroll
        for (int ks = 0; ks < 32; ks += 8) {
            unsigned a[4];
            a[0] = As[wm + gid][ks + tig];
            a[1] = As[wm + gid + 8][ks + tig];
            a[2] = As[wm + gid][ks + tig + 4];
            a[3] = As[wm + gid + 8][ks + tig + 4];
#pragma unroll
            for (int nt = 0; nt < 8; ++nt) {
                unsigned b[2];
                b[0] = Bs[nt * 8 + gid][ks + tig];
                b[1] = Bs[nt * 8 + gid][ks + tig + 4];
                mma_tf32(c[nt], a, b);
            }
        }
    }
#pragma unroll
    for (int nt = 0; nt < 8; ++nt) {
        int cc = n0 + nt * 8 + 2 * tig;
        float2 bb = *(const float2*)&bias[cc];
        size_t r0 = (size_t)(m0 + wm + gid) * Hn;
        size_t r1 = (size_t)(m0 + wm + gid + 8) * Hn;
        *(uint2*)&out[r0 + cc] = make_uint2(f2tf(c[nt][0] + bb.x), f2tf(c[nt][1] + bb.y));
        *(uint2*)&out[r1 + cc] = make_uint2(f2tf(c[nt][2] + bb.x), f2tf(c[nt][3] + bb.y));
    }
}

// ---------------- K1: time-decay gate (tensor GEMM + fast epilogue) -------
// output: bf16x2 {sigmoid(gate)/8, mask}
__global__ __launch_bounds__(128) void gate_mma(
    const float* __restrict__ x, const float* __restrict__ tseq,
    const float* __restrict__ tw1, const float* __restrict__ tb1,
    const float* __restrict__ tow1, const float* __restrict__ tow2,
    const float* __restrict__ tob, const float* __restrict__ mask)
{
    __shared__ unsigned As[64][36];
    __shared__ unsigned Bs[64][36];
    const int t = threadIdx.x;
    const int lane = t & 31, warp = t >> 5;
    const int gid = lane >> 2, tig = lane & 3;
    const int b = blockIdx.z;
    const int m0 = blockIdx.x * 64;
    const int n0 = blockIdx.y * 64;
    const int wm = warp * 16;
    const unsigned* A = g_tq + (size_t)b * Ln * Hn;
    const float* Bm = x + (size_t)b * Ln * Hn;
    const float* mptr = mask + (size_t)b * Ln * Ln;

    float c[8][4] = {};
    for (int k0 = 0; k0 < Hn; k0 += 32) {
        __syncthreads();
#pragma unroll
        for (int u = 0; u < 4; ++u) {
            int f = t + 128 * u;
            int row = f >> 3;
            int kq = (f & 7) * 4;
            *(uint4*)&As[row][kq] = *(const uint4*)&A[(size_t)(m0 + row) * Hn + k0 + kq];
            *(uint4*)&Bs[row][kq] = cvt4(*(const float4*)&Bm[(size_t)(n0 + row) * Hn + k0 + kq]);
        }
        __syncthreads();
#pragma unroll
        for (int ks = 0; ks < 32; ks += 8) {
            unsigned a[4];
            a[0] = As[wm + gid][ks + tig];
            a[1] = As[wm + gid + 8][ks + tig];
            a[2] = As[wm + gid][ks + tig + 4];
            a[3] = As[wm + gid + 8][ks + tig + 4];
#pragma unroll
            for (int nt = 0; nt < 8; ++nt) {
                unsigned bfr[2];
                bfr[0] = Bs[nt * 8 + gid][ks + tig];
                bfr[1] = Bs[nt * 8 + gid][ks + tig + 4];
                mma_tf32(c[nt], a, bfr);
            }
        }
    }

    const int rl = m0 + wm + gid, rh = rl + 8;
    const float t_lo = tseq[b * Ln + rl];
    const float t_hi = tseq[b * Ln + rh];
    unsigned* gout = g_gm + (size_t)b * Ln * Ln;

#pragma unroll
    for (int nt = 0; nt < 8; ++nt) {
        int cc = n0 + nt * 8 + 2 * tig;
        float2 tc = *(const float2*)&tseq[b * Ln + cc];
#pragma unroll
        for (int half = 0; half < 2; ++half) {
            int r = half ? rh : rl;
            float tr = half ? t_hi : t_lo;
            size_t idx = (size_t)r * Ln + cc;
            float2 w1 = *(const float2*)&tw1[idx];
            float2 b1 = *(const float2*)&tb1[idx];
            float2 o1 = *(const float2*)&tow1[idx];
            float2 o2 = *(const float2*)&tow2[idx];
            float2 ob = *(const float2*)&tob[idx];
            float2 mm = *(const float2*)&mptr[idx];
            float s0 = c[nt][half * 2 + 0], s1 = c[nt][half * 2 + 1];
            float tqk0 = tanh_ap(s0), tqk1 = tanh_ap(s1);
            float d0 = tanh_ap(__logf(1.0f + fabsf(tr - tc.x)) * w1.x + b1.x);
            float d1 = tanh_ap(__logf(1.0f + fabsf(tr - tc.y)) * w1.y + b1.y);
            float g0 = o1.x * d0 + o2.x * tqk0 + ob.x;
            float g1 = o1.y * d1 + o2.y * tqk1 + ob.y;
            g0 = 0.125f / (1.0f + __expf(-g0));
            g1 = 0.125f / (1.0f + __expf(-g1));
            __nv_bfloat162 p0 = __floats2bfloat162_rn(g0, mm.x);
            __nv_bfloat162 p1 = __floats2bfloat162_rn(g1, mm.y);
            *(uint2*)&gout[idx] = make_uint2(*(unsigned*)&p0, *(unsigned*)&p1);
        }
    }
}

// ---------------- K2: fused attention (tensor, flash-style) ---------------
__global__ __launch_bounds__(128) void attn_mma()
{
    __shared__ unsigned QPs[64][68];  // Q tile [q][d] tf32; later per-warp P [16][68]
    __shared__ unsigned Ks[64][68];   // K tile [key][d] tf32
    __shared__ unsigned Vs[64][72];   // V tile [key][d] tf32

    const int t = threadIdx.x;
    const int lane = t & 31, warp = t >> 5;
    const int gid = lane >> 2, tig = lane & 3;
    const int qt = blockIdx.x, h = blockIdx.y, b = blockIdx.z;
    const int q0 = qt * 64;
    const int wm = warp * 16;

    const unsigned* qptr = g_q + (size_t)b * Ln * Hn + h * DHn;
    const unsigned* kptr = g_k + (size_t)b * Ln * Hn + h * DHn;
    const unsigned* vptr = g_v + (size_t)b * Ln * Hn + h * DHn;
    const unsigned* gptr = g_gm + (size_t)b * Ln * Ln;

    // load Q tile [64][64] (already tf32)
#pragma unroll
    for (int u = 0; u < 8; ++u) {
        int f = t + 128 * u;
        int row = f >> 4;
        int kq = (f & 15) * 4;
        *(uint4*)&QPs[row][kq] = *(const uint4*)&qptr[(size_t)(q0 + row) * Hn + kq];
    }
    __syncthreads();

    // extract Q A-fragments (held all kernel)
    unsigned qf[8][4];
#pragma unroll
    for (int ks = 0; ks < 8; ++ks) {
        int kk = ks * 8;
        qf[ks][0] = QPs[wm + gid][kk + tig];
        qf[ks][1] = QPs[wm + gid + 8][kk + tig];
        qf[ks][2] = QPs[wm + gid][kk + tig + 4];
        qf[ks][3] = QPs[wm + gid + 8][kk + tig + 4];
    }

    float o[8][4] = {};
    float m_lo = -1e30f, m_hi = -1e30f, l_lo = 0.f, l_hi = 0.f;
    unsigned* Pw = &QPs[wm][0];   // warp-private P region [16][68]

    const int rl = q0 + wm + gid, rh = rl + 8;

    for (int kb = 0; kb < 8; ++kb) {
        const int c0 = kb * 64;
        __syncthreads();
#pragma unroll
        for (int u = 0; u < 8; ++u) {
            int f = t + 128 * u;
            int row = f >> 4;
            int kq = (f & 15) * 4;
            *(uint4*)&Ks[row][kq] = *(const uint4*)&kptr[(size_t)(c0 + row) * Hn + kq];
            *(uint4*)&Vs[row][kq] = *(const uint4*)&vptr[(size_t)(c0 + row) * Hn + kq];
        }
        __syncthreads();

        // S = Q @ K^T
        float s[8][4] = {};
#pragma unroll
        for (int ks = 0; ks < 8; ++ks) {
            int kk = ks * 8;
#pragma unroll
            for (int nt = 0; nt < 8; ++nt) {
                unsigned bfr[2];
                bfr[0] = Ks[nt * 8 + gid][kk + tig];
                bfr[1] = Ks[nt * 8 + gid][kk + tig + 4];
                mma_tf32(s[nt], qf[ks], bfr);
            }
        }

        // epilogue: s*gate + mask  (bf16x2 packed)
#pragma unroll
        for (int nt = 0; nt < 8; ++nt) {
            int cc = c0 + nt * 8 + 2 * tig;
            uint2 pl = *(const uint2*)&gptr[(size_t)rl * Ln + cc];
            uint2 ph = *(const uint2*)&gptr[(size_t)rh * Ln + cc];
            float2 e0 = __bfloat1622float2(*(__nv_bfloat162*)&pl.x);
            float2 e1 = __bfloat1622float2(*(__nv_bfloat162*)&pl.y);
            float2 e2 = __bfloat1622float2(*(__nv_bfloat162*)&ph.x);
            float2 e3 = __bfloat1622float2(*(__nv_bfloat162*)&ph.y);
            s[nt][0] = s[nt][0] * e0.x + e0.y;
            s[nt][1] = s[nt][1] * e1.x + e1.y;
            s[nt][2] = s[nt][2] * e2.x + e2.y;
            s[nt][3] = s[nt][3] * e3.x + e3.y;
        }

        // online softmax
        float mx_lo = -1e30f, mx_hi = -1e30f;
#pragma unroll
        for (int nt = 0; nt < 8; ++nt) {
            mx_lo = fmaxf(mx_lo, fmaxf(s[nt][0], s[nt][1]));
            mx_hi = fmaxf(mx_hi, fmaxf(s[nt][2], s[nt][3]));
        }
        mx_lo = fmaxf(mx_lo, __shfl_xor_sync(0xffffffffu, mx_lo, 1));
        mx_lo = fmaxf(mx_lo, __shfl_xor_sync(0xffffffffu, mx_lo, 2));
        mx_hi = fmaxf(mx_hi, __shfl_xor_sync(0xffffffffu, mx_hi, 1));
        mx_hi = fmaxf(mx_hi, __shfl_xor_sync(0xffffffffu, mx_hi, 2));
        float mn_lo = fmaxf(m_lo, mx_lo), mn_hi = fmaxf(m_hi, mx_hi);
        float sc_lo = __expf(m_lo - mn_lo), sc_hi = __expf(m_hi - mn_hi);
        m_lo = mn_lo; m_hi = mn_hi;
        float rs_lo = 0.f, rs_hi = 0.f;
#pragma unroll
        for (int nt = 0; nt < 8; ++nt) {
            s[nt][0] = __expf(s[nt][0] - mn_lo);
            s[nt][1] = __expf(s[nt][1] - mn_lo);
            s[nt][2] = __expf(s[nt][2] - mn_hi);
            s[nt][3] = __expf(s[nt][3] - mn_hi);
            rs_lo += s[nt][0] + s[nt][1];
            rs_hi += s[nt][2] + s[nt][3];
        }
        rs_lo += __shfl_xor_sync(0xffffffffu, rs_lo, 1);
        rs_lo += __shfl_xor_sync(0xffffffffu, rs_lo, 2);
        rs_hi += __shfl_xor_sync(0xffffffffu, rs_hi, 1);
        rs_hi += __shfl_xor_sync(0xffffffffu, rs_hi, 2);
        l_lo = l_lo * sc_lo + rs_lo;
        l_hi = l_hi * sc_hi + rs_hi;
#pragma unroll
        for (int dt = 0; dt < 8; ++dt) {
            o[dt][0] *= sc_lo; o[dt][1] *= sc_lo;
            o[dt][2] *= sc_hi; o[dt][3] *= sc_hi;
        }

        // store P (tf32) into warp-private region
#pragma unroll
        for (int nt = 0; nt < 8; ++nt) {
            *(uint2*)&Pw[(size_t)gid * 68 + nt * 8 + 2 * tig] =
                make_uint2(f2tf(s[nt][0]), f2tf(s[nt][1]));
            *(uint2*)&Pw[(size_t)(gid + 8) * 68 + nt * 8 + 2 * tig] =
                make_uint2(f2tf(s[nt][2]), f2tf(s[nt][3]));
        }
        __syncwarp();

        // O += P @ V
#pragma unroll
        for (int ks = 0; ks < 8; ++ks) {
            int kk = ks * 8;
            unsigned pa[4];
            pa[0] = Pw[(size_t)gid * 68 + kk + tig];
            pa[1] = Pw[(size_t)(gid + 8) * 68 + kk + tig];
            pa[2] = Pw[(size_t)gid * 68 + kk + tig + 4];
            pa[3] = Pw[(size_t)(gid + 8) * 68 + kk + tig + 4];
#pragma unroll
            for (int dt = 0; dt < 8; ++dt) {
                unsigned bfr[2];
                bfr[0] = Vs[kk + tig][dt * 8 + gid];
                bfr[1] = Vs[kk + tig + 4][dt * 8 + gid];
                mma_tf32(o[dt], pa, bfr);
            }
        }
        __syncwarp();
    }

    // write ctx pre-converted to tf32 (only consumed by outln's mma)
    float inv_lo = 1.0f / l_lo, inv_hi = 1.0f / l_hi;
    unsigned* cbase = g_ctx + (size_t)b * Ln * Hn + h * DHn;
#pragma unroll
    for (int dt = 0; dt < 8; ++dt) {
        int dd = dt * 8 + 2 * tig;
        *(uint2*)&cbase[(size_t)rl * Hn + dd] =
            make_uint2(f2tf(o[dt][0] * inv_lo), f2tf(o[dt][1] * inv_lo));
        *(uint2*)&cbase[(size_t)rh * Hn + dd] =
            make_uint2(f2tf(o[dt][2] * inv_hi), f2tf(o[dt][3] * inv_hi));
    }
}

// ---------------- K3: output projection + residual + layernorm ------------
__global__ __launch_bounds__(512) void outln_mma(
    const float* __restrict__ x,
    const float* __restrict__ Wd, const float* __restrict__ bd,
    const float* __restrict__ lng, const float* __restrict__ lnb,
    float* __restrict__ out)
{
    __shared__ unsigned As[64][36];    // ctx chunk [m][k] (tf32 already)
    __shared__ unsigned Bs[256][36];   // Wd chunk [n][k]
    __shared__ float redS[64][4];
    __shared__ float redQ[64][4];

    const int t = threadIdx.x;
    const int lane = t & 31, warp = t >> 5;      // warp 0..15
    const int gid = lane >> 2, tig = lane & 3;
    const int m0 = blockIdx.x * 64;
    const int mg = warp >> 2;        // 0..3 : 16-row group
    const int nq = warp & 3;         // 0..3 : 64-col quarter
    const int wm = mg * 16;
    const int wn = nq * 64;

    float c[8][4] = {};
    for (int k0 = 0; k0 < Hn; k0 += 32) {
        __syncthreads();
        {
            int row = t >> 3;
            int kq = (t & 7) * 4;
            *(uint4*)&As[row][kq] = *(const uint4*)&g_ctx[(size_t)(m0 + row) * Hn + k0 + kq];
        }
#pragma unroll
        for (int u = 0; u < 4; ++u) {
            int f = t + 512 * u;
            int row = f >> 3;
            int kq = (f & 7) * 4;
            *(uint4*)&Bs[row][kq] = cvt4(*(const float4*)&Wd[(size_t)row * Hn + k0 + kq]);
        }
        __syncthreads();
#pragma unroll
        for (int ks = 0; ks < 32; ks += 8) {
            unsigned a[4];
            a[0] = As[wm + gid][ks + tig];
            a[1] = As[wm + gid + 8][ks + tig];
            a[2] = As[wm + gid][ks + tig + 4];
            a[3] = As[wm + gid + 8][ks + tig + 4];
#pragma unroll
            for (int nt = 0; nt < 8; ++nt) {
                unsigned bfr[2];
                bfr[0] = Bs[wn + nt * 8 + gid][ks + tig];
                bfr[1] = Bs[wn + nt * 8 + gid][ks + tig + 4];
                mma_tf32(c[nt], a, bfr);
            }
        }
    }

    // v = c + bd + x ; accumulate sum and sumsq
    const int lrl = wm + gid, lrh = lrl + 8;
    const size_t rl = m0 + lrl, rh = m0 + lrh;
    float s_lo = 0.f, s_hi = 0.f, q_lo = 0.f, q_hi = 0.f;
#pragma unroll
    for (int nt = 0; nt < 8; ++nt) {
        int cc = wn + nt * 8 + 2 * tig;
        float2 bb = *(const float2*)&bd[cc];
        float2 xl = *(const float2*)&x[rl * Hn + cc];
        float2 xh = *(const float2*)&x[rh * Hn + cc];
        c[nt][0] += bb.x + xl.x; c[nt][1] += bb.y + xl.y;
        c[nt][2] += bb.x + xh.x; c[nt][3] += bb.y + xh.y;
        s_lo += c[nt][0] + c[nt][1];
        s_hi += c[nt][2] + c[nt][3];
        q_lo += c[nt][0] * c[nt][0] + c[nt][1] * c[nt][1];
        q_hi += c[nt][2] * c[nt][2] + c[nt][3] * c[nt][3];
    }
    s_lo += __shfl_xor_sync(0xffffffffu, s_lo, 1);
    s_lo += __shfl_xor_sync(0xffffffffu, s_lo, 2);
    s_hi += __shfl_xor_sync(0xffffffffu, s_hi, 1);
    s_hi += __shfl_xor_sync(0xffffffffu, s_hi, 2);
    q_lo += __shfl_xor_sync(0xffffffffu, q_lo, 1);
    q_lo += __shfl_xor_sync(0xffffffffu, q_lo, 2);
    q_hi += __shfl_xor_sync(0xffffffffu, q_hi, 1);
    q_hi += __shfl_xor_sync(0xffffffffu, q_hi, 2);
    __syncthreads();
    if (tig == 0) {
        redS[lrl][nq] = s_lo; redQ[lrl][nq] = q_lo;
        redS[lrh][nq] = s_hi; redQ[lrh][nq] = q_hi;
    }
    __syncthreads();
    float mu_lo = (redS[lrl][0] + redS[lrl][1] + redS[lrl][2] + redS[lrl][3]) * (1.0f / Hn);
    float mu_hi = (redS[lrh][0] + redS[lrh][1] + redS[lrh][2] + redS[lrh][3]) * (1.0f / Hn);
    float ex_lo = (redQ[lrl][0] + redQ[lrl][1] + redQ[lrl][2] + redQ[lrl][3]) * (1.0f / Hn);
    float ex_hi = (redQ[lrh][0] + redQ[lrh][1] + redQ[lrh][2] + redQ[lrh][3]) * (1.0f / Hn);
    float iv_lo = rsqrtf(ex_lo - mu_lo * mu_lo + 1e-12f);
    float iv_hi = rsqrtf(ex_hi - mu_hi * mu_hi + 1e-12f);

#pragma unroll
    for (int nt = 0; nt < 8; ++nt) {
        int cc = wn + nt * 8 + 2 * tig;
        float2 g = *(const float2*)&lng[cc];
        float2 be = *(const float2*)&lnb[cc];
        *(float2*)&out[rl * Hn + cc] = make_float2(
            (c[nt][0] - mu_lo) * iv_lo * g.x + be.x,
            (c[nt][1] - mu_lo) * iv_lo * g.y + be.y);
        *(float2*)&out[rh * Hn + cc] = make_float2(
            (c[nt][2] - mu_hi) * iv_hi * g.x + be.x,
            (c[nt][3] - mu_hi) * iv_hi * g.y + be.y);
    }
}

// ---------------- K4: interval prediction head ---------------------------
__global__ __launch_bounds__(256) void pred_kernel(
    const float* __restrict__ hs, const int* __restrict__ slen,
    const float* __restrict__ Wt, const float* __restrict__ bt,
    float* __restrict__ out)
{
    __shared__ float red[256];
    const int b = blockIdx.x;
    const int t = threadIdx.x;
    const int len = slen[b];
    const float* e1 = hs + ((size_t)b * Ln + (len - 1)) * Hn;
    const float* e2 = hs + ((size_t)b * Ln + (len - 2)) * Hn;
    red[t] = Wt[t] * e1[t] + Wt[Hn + t] * e2[t];
    __syncthreads();
    for (int s = 128; s > 0; s >>= 1) {
        if (t < s) red[t] += red[t + s];
        __syncthreads();
    }
    if (t == 0) out[(size_t)Bn * Ln * Hn + b] = red[0] + bt[0];
}

// ---------------- launch --------------------------------------------------
extern "C" void kernel_launch(void* const* d_in, const int* in_sizes, int n_in,
                              void* d_out, int out_size)
{
    const float* x    = (const float*)d_in[0];
    const float* tseq = (const float*)d_in[1];
    const float* mask = (const float*)d_in[2];
    const int*   slen = (const int*)d_in[3];
    const float* Wq   = (const float*)d_in[4];
    const float* bq   = (const float*)d_in[5];
    const float* Wk   = (const float*)d_in[6];
    const float* bk   = (const float*)d_in[7];
    const float* Wv   = (const float*)d_in[8];
    const float* bv   = (const float*)d_in[9];
    const float* Wd   = (const float*)d_in[10];
    const float* bd   = (const float*)d_in[11];
    const float* lng  = (const float*)d_in[12];
    const float* lnb  = (const float*)d_in[13];
    const float* Wtq  = (const float*)d_in[14];
    const float* btq  = (const float*)d_in[15];
    const float* tw1  = (const float*)d_in[16];
    const float* tb1  = (const float*)d_in[17];
    const float* tow1 = (const float*)d_in[18];
    const float* tow2 = (const float*)d_in[19];
    const float* tob  = (const float*)d_in[20];
    const float* Wt   = (const float*)d_in[21];
    const float* bt   = (const float*)d_in[22];
    float* out = (float*)d_out;

    proj_mma<<<dim3(Bn * Ln / 64, 16), 128>>>(x, Wq, bq, Wk, bk, Wv, bv, Wtq, btq);
    gate_mma<<<dim3(Ln / 64, Ln / 64, Bn), 128>>>(x, tseq, tw1, tb1, tow1, tow2, tob, mask);
    attn_mma<<<dim3(Ln / 64, NHn, Bn), 128>>>();
    outln_mma<<<dim3(Bn * Ln / 64), 512>>>(x, Wd, bd, lng, lnb, out);
    pred_kernel<<<dim3(Bn), 256>>>(out, slen, Wt, bt, out);
}

// round 6
// speedup vs baseline: 2.7426x; 1.0548x over previous
#include <cuda_runtime.h>
#include <cuda_bf16.h>

#define Bn 32
#define Ln 512
#define Hn 256
#define NHn 4
#define DHn 64

// ---------------- scratch (device globals; no allocation) ----------------
__device__ unsigned g_xtf[Bn * Ln * Hn];       // x in tf32 bits
__device__ unsigned g_wtf[5 * Hn * Hn];        // Wq,Wk,Wv,Wtq,Wd in tf32 bits
__device__ unsigned g_q[Bn * Ln * Hn];
__device__ unsigned g_k[Bn * Ln * Hn];
__device__ unsigned g_v[Bn * Ln * Hn];
__device__ unsigned g_tq[Bn * Ln * Hn];
__device__ unsigned g_gm[Bn * Ln * Ln];        // bf16x2 {gate*0.125, mask}
__device__ unsigned g_ctx[Bn * Ln * Hn];

// ---------------- helpers --------------------------------------------
__device__ __forceinline__ unsigned f2tf(float f) {
    unsigned u;
    asm("cvt.rna.tf32.f32 %0, %1;" : "=r"(u) : "f"(f));
    return u;
}
__device__ __forceinline__ float tanh_ap(float x) {
    float y;
    asm("tanh.approx.f32 %0, %1;" : "=f"(y) : "f"(x));
    return y;
}
__device__ __forceinline__ uint4 cvt4(float4 v) {
    return make_uint4(f2tf(v.x), f2tf(v.y), f2tf(v.z), f2tf(v.w));
}
__device__ __forceinline__ void cpa16(void* s, const void* g) {
    unsigned sa = (unsigned)__cvta_generic_to_shared(s);
    asm volatile("cp.async.cg.shared.global [%0], [%1], 16;" :: "r"(sa), "l"(g));
}
#define CP_COMMIT()  asm volatile("cp.async.commit_group;")
#define CP_WAIT1()   asm volatile("cp.async.wait_group 1;")
#define CP_WAIT0()   asm volatile("cp.async.wait_group 0;")

__device__ __forceinline__ void mma_tf32(float* c, const unsigned* a, const unsigned* b) {
    asm volatile(
        "mma.sync.aligned.m16n8k8.row.col.f32.tf32.tf32.f32 "
        "{%0,%1,%2,%3}, {%4,%5,%6,%7}, {%8,%9}, {%0,%1,%2,%3};\n"
        : "+f"(c[0]), "+f"(c[1]), "+f"(c[2]), "+f"(c[3])
        : "r"(a[0]), "r"(a[1]), "r"(a[2]), "r"(a[3]), "r"(b[0]), "r"(b[1]));
}

// ---------------- K-1: pre-convert fp32 -> tf32 bits ----------------------
__global__ __launch_bounds__(256) void cvt_kernel(
    const float4* __restrict__ src, int dstsel, int off4, int n4)
{
    int i = blockIdx.x * blockDim.x + threadIdx.x;
    if (i < n4) {
        uint4* dst = dstsel == 0 ? (uint4*)g_xtf : (uint4*)g_wtf;
        dst[off4 + i] = cvt4(src[i]);
    }
}

// ---------------- K0: fused Q/K/V/TQ projection (tensor + cp.async DB) ----
__global__ __launch_bounds__(128) void proj_mma(
    const float* __restrict__ bq, const float* __restrict__ bk,
    const float* __restrict__ bv, const float* __restrict__ btq)
{
    __shared__ unsigned As[2][64][36];
    __shared__ unsigned Bs[2][64][36];
    const int t = threadIdx.x;
    const int lane = t & 31, warp = t >> 5;
    const int gid = lane >> 2, tig = lane & 3;
    const int m0 = blockIdx.x * 64;
    const int by = blockIdx.y;
    const int wsel = by >> 2, n0 = (by & 3) * 64;
    const int wm = warp * 16;

    const unsigned* W = g_wtf + wsel * (Hn * Hn);
    const float* bias;
    unsigned* out;
    if (wsel == 0)      { bias = bq;  out = g_q;  }
    else if (wsel == 1) { bias = bk;  out = g_k;  }
    else if (wsel == 2) { bias = bv;  out = g_v;  }
    else                { bias = btq; out = g_tq; }

    float c[8][4] = {};

    // prologue: chunk 0 -> buf 0
#pragma unroll
    for (int u = 0; u < 4; ++u) {
        int f = t + 128 * u;
        int row = f >> 3;
        int kq = (f & 7) * 4;
        cpa16(&As[0][row][kq], &g_xtf[(size_t)(m0 + row) * Hn + kq]);
        cpa16(&Bs[0][row][kq], &W[(size_t)(n0 + row) * Hn + kq]);
    }
    CP_COMMIT();

    for (int i = 0; i < 8; ++i) {
        const int buf = i & 1;
        if (i < 7) {
            const int k1 = (i + 1) * 32;
            const int nb = buf ^ 1;
#pragma unroll
            for (int u = 0; u < 4; ++u) {
                int f = t + 128 * u;
                int row = f >> 3;
                int kq = (f & 7) * 4;
                cpa16(&As[nb][row][kq], &g_xtf[(size_t)(m0 + row) * Hn + k1 + kq]);
                cpa16(&Bs[nb][row][kq], &W[(size_t)(n0 + row) * Hn + k1 + kq]);
            }
            CP_COMMIT();
            CP_WAIT1();
        } else {
            CP_WAIT0();
        }
        __syncthreads();
#pragma unroll
        for (int ks = 0; ks < 32; ks += 8) {
            unsigned a[4];
            a[0] = As[buf][wm + gid][ks + tig];
            a[1] = As[buf][wm + gid + 8][ks + tig];
            a[2] = As[buf][wm + gid][ks + tig + 4];
            a[3] = As[buf][wm + gid + 8][ks + tig + 4];
#pragma unroll
            for (int nt = 0; nt < 8; ++nt) {
                unsigned b[2];
                b[0] = Bs[buf][nt * 8 + gid][ks + tig];
                b[1] = Bs[buf][nt * 8 + gid][ks + tig + 4];
                mma_tf32(c[nt], a, b);
            }
        }
        __syncthreads();
    }
#pragma unroll
    for (int nt = 0; nt < 8; ++nt) {
        int cc = n0 + nt * 8 + 2 * tig;
        float2 bb = *(const float2*)&bias[cc];
        size_t r0 = (size_t)(m0 + wm + gid) * Hn;
        size_t r1 = (size_t)(m0 + wm + gid + 8) * Hn;
        *(uint2*)&out[r0 + cc] = make_uint2(f2tf(c[nt][0] + bb.x), f2tf(c[nt][1] + bb.y));
        *(uint2*)&out[r1 + cc] = make_uint2(f2tf(c[nt][2] + bb.x), f2tf(c[nt][3] + bb.y));
    }
}

// ---------------- K1: time-decay gate (tensor + cp.async DB) --------------
__global__ __launch_bounds__(128) void gate_mma(
    const float* __restrict__ tseq,
    const float* __restrict__ tw1, const float* __restrict__ tb1,
    const float* __restrict__ tow1, const float* __restrict__ tow2,
    const float* __restrict__ tob, const float* __restrict__ mask)
{
    __shared__ unsigned As[2][64][36];
    __shared__ unsigned Bs[2][64][36];
    const int t = threadIdx.x;
    const int lane = t & 31, warp = t >> 5;
    const int gid = lane >> 2, tig = lane & 3;
    const int b = blockIdx.z;
    const int m0 = blockIdx.x * 64;
    const int n0 = blockIdx.y * 64;
    const int wm = warp * 16;
    const unsigned* A = g_tq + (size_t)b * Ln * Hn;
    const unsigned* Bm = g_xtf + (size_t)b * Ln * Hn;
    const float* mptr = mask + (size_t)b * Ln * Ln;

    float c[8][4] = {};

#pragma unroll
    for (int u = 0; u < 4; ++u) {
        int f = t + 128 * u;
        int row = f >> 3;
        int kq = (f & 7) * 4;
        cpa16(&As[0][row][kq], &A[(size_t)(m0 + row) * Hn + kq]);
        cpa16(&Bs[0][row][kq], &Bm[(size_t)(n0 + row) * Hn + kq]);
    }
    CP_COMMIT();

    for (int i = 0; i < 8; ++i) {
        const int buf = i & 1;
        if (i < 7) {
            const int k1 = (i + 1) * 32;
            const int nb = buf ^ 1;
#pragma unroll
            for (int u = 0; u < 4; ++u) {
                int f = t + 128 * u;
                int row = f >> 3;
                int kq = (f & 7) * 4;
                cpa16(&As[nb][row][kq], &A[(size_t)(m0 + row) * Hn + k1 + kq]);
                cpa16(&Bs[nb][row][kq], &Bm[(size_t)(n0 + row) * Hn + k1 + kq]);
            }
            CP_COMMIT();
            CP_WAIT1();
        } else {
            CP_WAIT0();
        }
        __syncthreads();
#pragma unroll
        for (int ks = 0; ks < 32; ks += 8) {
            unsigned a[4];
            a[0] = As[buf][wm + gid][ks + tig];
            a[1] = As[buf][wm + gid + 8][ks + tig];
            a[2] = As[buf][wm + gid][ks + tig + 4];
            a[3] = As[buf][wm + gid + 8][ks + tig + 4];
#pragma unroll
            for (int nt = 0; nt < 8; ++nt) {
                unsigned bfr[2];
                bfr[0] = Bs[buf][nt * 8 + gid][ks + tig];
                bfr[1] = Bs[buf][nt * 8 + gid][ks + tig + 4];
                mma_tf32(c[nt], a, bfr);
            }
        }
        __syncthreads();
    }

    const int rl = m0 + wm + gid, rh = rl + 8;
    const float t_lo = tseq[b * Ln + rl];
    const float t_hi = tseq[b * Ln + rh];
    unsigned* gout = g_gm + (size_t)b * Ln * Ln;

#pragma unroll
    for (int nt = 0; nt < 8; ++nt) {
        int cc = n0 + nt * 8 + 2 * tig;
        float2 tc = *(const float2*)&tseq[b * Ln + cc];
#pragma unroll
        for (int half = 0; half < 2; ++half) {
            int r = half ? rh : rl;
            float tr = half ? t_hi : t_lo;
            size_t idx = (size_t)r * Ln + cc;
            float2 w1 = *(const float2*)&tw1[idx];
            float2 b1 = *(const float2*)&tb1[idx];
            float2 o1 = *(const float2*)&tow1[idx];
            float2 o2 = *(const float2*)&tow2[idx];
            float2 ob = *(const float2*)&tob[idx];
            float2 mm = *(const float2*)&mptr[idx];
            float s0 = c[nt][half * 2 + 0], s1 = c[nt][half * 2 + 1];
            float tqk0 = tanh_ap(s0), tqk1 = tanh_ap(s1);
            float d0 = tanh_ap(__logf(1.0f + fabsf(tr - tc.x)) * w1.x + b1.x);
            float d1 = tanh_ap(__logf(1.0f + fabsf(tr - tc.y)) * w1.y + b1.y);
            float g0 = o1.x * d0 + o2.x * tqk0 + ob.x;
            float g1 = o1.y * d1 + o2.y * tqk1 + ob.y;
            g0 = 0.125f / (1.0f + __expf(-g0));
            g1 = 0.125f / (1.0f + __expf(-g1));
            __nv_bfloat162 p0 = __floats2bfloat162_rn(g0, mm.x);
            __nv_bfloat162 p1 = __floats2bfloat162_rn(g1, mm.y);
            *(uint2*)&gout[idx] = make_uint2(*(unsigned*)&p0, *(unsigned*)&p1);
        }
    }
}

// ---------------- K2: fused attention (tensor, flash-style) ---------------
__global__ __launch_bounds__(128) void attn_mma()
{
    __shared__ unsigned QPs[64][68];  // Q tile [q][d] tf32; later per-warp P [16][68]
    __shared__ unsigned Ks[64][68];   // K tile [key][d] tf32
    __shared__ unsigned Vs[64][72];   // V tile [key][d] tf32

    const int t = threadIdx.x;
    const int lane = t & 31, warp = t >> 5;
    const int gid = lane >> 2, tig = lane & 3;
    const int qt = blockIdx.x, h = blockIdx.y, b = blockIdx.z;
    const int q0 = qt * 64;
    const int wm = warp * 16;

    const unsigned* qptr = g_q + (size_t)b * Ln * Hn + h * DHn;
    const unsigned* kptr = g_k + (size_t)b * Ln * Hn + h * DHn;
    const unsigned* vptr = g_v + (size_t)b * Ln * Hn + h * DHn;
    const unsigned* gptr = g_gm + (size_t)b * Ln * Ln;

#pragma unroll
    for (int u = 0; u < 8; ++u) {
        int f = t + 128 * u;
        int row = f >> 4;
        int kq = (f & 15) * 4;
        *(uint4*)&QPs[row][kq] = *(const uint4*)&qptr[(size_t)(q0 + row) * Hn + kq];
    }
    __syncthreads();

    unsigned qf[8][4];
#pragma unroll
    for (int ks = 0; ks < 8; ++ks) {
        int kk = ks * 8;
        qf[ks][0] = QPs[wm + gid][kk + tig];
        qf[ks][1] = QPs[wm + gid + 8][kk + tig];
        qf[ks][2] = QPs[wm + gid][kk + tig + 4];
        qf[ks][3] = QPs[wm + gid + 8][kk + tig + 4];
    }

    float o[8][4] = {};
    float m_lo = -1e30f, m_hi = -1e30f, l_lo = 0.f, l_hi = 0.f;
    unsigned* Pw = &QPs[wm][0];

    const int rl = q0 + wm + gid, rh = rl + 8;

    for (int kb = 0; kb < 8; ++kb) {
        const int c0 = kb * 64;
        __syncthreads();
#pragma unroll
        for (int u = 0; u < 8; ++u) {
            int f = t + 128 * u;
            int row = f >> 4;
            int kq = (f & 15) * 4;
            *(uint4*)&Ks[row][kq] = *(const uint4*)&kptr[(size_t)(c0 + row) * Hn + kq];
            *(uint4*)&Vs[row][kq] = *(const uint4*)&vptr[(size_t)(c0 + row) * Hn + kq];
        }
        __syncthreads();

        float s[8][4] = {};
#pragma unroll
        for (int ks = 0; ks < 8; ++ks) {
            int kk = ks * 8;
#pragma unroll
            for (int nt = 0; nt < 8; ++nt) {
                unsigned bfr[2];
                bfr[0] = Ks[nt * 8 + gid][kk + tig];
                bfr[1] = Ks[nt * 8 + gid][kk + tig + 4];
                mma_tf32(s[nt], qf[ks], bfr);
            }
        }

#pragma unroll
        for (int nt = 0; nt < 8; ++nt) {
            int cc = c0 + nt * 8 + 2 * tig;
            uint2 pl = *(const uint2*)&gptr[(size_t)rl * Ln + cc];
            uint2 ph = *(const uint2*)&gptr[(size_t)rh * Ln + cc];
            float2 e0 = __bfloat1622float2(*(__nv_bfloat162*)&pl.x);
            float2 e1 = __bfloat1622float2(*(__nv_bfloat162*)&pl.y);
            float2 e2 = __bfloat1622float2(*(__nv_bfloat162*)&ph.x);
            float2 e3 = __bfloat1622float2(*(__nv_bfloat162*)&ph.y);
            s[nt][0] = s[nt][0] * e0.x + e0.y;
            s[nt][1] = s[nt][1] * e1.x + e1.y;
            s[nt][2] = s[nt][2] * e2.x + e2.y;
            s[nt][3] = s[nt][3] * e3.x + e3.y;
        }

        float mx_lo = -1e30f, mx_hi = -1e30f;
#pragma unroll
        for (int nt = 0; nt < 8; ++nt) {
            mx_lo = fmaxf(mx_lo, fmaxf(s[nt][0], s[nt][1]));
            mx_hi = fmaxf(mx_hi, fmaxf(s[nt][2], s[nt][3]));
        }
        mx_lo = fmaxf(mx_lo, __shfl_xor_sync(0xffffffffu, mx_lo, 1));
        mx_lo = fmaxf(mx_lo, __shfl_xor_sync(0xffffffffu, mx_lo, 2));
        mx_hi = fmaxf(mx_hi, __shfl_xor_sync(0xffffffffu, mx_hi, 1));
        mx_hi = fmaxf(mx_hi, __shfl_xor_sync(0xffffffffu, mx_hi, 2));
        float mn_lo = fmaxf(m_lo, mx_lo), mn_hi = fmaxf(m_hi, mx_hi);
        float sc_lo = __expf(m_lo - mn_lo), sc_hi = __expf(m_hi - mn_hi);
        m_lo = mn_lo; m_hi = mn_hi;
        float rs_lo = 0.f, rs_hi = 0.f;
#pragma unroll
        for (int nt = 0; nt < 8; ++nt) {
            s[nt][0] = __expf(s[nt][0] - mn_lo);
            s[nt][1] = __expf(s[nt][1] - mn_lo);
            s[nt][2] = __expf(s[nt][2] - mn_hi);
            s[nt][3] = __expf(s[nt][3] - mn_hi);
            rs_lo += s[nt][0] + s[nt][1];
            rs_hi += s[nt][2] + s[nt][3];
        }
        rs_lo += __shfl_xor_sync(0xffffffffu, rs_lo, 1);
        rs_lo += __shfl_xor_sync(0xffffffffu, rs_lo, 2);
        rs_hi += __shfl_xor_sync(0xffffffffu, rs_hi, 1);
        rs_hi += __shfl_xor_sync(0xffffffffu, rs_hi, 2);
        l_lo = l_lo * sc_lo + rs_lo;
        l_hi = l_hi * sc_hi + rs_hi;
#pragma unroll
        for (int dt = 0; dt < 8; ++dt) {
            o[dt][0] *= sc_lo; o[dt][1] *= sc_lo;
            o[dt][2] *= sc_hi; o[dt][3] *= sc_hi;
        }

#pragma unroll
        for (int nt = 0; nt < 8; ++nt) {
            *(uint2*)&Pw[(size_t)gid * 68 + nt * 8 + 2 * tig] =
                make_uint2(f2tf(s[nt][0]), f2tf(s[nt][1]));
            *(uint2*)&Pw[(size_t)(gid + 8) * 68 + nt * 8 + 2 * tig] =
                make_uint2(f2tf(s[nt][2]), f2tf(s[nt][3]));
        }
        __syncwarp();

#pragma unroll
        for (int ks = 0; ks < 8; ++ks) {
            int kk = ks * 8;
            unsigned pa[4];
            pa[0] = Pw[(size_t)gid * 68 + kk + tig];
            pa[1] = Pw[(size_t)(gid + 8) * 68 + kk + tig];
            pa[2] = Pw[(size_t)gid * 68 + kk + tig + 4];
            pa[3] = Pw[(size_t)(gid + 8) * 68 + kk + tig + 4];
#pragma unroll
            for (int dt = 0; dt < 8; ++dt) {
                unsigned bfr[2];
                bfr[0] = Vs[kk + tig][dt * 8 + gid];
                bfr[1] = Vs[kk + tig + 4][dt * 8 + gid];
                mma_tf32(o[dt], pa, bfr);
            }
        }
        __syncwarp();
    }

    float inv_lo = 1.0f / l_lo, inv_hi = 1.0f / l_hi;
    unsigned* cbase = g_ctx + (size_t)b * Ln * Hn + h * DHn;
#pragma unroll
    for (int dt = 0; dt < 8; ++dt) {
        int dd = dt * 8 + 2 * tig;
        *(uint2*)&cbase[(size_t)rl * Hn + dd] =
            make_uint2(f2tf(o[dt][0] * inv_lo), f2tf(o[dt][1] * inv_lo));
        *(uint2*)&cbase[(size_t)rh * Hn + dd] =
            make_uint2(f2tf(o[dt][2] * inv_hi), f2tf(o[dt][3] * inv_hi));
    }
}

// ---------------- K3: output projection + residual + layernorm ------------
// dynamic smem: As[2][64][36] + Bs[2][256][36]
__global__ __launch_bounds__(512) void outln_mma(
    const float* __restrict__ x, const float* __restrict__ bd,
    const float* __restrict__ lng, const float* __restrict__ lnb,
    float* __restrict__ out)
{
    extern __shared__ unsigned dsm[];
    unsigned* As = dsm;             // 2 * 64 * 36  = 4608
    unsigned* Bs = dsm + 4608;      // 2 * 256 * 36 = 18432
    __shared__ float redS[64][4];
    __shared__ float redQ[64][4];

    const int t = threadIdx.x;
    const int lane = t & 31, warp = t >> 5;
    const int gid = lane >> 2, tig = lane & 3;
    const int m0 = blockIdx.x * 64;
    const int mg = warp >> 2;
    const int nq = warp & 3;
    const int wm = mg * 16;
    const int wn = nq * 64;
    const unsigned* Wd = g_wtf + 4 * (Hn * Hn);

    float c[8][4] = {};

    // prologue
    {
        int row = t >> 3, kq = (t & 7) * 4;
        cpa16(&As[row * 36 + kq], &g_ctx[(size_t)(m0 + row) * Hn + kq]);
#pragma unroll
        for (int u = 0; u < 4; ++u) {
            int f = t + 512 * u;
            int r2 = f >> 3, k2 = (f & 7) * 4;
            cpa16(&Bs[r2 * 36 + k2], &Wd[(size_t)r2 * Hn + k2]);
        }
        CP_COMMIT();
    }

    for (int i = 0; i < 8; ++i) {
        const int buf = i & 1;
        if (i < 7) {
            const int k1 = (i + 1) * 32;
            const int nb = buf ^ 1;
            int row = t >> 3, kq = (t & 7) * 4;
            cpa16(&As[nb * 2304 + row * 36 + kq], &g_ctx[(size_t)(m0 + row) * Hn + k1 + kq]);
#pragma unroll
            for (int u = 0; u < 4; ++u) {
                int f = t + 512 * u;
                int r2 = f >> 3, k2 = (f & 7) * 4;
                cpa16(&Bs[nb * 9216 + r2 * 36 + k2], &Wd[(size_t)r2 * Hn + k1 + k2]);
            }
            CP_COMMIT();
            CP_WAIT1();
        } else {
            CP_WAIT0();
        }
        __syncthreads();
#pragma unroll
        for (int ks = 0; ks < 32; ks += 8) {
            unsigned a[4];
            a[0] = As[buf * 2304 + (wm + gid) * 36 + ks + tig];
            a[1] = As[buf * 2304 + (wm + gid + 8) * 36 + ks + tig];
            a[2] = As[buf * 2304 + (wm + gid) * 36 + ks + tig + 4];
            a[3] = As[buf * 2304 + (wm + gid + 8) * 36 + ks + tig + 4];
#pragma unroll
            for (int nt = 0; nt < 8; ++nt) {
                unsigned bfr[2];
                bfr[0] = Bs[buf * 9216 + (wn + nt * 8 + gid) * 36 + ks + tig];
                bfr[1] = Bs[buf * 9216 + (wn + nt * 8 + gid) * 36 + ks + tig + 4];
                mma_tf32(c[nt], a, bfr);
            }
        }
        __syncthreads();
    }

    const int lrl = wm + gid, lrh = lrl + 8;
    const size_t rl = m0 + lrl, rh = m0 + lrh;
    float s_lo = 0.f, s_hi = 0.f, q_lo = 0.f, q_hi = 0.f;
#pragma unroll
    for (int nt = 0; nt < 8; ++nt) {
        int cc = wn + nt * 8 + 2 * tig;
        float2 bb = *(const float2*)&bd[cc];
        float2 xl = *(const float2*)&x[rl * Hn + cc];
        float2 xh = *(const float2*)&x[rh * Hn + cc];
        c[nt][0] += bb.x + xl.x; c[nt][1] += bb.y + xl.y;
        c[nt][2] += bb.x + xh.x; c[nt][3] += bb.y + xh.y;
        s_lo += c[nt][0] + c[nt][1];
        s_hi += c[nt][2] + c[nt][3];
        q_lo += c[nt][0] * c[nt][0] + c[nt][1] * c[nt][1];
        q_hi += c[nt][2] * c[nt][2] + c[nt][3] * c[nt][3];
    }
    s_lo += __shfl_xor_sync(0xffffffffu, s_lo, 1);
    s_lo += __shfl_xor_sync(0xffffffffu, s_lo, 2);
    s_hi += __shfl_xor_sync(0xffffffffu, s_hi, 1);
    s_hi += __shfl_xor_sync(0xffffffffu, s_hi, 2);
    q_lo += __shfl_xor_sync(0xffffffffu, q_lo, 1);
    q_lo += __shfl_xor_sync(0xffffffffu, q_lo, 2);
    q_hi += __shfl_xor_sync(0xffffffffu, q_hi, 1);
    q_hi += __shfl_xor_sync(0xffffffffu, q_hi, 2);
    __syncthreads();
    if (tig == 0) {
        redS[lrl][nq] = s_lo; redQ[lrl][nq] = q_lo;
        redS[lrh][nq] = s_hi; redQ[lrh][nq] = q_hi;
    }
    __syncthreads();
    float mu_lo = (redS[lrl][0] + redS[lrl][1] + redS[lrl][2] + redS[lrl][3]) * (1.0f / Hn);
    float mu_hi = (redS[lrh][0] + redS[lrh][1] + redS[lrh][2] + redS[lrh][3]) * (1.0f / Hn);
    float ex_lo = (redQ[lrl][0] + redQ[lrl][1] + redQ[lrl][2] + redQ[lrl][3]) * (1.0f / Hn);
    float ex_hi = (redQ[lrh][0] + redQ[lrh][1] + redQ[lrh][2] + redQ[lrh][3]) * (1.0f / Hn);
    float iv_lo = rsqrtf(ex_lo - mu_lo * mu_lo + 1e-12f);
    float iv_hi = rsqrtf(ex_hi - mu_hi * mu_hi + 1e-12f);

#pragma unroll
    for (int nt = 0; nt < 8; ++nt) {
        int cc = wn + nt * 8 + 2 * tig;
        float2 g = *(const float2*)&lng[cc];
        float2 be = *(const float2*)&lnb[cc];
        *(float2*)&out[rl * Hn + cc] = make_float2(
            (c[nt][0] - mu_lo) * iv_lo * g.x + be.x,
            (c[nt][1] - mu_lo) * iv_lo * g.y + be.y);
        *(float2*)&out[rh * Hn + cc] = make_float2(
            (c[nt][2] - mu_hi) * iv_hi * g.x + be.x,
            (c[nt][3] - mu_hi) * iv_hi * g.y + be.y);
    }
}

// ---------------- K4: interval prediction head ---------------------------
__global__ __launch_bounds__(256) void pred_kernel(
    const float* __restrict__ hs, const int* __restrict__ slen,
    const float* __restrict__ Wt, const float* __restrict__ bt,
    float* __restrict__ out)
{
    __shared__ float red[256];
    const int b = blockIdx.x;
    const int t = threadIdx.x;
    const int len = slen[b];
    const float* e1 = hs + ((size_t)b * Ln + (len - 1)) * Hn;
    const float* e2 = hs + ((size_t)b * Ln + (len - 2)) * Hn;
    red[t] = Wt[t] * e1[t] + Wt[Hn + t] * e2[t];
    __syncthreads();
    for (int s = 128; s > 0; s >>= 1) {
        if (t < s) red[t] += red[t + s];
        __syncthreads();
    }
    if (t == 0) out[(size_t)Bn * Ln * Hn + b] = red[0] + bt[0];
}

// ---------------- launch --------------------------------------------------
extern "C" void kernel_launch(void* const* d_in, const int* in_sizes, int n_in,
                              void* d_out, int out_size)
{
    const float* x    = (const float*)d_in[0];
    const float* tseq = (const float*)d_in[1];
    const float* mask = (const float*)d_in[2];
    const int*   slen = (const int*)d_in[3];
    const float* Wq   = (const float*)d_in[4];
    const float* bq   = (const float*)d_in[5];
    const float* Wk   = (const float*)d_in[6];
    const float* bk   = (const float*)d_in[7];
    const float* Wv   = (const float*)d_in[8];
    const float* bv   = (const float*)d_in[9];
    const float* Wd   = (const float*)d_in[10];
    const float* bd   = (const float*)d_in[11];
    const float* lng  = (const float*)d_in[12];
    const float* lnb  = (const float*)d_in[13];
    const float* Wtq  = (const float*)d_in[14];
    const float* btq  = (const float*)d_in[15];
    const float* tw1  = (const float*)d_in[16];
    const float* tb1  = (const float*)d_in[17];
    const float* tow1 = (const float*)d_in[18];
    const float* tow2 = (const float*)d_in[19];
    const float* tob  = (const float*)d_in[20];
    const float* Wt   = (const float*)d_in[21];
    const float* bt   = (const float*)d_in[22];
    float* out = (float*)d_out;

    static const int OUTLN_SMEM = (4608 + 18432) * 4;  // 92160 B dynamic
    cudaFuncSetAttribute(outln_mma, cudaFuncAttributeMaxDynamicSharedMemorySize, OUTLN_SMEM);

    // pre-convert x and all weight matrices to tf32 bit patterns
    cvt_kernel<<<4096, 256>>>((const float4*)x,  0, 0, 1048576);
    cvt_kernel<<<64, 256>>>((const float4*)Wq,  1, 0,     16384);
    cvt_kernel<<<64, 256>>>((const float4*)Wk,  1, 16384, 16384);
    cvt_kernel<<<64, 256>>>((const float4*)Wv,  1, 32768, 16384);
    cvt_kernel<<<64, 256>>>((const float4*)Wtq, 1, 49152, 16384);
    cvt_kernel<<<64, 256>>>((const float4*)Wd,  1, 65536, 16384);

    proj_mma<<<dim3(Bn * Ln / 64, 16), 128>>>(bq, bk, bv, btq);
    gate_mma<<<dim3(Ln / 64, Ln / 64, Bn), 128>>>(tseq, tw1, tb1, tow1, tow2, tob, mask);
    attn_mma<<<dim3(Ln / 64, NHn, Bn), 128>>>();
    outln_mma<<<dim3(Bn * Ln / 64), 512, OUTLN_SMEM>>>(x, bd, lng, lnb, out);
    pred_kernel<<<dim3(Bn), 256>>>(out, slen, Wt, bt, out);
}

// round 7
// speedup vs baseline: 2.8476x; 1.0383x over previous
#include <cuda_runtime.h>
#include <cuda_bf16.h>

#define Bn 32
#define Ln 512
#define Hn 256
#define NHn 4
#define DHn 64

// ---------------- scratch (device globals; no allocation) ----------------
__device__ unsigned g_xtf[Bn * Ln * Hn];       // x in tf32 bits
__device__ unsigned g_wtf[5 * Hn * Hn];        // Wq,Wk,Wv,Wtq,Wd in tf32 bits
__device__ unsigned g_q[Bn * Ln * Hn];
__device__ unsigned g_k[Bn * Ln * Hn];
__device__ unsigned g_v[Bn * Ln * Hn];
__device__ unsigned g_tq[Bn * Ln * Hn];
__device__ unsigned g_gm[Bn * Ln * Ln];        // bf16x2 {gate*0.125, mask}
__device__ unsigned g_ctx[Bn * Ln * Hn];

// ---------------- helpers --------------------------------------------
__device__ __forceinline__ unsigned f2tf(float f) {
    unsigned u;
    asm("cvt.rna.tf32.f32 %0, %1;" : "=r"(u) : "f"(f));
    return u;
}
__device__ __forceinline__ float tanh_ap(float x) {
    float y;
    asm("tanh.approx.f32 %0, %1;" : "=f"(y) : "f"(x));
    return y;
}
__device__ __forceinline__ uint4 cvt4(float4 v) {
    return make_uint4(f2tf(v.x), f2tf(v.y), f2tf(v.z), f2tf(v.w));
}
__device__ __forceinline__ void cpa16(void* s, const void* g) {
    unsigned sa = (unsigned)__cvta_generic_to_shared(s);
    asm volatile("cp.async.cg.shared.global [%0], [%1], 16;" :: "r"(sa), "l"(g));
}
#define CP_COMMIT()  asm volatile("cp.async.commit_group;")
#define CP_WAIT1()   asm volatile("cp.async.wait_group 1;")
#define CP_WAIT0()   asm volatile("cp.async.wait_group 0;")

__device__ __forceinline__ void mma_tf32(float* c, const unsigned* a, const unsigned* b) {
    asm volatile(
        "mma.sync.aligned.m16n8k8.row.col.f32.tf32.tf32.f32 "
        "{%0,%1,%2,%3}, {%4,%5,%6,%7}, {%8,%9}, {%0,%1,%2,%3};\n"
        : "+f"(c[0]), "+f"(c[1]), "+f"(c[2]), "+f"(c[3])
        : "r"(a[0]), "r"(a[1]), "r"(a[2]), "r"(a[3]), "r"(b[0]), "r"(b[1]));
}

// shared 64x64x256 tf32 GEMM mainloop with cp.async double buffer
__device__ __forceinline__ void gemm_mainloop(
    const unsigned* __restrict__ Ag, const unsigned* __restrict__ Bg,
    int m0, int n0, int t, int wm, int gid, int tig,
    unsigned (*As)[64][36], unsigned (*Bs)[64][36], float c[8][4])
{
#pragma unroll
    for (int u = 0; u < 4; ++u) {
        int f = t + 128 * u;
        int row = f >> 3;
        int kq = (f & 7) * 4;
        cpa16(&As[0][row][kq], &Ag[(size_t)(m0 + row) * Hn + kq]);
        cpa16(&Bs[0][row][kq], &Bg[(size_t)(n0 + row) * Hn + kq]);
    }
    CP_COMMIT();

    for (int i = 0; i < 8; ++i) {
        const int buf = i & 1;
        if (i < 7) {
            const int k1 = (i + 1) * 32;
            const int nb = buf ^ 1;
#pragma unroll
            for (int u = 0; u < 4; ++u) {
                int f = t + 128 * u;
                int row = f >> 3;
                int kq = (f & 7) * 4;
                cpa16(&As[nb][row][kq], &Ag[(size_t)(m0 + row) * Hn + k1 + kq]);
                cpa16(&Bs[nb][row][kq], &Bg[(size_t)(n0 + row) * Hn + k1 + kq]);
            }
            CP_COMMIT();
            CP_WAIT1();
        } else {
            CP_WAIT0();
        }
        __syncthreads();
#pragma unroll
        for (int ks = 0; ks < 32; ks += 8) {
            unsigned a[4];
            a[0] = As[buf][wm + gid][ks + tig];
            a[1] = As[buf][wm + gid + 8][ks + tig];
            a[2] = As[buf][wm + gid][ks + tig + 4];
            a[3] = As[buf][wm + gid + 8][ks + tig + 4];
#pragma unroll
            for (int nt = 0; nt < 8; ++nt) {
                unsigned b[2];
                b[0] = Bs[buf][nt * 8 + gid][ks + tig];
                b[1] = Bs[buf][nt * 8 + gid][ks + tig + 4];
                mma_tf32(c[nt], a, b);
            }
        }
        __syncthreads();
    }
}

// ---------------- K-1: fused pre-convert fp32 -> tf32 bits ----------------
#define XN4 (Bn * Ln * Hn / 4)     // 1048576
#define WN4 (5 * Hn * Hn / 4)      // 81920
__global__ __launch_bounds__(256) void cvt_all(
    const float4* __restrict__ x,
    const float4* __restrict__ Wq, const float4* __restrict__ Wk,
    const float4* __restrict__ Wv, const float4* __restrict__ Wtq,
    const float4* __restrict__ Wd)
{
    int i = blockIdx.x * 256 + threadIdx.x;
    if (i < XN4) {
        ((uint4*)g_xtf)[i] = cvt4(x[i]);
    } else {
        int j = i - XN4;
        if (j < WN4) {
            int m = j >> 14, r = j & 16383;
            const float4* src = m == 0 ? Wq : m == 1 ? Wk : m == 2 ? Wv : m == 3 ? Wtq : Wd;
            ((uint4*)g_wtf)[j] = cvt4(src[r]);
        }
    }
}

// ---------------- K0a: TQ projection only (critical path for gate) --------
__global__ __launch_bounds__(128) void proj_tq(const float* __restrict__ btq)
{
    __shared__ unsigned As[2][64][36];
    __shared__ unsigned Bs[2][64][36];
    const int t = threadIdx.x;
    const int lane = t & 31, warp = t >> 5;
    const int gid = lane >> 2, tig = lane & 3;
    const int m0 = blockIdx.x * 64;
    const int n0 = blockIdx.y * 64;
    const int wm = warp * 16;

    float c[8][4] = {};
    gemm_mainloop(g_xtf, g_wtf + 3 * Hn * Hn, m0, n0, t, wm, gid, tig, As, Bs, c);

#pragma unroll
    for (int nt = 0; nt < 8; ++nt) {
        int cc = n0 + nt * 8 + 2 * tig;
        float2 bb = *(const float2*)&btq[cc];
        size_t r0 = (size_t)(m0 + wm + gid) * Hn;
        size_t r1 = (size_t)(m0 + wm + gid + 8) * Hn;
        *(uint2*)&g_tq[r0 + cc] = make_uint2(f2tf(c[nt][0] + bb.x), f2tf(c[nt][1] + bb.y));
        *(uint2*)&g_tq[r1 + cc] = make_uint2(f2tf(c[nt][2] + bb.x), f2tf(c[nt][3] + bb.y));
    }
}

// ---------------- K0b: fused gate + Q/K/V projection ----------------------
// grid.x = 2048 (gate: 32 b x 8 mt x 8 nt) + 3072 (qkv: 256 mt x 12 combos)
#define GATE_BLKS 2048
__global__ __launch_bounds__(128) void fused_gate_qkv(
    const float* __restrict__ tseq,
    const float* __restrict__ tw1, const float* __restrict__ tb1,
    const float* __restrict__ tow1, const float* __restrict__ tow2,
    const float* __restrict__ tob, const float* __restrict__ mask,
    const float* __restrict__ bq, const float* __restrict__ bk,
    const float* __restrict__ bv)
{
    __shared__ unsigned As[2][64][36];
    __shared__ unsigned Bs[2][64][36];
    const int t = threadIdx.x;
    const int lane = t & 31, warp = t >> 5;
    const int gid = lane >> 2, tig = lane & 3;
    const int wm = warp * 16;
    const int bid = blockIdx.x;

    float c[8][4] = {};

    if (bid < GATE_BLKS) {
        // ---------------- gate path ----------------
        const int b = bid >> 6;
        const int rem = bid & 63;
        const int m0 = (rem >> 3) * 64;
        const int n0 = (rem & 7) * 64;
        gemm_mainloop(g_tq + (size_t)b * Ln * Hn, g_xtf + (size_t)b * Ln * Hn,
                      m0, n0, t, wm, gid, tig, As, Bs, c);

        const int rl = m0 + wm + gid, rh = rl + 8;
        const float t_lo = tseq[b * Ln + rl];
        const float t_hi = tseq[b * Ln + rh];
        const float* mptr = mask + (size_t)b * Ln * Ln;
        unsigned* gout = g_gm + (size_t)b * Ln * Ln;

#pragma unroll
        for (int nt = 0; nt < 8; ++nt) {
            int cc = n0 + nt * 8 + 2 * tig;
            float2 tc = *(const float2*)&tseq[b * Ln + cc];
#pragma unroll
            for (int half = 0; half < 2; ++half) {
                int r = half ? rh : rl;
                float tr = half ? t_hi : t_lo;
                size_t idx = (size_t)r * Ln + cc;
                float2 w1 = *(const float2*)&tw1[idx];
                float2 b1 = *(const float2*)&tb1[idx];
                float2 o1 = *(const float2*)&tow1[idx];
                float2 o2 = *(const float2*)&tow2[idx];
                float2 ob = *(const float2*)&tob[idx];
                float2 mm = *(const float2*)&mptr[idx];
                float s0 = c[nt][half * 2 + 0], s1 = c[nt][half * 2 + 1];
                float tqk0 = tanh_ap(s0), tqk1 = tanh_ap(s1);
                float d0 = tanh_ap(__logf(1.0f + fabsf(tr - tc.x)) * w1.x + b1.x);
                float d1 = tanh_ap(__logf(1.0f + fabsf(tr - tc.y)) * w1.y + b1.y);
                float g0 = o1.x * d0 + o2.x * tqk0 + ob.x;
                float g1 = o1.y * d1 + o2.y * tqk1 + ob.y;
                g0 = 0.125f / (1.0f + __expf(-g0));
                g1 = 0.125f / (1.0f + __expf(-g1));
                __nv_bfloat162 p0 = __floats2bfloat162_rn(g0, mm.x);
                __nv_bfloat162 p1 = __floats2bfloat162_rn(g1, mm.y);
                *(uint2*)&gout[idx] = make_uint2(*(unsigned*)&p0, *(unsigned*)&p1);
            }
        }
    } else {
        // ---------------- Q/K/V projection path ----------------
        const int pid = bid - GATE_BLKS;
        const int mt = pid / 12, combo = pid % 12;
        const int wsel = combo >> 2;
        const int m0 = mt * 64;
        const int n0 = (combo & 3) * 64;
        const float* bias = wsel == 0 ? bq : wsel == 1 ? bk : bv;
        unsigned* out = wsel == 0 ? g_q : wsel == 1 ? g_k : g_v;

        gemm_mainloop(g_xtf, g_wtf + (size_t)wsel * Hn * Hn,
                      m0, n0, t, wm, gid, tig, As, Bs, c);

#pragma unroll
        for (int nt = 0; nt < 8; ++nt) {
            int cc = n0 + nt * 8 + 2 * tig;
            float2 bb = *(const float2*)&bias[cc];
            size_t r0 = (size_t)(m0 + wm + gid) * Hn;
            size_t r1 = (size_t)(m0 + wm + gid + 8) * Hn;
            *(uint2*)&out[r0 + cc] = make_uint2(f2tf(c[nt][0] + bb.x), f2tf(c[nt][1] + bb.y));
            *(uint2*)&out[r1 + cc] = make_uint2(f2tf(c[nt][2] + bb.x), f2tf(c[nt][3] + bb.y));
        }
    }
}

// ---------------- K2: fused attention (tensor, flash-style) ---------------
__global__ __launch_bounds__(128) void attn_mma()
{
    __shared__ unsigned QPs[64][68];  // Q tile [q][d] tf32; later per-warp P [16][68]
    __shared__ unsigned Ks[64][68];   // K tile [key][d] tf32
    __shared__ unsigned Vs[64][72];   // V tile [key][d] tf32

    const int t = threadIdx.x;
    const int lane = t & 31, warp = t >> 5;
    const int gid = lane >> 2, tig = lane & 3;
    const int qt = blockIdx.x, h = blockIdx.y, b = blockIdx.z;
    const int q0 = qt * 64;
    const int wm = warp * 16;

    const unsigned* qptr = g_q + (size_t)b * Ln * Hn + h * DHn;
    const unsigned* kptr = g_k + (size_t)b * Ln * Hn + h * DHn;
    const unsigned* vptr = g_v + (size_t)b * Ln * Hn + h * DHn;
    const unsigned* gptr = g_gm + (size_t)b * Ln * Ln;

#pragma unroll
    for (int u = 0; u < 8; ++u) {
        int f = t + 128 * u;
        int row = f >> 4;
        int kq = (f & 15) * 4;
        *(uint4*)&QPs[row][kq] = *(const uint4*)&qptr[(size_t)(q0 + row) * Hn + kq];
    }
    __syncthreads();

    unsigned qf[8][4];
#pragma unroll
    for (int ks = 0; ks < 8; ++ks) {
        int kk = ks * 8;
        qf[ks][0] = QPs[wm + gid][kk + tig];
        qf[ks][1] = QPs[wm + gid + 8][kk + tig];
        qf[ks][2] = QPs[wm + gid][kk + tig + 4];
        qf[ks][3] = QPs[wm + gid + 8][kk + tig + 4];
    }

    float o[8][4] = {};
    float m_lo = -1e30f, m_hi = -1e30f, l_lo = 0.f, l_hi = 0.f;
    unsigned* Pw = &QPs[wm][0];

    const int rl = q0 + wm + gid, rh = rl + 8;

    for (int kb = 0; kb < 8; ++kb) {
        const int c0 = kb * 64;
        __syncthreads();
#pragma unroll
        for (int u = 0; u < 8; ++u) {
            int f = t + 128 * u;
            int row = f >> 4;
            int kq = (f & 15) * 4;
            *(uint4*)&Ks[row][kq] = *(const uint4*)&kptr[(size_t)(c0 + row) * Hn + kq];
            *(uint4*)&Vs[row][kq] = *(const uint4*)&vptr[(size_t)(c0 + row) * Hn + kq];
        }
        __syncthreads();

        float s[8][4] = {};
#pragma unroll
        for (int ks = 0; ks < 8; ++ks) {
            int kk = ks * 8;
#pragma unroll
            for (int nt = 0; nt < 8; ++nt) {
                unsigned bfr[2];
                bfr[0] = Ks[nt * 8 + gid][kk + tig];
                bfr[1] = Ks[nt * 8 + gid][kk + tig + 4];
                mma_tf32(s[nt], qf[ks], bfr);
            }
        }

#pragma unroll
        for (int nt = 0; nt < 8; ++nt) {
            int cc = c0 + nt * 8 + 2 * tig;
            uint2 pl = *(const uint2*)&gptr[(size_t)rl * Ln + cc];
            uint2 ph = *(const uint2*)&gptr[(size_t)rh * Ln + cc];
            float2 e0 = __bfloat1622float2(*(__nv_bfloat162*)&pl.x);
            float2 e1 = __bfloat1622float2(*(__nv_bfloat162*)&pl.y);
            float2 e2 = __bfloat1622float2(*(__nv_bfloat162*)&ph.x);
            float2 e3 = __bfloat1622float2(*(__nv_bfloat162*)&ph.y);
            s[nt][0] = s[nt][0] * e0.x + e0.y;
            s[nt][1] = s[nt][1] * e1.x + e1.y;
            s[nt][2] = s[nt][2] * e2.x + e2.y;
            s[nt][3] = s[nt][3] * e3.x + e3.y;
        }

        float mx_lo = -1e30f, mx_hi = -1e30f;
#pragma unroll
        for (int nt = 0; nt < 8; ++nt) {
            mx_lo = fmaxf(mx_lo, fmaxf(s[nt][0], s[nt][1]));
            mx_hi = fmaxf(mx_hi, fmaxf(s[nt][2], s[nt][3]));
        }
        mx_lo = fmaxf(mx_lo, __shfl_xor_sync(0xffffffffu, mx_lo, 1));
        mx_lo = fmaxf(mx_lo, __shfl_xor_sync(0xffffffffu, mx_lo, 2));
        mx_hi = fmaxf(mx_hi, __shfl_xor_sync(0xffffffffu, mx_hi, 1));
        mx_hi = fmaxf(mx_hi, __shfl_xor_sync(0xffffffffu, mx_hi, 2));
        float mn_lo = fmaxf(m_lo, mx_lo), mn_hi = fmaxf(m_hi, mx_hi);
        float sc_lo = __expf(m_lo - mn_lo), sc_hi = __expf(m_hi - mn_hi);
        m_lo = mn_lo; m_hi = mn_hi;
        float rs_lo = 0.f, rs_hi = 0.f;
#pragma unroll
        for (int nt = 0; nt < 8; ++nt) {
            s[nt][0] = __expf(s[nt][0] - mn_lo);
            s[nt][1] = __expf(s[nt][1] - mn_lo);
            s[nt][2] = __expf(s[nt][2] - mn_hi);
            s[nt][3] = __expf(s[nt][3] - mn_hi);
            rs_lo += s[nt][0] + s[nt][1];
            rs_hi += s[nt][2] + s[nt][3];
        }
        rs_lo += __shfl_xor_sync(0xffffffffu, rs_lo, 1);
        rs_lo += __shfl_xor_sync(0xffffffffu, rs_lo, 2);
        rs_hi += __shfl_xor_sync(0xffffffffu, rs_hi, 1);
        rs_hi += __shfl_xor_sync(0xffffffffu, rs_hi, 2);
        l_lo = l_lo * sc_lo + rs_lo;
        l_hi = l_hi * sc_hi + rs_hi;
#pragma unroll
        for (int dt = 0; dt < 8; ++dt) {
            o[dt][0] *= sc_lo; o[dt][1] *= sc_lo;
            o[dt][2] *= sc_hi; o[dt][3] *= sc_hi;
        }

#pragma unroll
        for (int nt = 0; nt < 8; ++nt) {
            *(uint2*)&Pw[(size_t)gid * 68 + nt * 8 + 2 * tig] =
                make_uint2(f2tf(s[nt][0]), f2tf(s[nt][1]));
            *(uint2*)&Pw[(size_t)(gid + 8) * 68 + nt * 8 + 2 * tig] =
                make_uint2(f2tf(s[nt][2]), f2tf(s[nt][3]));
        }
        __syncwarp();

#pragma unroll
        for (int ks = 0; ks < 8; ++ks) {
            int kk = ks * 8;
            unsigned pa[4];
            pa[0] = Pw[(size_t)gid * 68 + kk + tig];
            pa[1] = Pw[(size_t)(gid + 8) * 68 + kk + tig];
            pa[2] = Pw[(size_t)gid * 68 + kk + tig + 4];
            pa[3] = Pw[(size_t)(gid + 8) * 68 + kk + tig + 4];
#pragma unroll
            for (int dt = 0; dt < 8; ++dt) {
                unsigned bfr[2];
                bfr[0] = Vs[kk + tig][dt * 8 + gid];
                bfr[1] = Vs[kk + tig + 4][dt * 8 + gid];
                mma_tf32(o[dt], pa, bfr);
            }
        }
        __syncwarp();
    }

    float inv_lo = 1.0f / l_lo, inv_hi = 1.0f / l_hi;
    unsigned* cbase = g_ctx + (size_t)b * Ln * Hn + h * DHn;
#pragma unroll
    for (int dt = 0; dt < 8; ++dt) {
        int dd = dt * 8 + 2 * tig;
        *(uint2*)&cbase[(size_t)rl * Hn + dd] =
            make_uint2(f2tf(o[dt][0] * inv_lo), f2tf(o[dt][1] * inv_lo));
        *(uint2*)&cbase[(size_t)rh * Hn + dd] =
            make_uint2(f2tf(o[dt][2] * inv_hi), f2tf(o[dt][3] * inv_hi));
    }
}

// ---------------- K3: output projection + residual + layernorm ------------
__global__ __launch_bounds__(512) void outln_mma(
    const float* __restrict__ x, const float* __restrict__ bd,
    const float* __restrict__ lng, const float* __restrict__ lnb,
    float* __restrict__ out)
{
    extern __shared__ unsigned dsm[];
    unsigned* As = dsm;             // 2 * 64 * 36  = 4608
    unsigned* Bs = dsm + 4608;      // 2 * 256 * 36 = 18432
    __shared__ float redS[64][4];
    __shared__ float redQ[64][4];

    const int t = threadIdx.x;
    const int lane = t & 31, warp = t >> 5;
    const int gid = lane >> 2, tig = lane & 3;
    const int m0 = blockIdx.x * 64;
    const int mg = warp >> 2;
    const int nq = warp & 3;
    const int wm = mg * 16;
    const int wn = nq * 64;
    const unsigned* Wd = g_wtf + 4 * (Hn * Hn);

    float c[8][4] = {};

    {
        int row = t >> 3, kq = (t & 7) * 4;
        cpa16(&As[row * 36 + kq], &g_ctx[(size_t)(m0 + row) * Hn + kq]);
#pragma unroll
        for (int u = 0; u < 4; ++u) {
            int f = t + 512 * u;
            int r2 = f >> 3, k2 = (f & 7) * 4;
            cpa16(&Bs[r2 * 36 + k2], &Wd[(size_t)r2 * Hn + k2]);
        }
        CP_COMMIT();
    }

    for (int i = 0; i < 8; ++i) {
        const int buf = i & 1;
        if (i < 7) {
            const int k1 = (i + 1) * 32;
            const int nb = buf ^ 1;
            int row = t >> 3, kq = (t & 7) * 4;
            cpa16(&As[nb * 2304 + row * 36 + kq], &g_ctx[(size_t)(m0 + row) * Hn + k1 + kq]);
#pragma unroll
            for (int u = 0; u < 4; ++u) {
                int f = t + 512 * u;
                int r2 = f >> 3, k2 = (f & 7) * 4;
                cpa16(&Bs[nb * 9216 + r2 * 36 + k2], &Wd[(size_t)r2 * Hn + k1 + k2]);
            }
            CP_COMMIT();
            CP_WAIT1();
        } else {
            CP_WAIT0();
        }
        __syncthreads();
#pragma unroll
        for (int ks = 0; ks < 32; ks += 8) {
            unsigned a[4];
            a[0] = As[buf * 2304 + (wm + gid) * 36 + ks + tig];
            a[1] = As[buf * 2304 + (wm + gid + 8) * 36 + ks + tig];
            a[2] = As[buf * 2304 + (wm + gid) * 36 + ks + tig + 4];
            a[3] = As[buf * 2304 + (wm + gid + 8) * 36 + ks + tig + 4];
#pragma unroll
            for (int nt = 0; nt < 8; ++nt) {
                unsigned bfr[2];
                bfr[0] = Bs[buf * 9216 + (wn + nt * 8 + gid) * 36 + ks + tig];
                bfr[1] = Bs[buf * 9216 + (wn + nt * 8 + gid) * 36 + ks + tig + 4];
                mma_tf32(c[nt], a, bfr);
            }
        }
        __syncthreads();
    }

    const int lrl = wm + gid, lrh = lrl + 8;
    const size_t rl = m0 + lrl, rh = m0 + lrh;
    float s_lo = 0.f, s_hi = 0.f, q_lo = 0.f, q_hi = 0.f;
#pragma unroll
    for (int nt = 0; nt < 8; ++nt) {
        int cc = wn + nt * 8 + 2 * tig;
        float2 bb = *(const float2*)&bd[cc];
        float2 xl = *(const float2*)&x[rl * Hn + cc];
        float2 xh = *(const float2*)&x[rh * Hn + cc];
        c[nt][0] += bb.x + xl.x; c[nt][1] += bb.y + xl.y;
        c[nt][2] += bb.x + xh.x; c[nt][3] += bb.y + xh.y;
        s_lo += c[nt][0] + c[nt][1];
        s_hi += c[nt][2] + c[nt][3];
        q_lo += c[nt][0] * c[nt][0] + c[nt][1] * c[nt][1];
        q_hi += c[nt][2] * c[nt][2] + c[nt][3] * c[nt][3];
    }
    s_lo += __shfl_xor_sync(0xffffffffu, s_lo, 1);
    s_lo += __shfl_xor_sync(0xffffffffu, s_lo, 2);
    s_hi += __shfl_xor_sync(0xffffffffu, s_hi, 1);
    s_hi += __shfl_xor_sync(0xffffffffu, s_hi, 2);
    q_lo += __shfl_xor_sync(0xffffffffu, q_lo, 1);
    q_lo += __shfl_xor_sync(0xffffffffu, q_lo, 2);
    q_hi += __shfl_xor_sync(0xffffffffu, q_hi, 1);
    q_hi += __shfl_xor_sync(0xffffffffu, q_hi, 2);
    __syncthreads();
    if (tig == 0) {
        redS[lrl][nq] = s_lo; redQ[lrl][nq] = q_lo;
        redS[lrh][nq] = s_hi; redQ[lrh][nq] = q_hi;
    }
    __syncthreads();
    float mu_lo = (redS[lrl][0] + redS[lrl][1] + redS[lrl][2] + redS[lrl][3]) * (1.0f / Hn);
    float mu_hi = (redS[lrh][0] + redS[lrh][1] + redS[lrh][2] + redS[lrh][3]) * (1.0f / Hn);
    float ex_lo = (redQ[lrl][0] + redQ[lrl][1] + redQ[lrl][2] + redQ[lrl][3]) * (1.0f / Hn);
    float ex_hi = (redQ[lrh][0] + redQ[lrh][1] + redQ[lrh][2] + redQ[lrh][3]) * (1.0f / Hn);
    float iv_lo = rsqrtf(ex_lo - mu_lo * mu_lo + 1e-12f);
    float iv_hi = rsqrtf(ex_hi - mu_hi * mu_hi + 1e-12f);

#pragma unroll
    for (int nt = 0; nt < 8; ++nt) {
        int cc = wn + nt * 8 + 2 * tig;
        float2 g = *(const float2*)&lng[cc];
        float2 be = *(const float2*)&lnb[cc];
        *(float2*)&out[rl * Hn + cc] = make_float2(
            (c[nt][0] - mu_lo) * iv_lo * g.x + be.x,
            (c[nt][1] - mu_lo) * iv_lo * g.y + be.y);
        *(float2*)&out[rh * Hn + cc] = make_float2(
            (c[nt][2] - mu_hi) * iv_hi * g.x + be.x,
            (c[nt][3] - mu_hi) * iv_hi * g.y + be.y);
    }
}

// ---------------- K4: interval prediction head ---------------------------
__global__ __launch_bounds__(256) void pred_kernel(
    const float* __restrict__ hs, const int* __restrict__ slen,
    const float* __restrict__ Wt, const float* __restrict__ bt,
    float* __restrict__ out)
{
    __shared__ float red[256];
    const int b = blockIdx.x;
    const int t = threadIdx.x;
    const int len = slen[b];
    const float* e1 = hs + ((size_t)b * Ln + (len - 1)) * Hn;
    const float* e2 = hs + ((size_t)b * Ln + (len - 2)) * Hn;
    red[t] = Wt[t] * e1[t] + Wt[Hn + t] * e2[t];
    __syncthreads();
    for (int s = 128; s > 0; s >>= 1) {
        if (t < s) red[t] += red[t + s];
        __syncthreads();
    }
    if (t == 0) out[(size_t)Bn * Ln * Hn + b] = red[0] + bt[0];
}

// ---------------- launch --------------------------------------------------
extern "C" void kernel_launch(void* const* d_in, const int* in_sizes, int n_in,
                              void* d_out, int out_size)
{
    const float* x    = (const float*)d_in[0];
    const float* tseq = (const float*)d_in[1];
    const float* mask = (const float*)d_in[2];
    const int*   slen = (const int*)d_in[3];
    const float* Wq   = (const float*)d_in[4];
    const float* bq   = (const float*)d_in[5];
    const float* Wk   = (const float*)d_in[6];
    const float* bk   = (const float*)d_in[7];
    const float* Wv   = (const float*)d_in[8];
    const float* bv   = (const float*)d_in[9];
    const float* Wd   = (const float*)d_in[10];
    const float* bd   = (const float*)d_in[11];
    const float* lng  = (const float*)d_in[12];
    const float* lnb  = (const float*)d_in[13];
    const float* Wtq  = (const float*)d_in[14];
    const float* btq  = (const float*)d_in[15];
    const float* tw1  = (const float*)d_in[16];
    const float* tb1  = (const float*)d_in[17];
    const float* tow1 = (const float*)d_in[18];
    const float* tow2 = (const float*)d_in[19];
    const float* tob  = (const float*)d_in[20];
    const float* Wt   = (const float*)d_in[21];
    const float* bt   = (const float*)d_in[22];
    float* out = (float*)d_out;

    static const int OUTLN_SMEM = (4608 + 18432) * 4;  // 92160 B dynamic
    cudaFuncSetAttribute(outln_mma, cudaFuncAttributeMaxDynamicSharedMemorySize, OUTLN_SMEM);

    cvt_all<<<(XN4 + WN4 + 255) / 256, 256>>>(
        (const float4*)x, (const float4*)Wq, (const float4*)Wk,
        (const float4*)Wv, (const float4*)Wtq, (const float4*)Wd);
    proj_tq<<<dim3(Bn * Ln / 64, 4), 128>>>(btq);
    fused_gate_qkv<<<GATE_BLKS + 3072, 128>>>(
        tseq, tw1, tb1, tow1, tow2, tob, mask, bq, bk, bv);
    attn_mma<<<dim3(Ln / 64, NHn, Bn), 128>>>();
    outln_mma<<<dim3(Bn * Ln / 64), 512, OUTLN_SMEM>>>(x, bd, lng, lnb, out);
    pred_kernel<<<dim3(Bn), 256>>>(out, slen, Wt, bt, out);
}

// round 10
// speedup vs baseline: 2.9442x; 1.0339x over previous
#include <cuda_runtime.h>
#include <cuda_bf16.h>

#define Bn 32
#define Ln 512
#define Hn 256
#define NHn 4
#define DHn 64

// ---------------- scratch (device globals; no allocation) ----------------
__device__ __align__(16) unsigned g_xtf[Bn * Ln * Hn];          // x in tf32 bits
__device__ __align__(16) unsigned g_wtf[5 * Hn * Hn];           // Wq,Wk,Wv,Wtq,Wd tf32
__device__ __align__(16) unsigned g_q16[Bn * Ln * (Hn / 2)];    // q bf16 pairs [token][128]
__device__ __align__(16) unsigned g_k16[Bn * Ln * (Hn / 2)];    // k bf16 pairs
__device__ __align__(16) __nv_bfloat16 g_vt16[Bn * NHn * DHn * Ln]; // V^T [b,h][d][token]
__device__ __align__(16) unsigned g_tq[Bn * Ln * Hn];           // tf32
__device__ __align__(16) unsigned g_gm[Bn * Ln * Ln];           // bf16x2 {gate/8, mask}
__device__ __align__(16) unsigned g_ctx[Bn * Ln * Hn];          // tf32

// ---------------- helpers --------------------------------------------
__device__ __forceinline__ unsigned f2tf(float f) {
    unsigned u;
    asm("cvt.rna.tf32.f32 %0, %1;" : "=r"(u) : "f"(f));
    return u;
}
__device__ __forceinline__ float tanh_ap(float x) {
    float y;
    asm("tanh.approx.f32 %0, %1;" : "=f"(y) : "f"(x));
    return y;
}
__device__ __forceinline__ uint4 cvt4(float4 v) {
    return make_uint4(f2tf(v.x), f2tf(v.y), f2tf(v.z), f2tf(v.w));
}
__device__ __forceinline__ unsigned packbf(float lo, float hi) {
    __nv_bfloat162 p = __floats2bfloat162_rn(lo, hi);
    return *(unsigned*)&p;
}
__device__ __forceinline__ void cpa16(void* s, const void* g) {
    unsigned sa = (unsigned)__cvta_generic_to_shared(s);
    asm volatile("cp.async.cg.shared.global [%0], [%1], 16;" :: "r"(sa), "l"(g));
}
#define CP_COMMIT()  asm volatile("cp.async.commit_group;")
#define CP_WAIT1()   asm volatile("cp.async.wait_group 1;")
#define CP_WAIT0()   asm volatile("cp.async.wait_group 0;")

__device__ __forceinline__ void mma_tf32(float* c, const unsigned* a, const unsigned* b) {
    asm volatile(
        "mma.sync.aligned.m16n8k8.row.col.f32.tf32.tf32.f32 "
        "{%0,%1,%2,%3}, {%4,%5,%6,%7}, {%8,%9}, {%0,%1,%2,%3};\n"
        : "+f"(c[0]), "+f"(c[1]), "+f"(c[2]), "+f"(c[3])
        : "r"(a[0]), "r"(a[1]), "r"(a[2]), "r"(a[3]), "r"(b[0]), "r"(b[1]));
}
__device__ __forceinline__ void mma_bf16(float* c, const unsigned* a, const unsigned* b) {
    asm volatile(
        "mma.sync.aligned.m16n8k16.row.col.f32.bf16.bf16.f32 "
        "{%0,%1,%2,%3}, {%4,%5,%6,%7}, {%8,%9}, {%0,%1,%2,%3};\n"
        : "+f"(c[0]), "+f"(c[1]), "+f"(c[2]), "+f"(c[3])
        : "r"(a[0]), "r"(a[1]), "r"(a[2]), "r"(a[3]), "r"(b[0]), "r"(b[1]));
}

// shared 64x64x256 tf32 GEMM mainloop with cp.async double buffer
__device__ __forceinline__ void gemm_mainloop(
    const unsigned* __restrict__ Ag, const unsigned* __restrict__ Bg,
    int m0, int n0, int t, int wm, int gid, int tig,
    unsigned (*As)[64][36], unsigned (*Bs)[64][36], float c[8][4])
{
#pragma unroll
    for (int u = 0; u < 4; ++u) {
        int f = t + 128 * u;
        int row = f >> 3;
        int kq = (f & 7) * 4;
        cpa16(&As[0][row][kq], &Ag[(size_t)(m0 + row) * Hn + kq]);
        cpa16(&Bs[0][row][kq], &Bg[(size_t)(n0 + row) * Hn + kq]);
    }
    CP_COMMIT();

    for (int i = 0; i < 8; ++i) {
        const int buf = i & 1;
        if (i < 7) {
            const int k1 = (i + 1) * 32;
            const int nb = buf ^ 1;
#pragma unroll
            for (int u = 0; u < 4; ++u) {
                int f = t + 128 * u;
                int row = f >> 3;
                int kq = (f & 7) * 4;
                cpa16(&As[nb][row][kq], &Ag[(size_t)(m0 + row) * Hn + k1 + kq]);
                cpa16(&Bs[nb][row][kq], &Bg[(size_t)(n0 + row) * Hn + k1 + kq]);
            }
            CP_COMMIT();
            CP_WAIT1();
        } else {
            CP_WAIT0();
        }
        __syncthreads();
#pragma unroll
        for (int ks = 0; ks < 32; ks += 8) {
            unsigned a[4];
            a[0] = As[buf][wm + gid][ks + tig];
            a[1] = As[buf][wm + gid + 8][ks + tig];
            a[2] = As[buf][wm + gid][ks + tig + 4];
            a[3] = As[buf][wm + gid + 8][ks + tig + 4];
#pragma unroll
            for (int nt = 0; nt < 8; ++nt) {
                unsigned b[2];
                b[0] = Bs[buf][nt * 8 + gid][ks + tig];
                b[1] = Bs[buf][nt * 8 + gid][ks + tig + 4];
                mma_tf32(c[nt], a, b);
            }
        }
        __syncthreads();
    }
}

// ---------------- K-1: fused pre-convert fp32 -> tf32 bits ----------------
#define XN4 (Bn * Ln * Hn / 4)     // 1048576
#define WN4 (5 * Hn * Hn / 4)      // 81920
__global__ __launch_bounds__(256) void cvt_all(
    const float4* __restrict__ x,
    const float4* __restrict__ Wq, const float4* __restrict__ Wk,
    const float4* __restrict__ Wv, const float4* __restrict__ Wtq,
    const float4* __restrict__ Wd)
{
    int i = blockIdx.x * 256 + threadIdx.x;
    if (i < XN4) {
        ((uint4*)g_xtf)[i] = cvt4(x[i]);
    } else {
        int j = i - XN4;
        if (j < WN4) {
            int m = j >> 14, r = j & 16383;
            const float4* src = m == 0 ? Wq : m == 1 ? Wk : m == 2 ? Wv : m == 3 ? Wtq : Wd;
            ((uint4*)g_wtf)[j] = cvt4(src[r]);
        }
    }
}

// ---------------- K0a: TQ projection only (critical path for gate) --------
__global__ __launch_bounds__(128) void proj_tq(const float* __restrict__ btq)
{
    __shared__ unsigned As[2][64][36];
    __shared__ unsigned Bs[2][64][36];
    const int t = threadIdx.x;
    const int lane = t & 31, warp = t >> 5;
    const int gid = lane >> 2, tig = lane & 3;
    const int m0 = blockIdx.x * 64;
    const int n0 = blockIdx.y * 64;
    const int wm = warp * 16;

    float c[8][4] = {};
    gemm_mainloop(g_xtf, g_wtf + 3 * Hn * Hn, m0, n0, t, wm, gid, tig, As, Bs, c);

#pragma unroll
    for (int nt = 0; nt < 8; ++nt) {
        int cc = n0 + nt * 8 + 2 * tig;
        float2 bb = *(const float2*)&btq[cc];
        size_t r0 = (size_t)(m0 + wm + gid) * Hn;
        size_t r1 = (size_t)(m0 + wm + gid + 8) * Hn;
        *(uint2*)&g_tq[r0 + cc] = make_uint2(f2tf(c[nt][0] + bb.x), f2tf(c[nt][1] + bb.y));
        *(uint2*)&g_tq[r1 + cc] = make_uint2(f2tf(c[nt][2] + bb.x), f2tf(c[nt][3] + bb.y));
    }
}

// ---------------- K0b: fused gate + Q/K/V projection ----------------------
#define GATE_BLKS 2048
__global__ __launch_bounds__(128) void fused_gate_qkv(
    const float* __restrict__ tseq,
    const float* __restrict__ tw1, const float* __restrict__ tb1,
    const float* __restrict__ tow1, const float* __restrict__ tow2,
    const float* __restrict__ tob, const float* __restrict__ mask,
    const float* __restrict__ bq, const float* __restrict__ bk,
    const float* __restrict__ bv)
{
    __shared__ unsigned As[2][64][36];
    __shared__ unsigned Bs[2][64][36];
    const int t = threadIdx.x;
    const int lane = t & 31, warp = t >> 5;
    const int gid = lane >> 2, tig = lane & 3;
    const int wm = warp * 16;
    const int bid = blockIdx.x;

    float c[8][4] = {};

    if (bid < GATE_BLKS) {
        // ---------------- gate path ----------------
        const int b = bid >> 6;
        const int rem = bid & 63;
        const int m0 = (rem >> 3) * 64;
        const int n0 = (rem & 7) * 64;
        gemm_mainloop(g_tq + (size_t)b * Ln * Hn, g_xtf + (size_t)b * Ln * Hn,
                      m0, n0, t, wm, gid, tig, As, Bs, c);

        const int rl = m0 + wm + gid, rh = rl + 8;
        const float t_lo = tseq[b * Ln + rl];
        const float t_hi = tseq[b * Ln + rh];
        const float* mptr = mask + (size_t)b * Ln * Ln;
        unsigned* gout = g_gm + (size_t)b * Ln * Ln;

#pragma unroll
        for (int nt = 0; nt < 8; ++nt) {
            int cc = n0 + nt * 8 + 2 * tig;
            float2 tc = *(const float2*)&tseq[b * Ln + cc];
#pragma unroll
            for (int half = 0; half < 2; ++half) {
                int r = half ? rh : rl;
                float tr = half ? t_hi : t_lo;
                size_t idx = (size_t)r * Ln + cc;
                float2 w1 = *(const float2*)&tw1[idx];
                float2 b1 = *(const float2*)&tb1[idx];
                float2 o1 = *(const float2*)&tow1[idx];
                float2 o2 = *(const float2*)&tow2[idx];
                float2 ob = *(const float2*)&tob[idx];
                float2 mm = *(const float2*)&mptr[idx];
                float s0 = c[nt][half * 2 + 0], s1 = c[nt][half * 2 + 1];
                float tqk0 = tanh_ap(s0), tqk1 = tanh_ap(s1);
                float d0 = tanh_ap(__logf(1.0f + fabsf(tr - tc.x)) * w1.x + b1.x);
                float d1 = tanh_ap(__logf(1.0f + fabsf(tr - tc.y)) * w1.y + b1.y);
                float g0 = o1.x * d0 + o2.x * tqk0 + ob.x;
                float g1 = o1.y * d1 + o2.y * tqk1 + ob.y;
                g0 = 0.125f / (1.0f + __expf(-g0));
                g1 = 0.125f / (1.0f + __expf(-g1));
                __nv_bfloat162 p0 = __floats2bfloat162_rn(g0, mm.x);
                __nv_bfloat162 p1 = __floats2bfloat162_rn(g1, mm.y);
                *(uint2*)&gout[idx] = make_uint2(*(unsigned*)&p0, *(unsigned*)&p1);
            }
        }
    } else {
        // ---------------- Q/K/V projection path ----------------
        const int pid = bid - GATE_BLKS;
        const int mt = pid / 12, combo = pid % 12;
        const int wsel = combo >> 2;
        const int m0 = mt * 64;
        const int n0 = (combo & 3) * 64;
        const float* bias = wsel == 0 ? bq : wsel == 1 ? bk : bv;

        gemm_mainloop(g_xtf, g_wtf + (size_t)wsel * Hn * Hn,
                      m0, n0, t, wm, gid, tig, As, Bs, c);

        const int r0 = m0 + wm + gid, r1 = r0 + 8;
        if (wsel < 2) {
            unsigned* out16 = wsel == 0 ? g_q16 : g_k16;
#pragma unroll
            for (int nt = 0; nt < 8; ++nt) {
                int cc = n0 + nt * 8 + 2 * tig;
                float2 bb = *(const float2*)&bias[cc];
                out16[(size_t)r0 * 128 + (cc >> 1)] = packbf(c[nt][0] + bb.x, c[nt][1] + bb.y);
                out16[(size_t)r1 * 128 + (cc >> 1)] = packbf(c[nt][2] + bb.x, c[nt][3] + bb.y);
            }
        } else {
            // V: write transposed bf16 [b,h][d][token]
            const int bb0 = r0 >> 9;              // batch
            const int tk0 = r0 & 511;             // token within batch
#pragma unroll
            for (int nt = 0; nt < 8; ++nt) {
                int cc = n0 + nt * 8 + 2 * tig;
                float2 bbv = *(const float2*)&bias[cc];
                int hh = cc >> 6, dl = cc & 63;
                size_t base = ((size_t)(bb0 * NHn + hh) * DHn + dl) * Ln + tk0;
                g_vt16[base]           = __float2bfloat16(c[nt][0] + bbv.x);
                g_vt16[base + Ln]      = __float2bfloat16(c[nt][1] + bbv.y);
                g_vt16[base + 8]       = __float2bfloat16(c[nt][2] + bbv.x);
                g_vt16[base + Ln + 8]  = __float2bfloat16(c[nt][3] + bbv.y);
            }
        }
    }
}

// ---------------- K2: fused attention (bf16 tensor, flash-style) ----------
__global__ __launch_bounds__(128) void attn_mma()
{
    __shared__ unsigned Qs[64][36];   // Q bf16 pairs [q][dpair]
    __shared__ unsigned Ks[64][36];   // K bf16 pairs [key][dpair]
    __shared__ unsigned Vp[64][36];   // V bf16 pairs transposed [d][keypair]

    const int t = threadIdx.x;
    const int lane = t & 31, warp = t >> 5;
    const int gid = lane >> 2, tig = lane & 3;
    const int qt = blockIdx.x, h = blockIdx.y, b = blockIdx.z;
    const int q0 = qt * 64;
    const int wm = warp * 16;

    const unsigned* qptr = g_q16 + (size_t)b * Ln * 128 + h * 32;
    const unsigned* kptr = g_k16 + (size_t)b * Ln * 128 + h * 32;
    const unsigned* vtp = (const unsigned*)(g_vt16 + ((size_t)(b * NHn + h)) * DHn * Ln);
    const unsigned* gptr = g_gm + (size_t)b * Ln * Ln;

    // load Q tile: 64 rows x 32 pairs
#pragma unroll
    for (int u = 0; u < 4; ++u) {
        int f = t + 128 * u;
        int row = f >> 3;
        int ch = (f & 7) * 4;
        *(uint4*)&Qs[row][ch] = *(const uint4*)&qptr[(size_t)(q0 + row) * 128 + ch];
    }
    __syncthreads();

    // Q A-fragments (held in regs): 4 k-steps x 4 regs
    unsigned qf[4][4];
#pragma unroll
    for (int ks = 0; ks < 4; ++ks) {
        qf[ks][0] = Qs[wm + gid][ks * 8 + tig];
        qf[ks][1] = Qs[wm + gid + 8][ks * 8 + tig];
        qf[ks][2] = Qs[wm + gid][ks * 8 + 4 + tig];
        qf[ks][3] = Qs[wm + gid + 8][ks * 8 + 4 + tig];
    }

    float o[8][4] = {};
    float m_lo = -1e30f, m_hi = -1e30f, l_lo = 0.f, l_hi = 0.f;
    const int rl = q0 + wm + gid, rh = rl + 8;

    for (int kb = 0; kb < 8; ++kb) {
        const int c0 = kb * 64;
        __syncthreads();
        // K tile [key][dpair], V tile transposed [d][keypair]
#pragma unroll
        for (int u = 0; u < 4; ++u) {
            int f = t + 128 * u;
            int row = f >> 3;
            int ch = (f & 7) * 4;
            *(uint4*)&Ks[row][ch] = *(const uint4*)&kptr[(size_t)(c0 + row) * 128 + ch];
            *(uint4*)&Vp[row][ch] = *(const uint4*)&vtp[(size_t)row * 256 + (c0 >> 1) + ch];
        }
        __syncthreads();

        // S = Q @ K^T  (bf16, 4 k-steps)
        float s[8][4] = {};
#pragma unroll
        for (int ks = 0; ks < 4; ++ks) {
#pragma unroll
            for (int nt = 0; nt < 8; ++nt) {
                unsigned bfr[2];
                bfr[0] = Ks[nt * 8 + gid][ks * 8 + tig];
                bfr[1] = Ks[nt * 8 + gid][ks * 8 + 4 + tig];
                mma_bf16(s[nt], qf[ks], bfr);
            }
        }

        // epilogue: s*gate + mask  (bf16x2 packed)
#pragma unroll
        for (int nt = 0; nt < 8; ++nt) {
            int cc = c0 + nt * 8 + 2 * tig;
            uint2 pl = *(const uint2*)&gptr[(size_t)rl * Ln + cc];
            uint2 ph = *(const uint2*)&gptr[(size_t)rh * Ln + cc];
            float2 e0 = __bfloat1622float2(*(__nv_bfloat162*)&pl.x);
            float2 e1 = __bfloat1622float2(*(__nv_bfloat162*)&pl.y);
            float2 e2 = __bfloat1622float2(*(__nv_bfloat162*)&ph.x);
            float2 e3 = __bfloat1622float2(*(__nv_bfloat162*)&ph.y);
            s[nt][0] = s[nt][0] * e0.x + e0.y;
            s[nt][1] = s[nt][1] * e1.x + e1.y;
            s[nt][2] = s[nt][2] * e2.x + e2.y;
            s[nt][3] = s[nt][3] * e3.x + e3.y;
        }

        // online softmax
        float mx_lo = -1e30f, mx_hi = -1e30f;
#pragma unroll
        for (int nt = 0; nt < 8; ++nt) {
            mx_lo = fmaxf(mx_lo, fmaxf(s[nt][0], s[nt][1]));
            mx_hi = fmaxf(mx_hi, fmaxf(s[nt][2], s[nt][3]));
        }
        mx_lo = fmaxf(mx_lo, __shfl_xor_sync(0xffffffffu, mx_lo, 1));
        mx_lo = fmaxf(mx_lo, __shfl_xor_sync(0xffffffffu, mx_lo, 2));
        mx_hi = fmaxf(mx_hi, __shfl_xor_sync(0xffffffffu, mx_hi, 1));
        mx_hi = fmaxf(mx_hi, __shfl_xor_sync(0xffffffffu, mx_hi, 2));
        float mn_lo = fmaxf(m_lo, mx_lo), mn_hi = fmaxf(m_hi, mx_hi);
        float sc_lo = __expf(m_lo - mn_lo), sc_hi = __expf(m_hi - mn_hi);
        m_lo = mn_lo; m_hi = mn_hi;
        float rs_lo = 0.f, rs_hi = 0.f;
#pragma unroll
        for (int nt = 0; nt < 8; ++nt) {
            s[nt][0] = __expf(s[nt][0] - mn_lo);
            s[nt][1] = __expf(s[nt][1] - mn_lo);
            s[nt][2] = __expf(s[nt][2] - mn_hi);
            s[nt][3] = __expf(s[nt][3] - mn_hi);
            rs_lo += s[nt][0] + s[nt][1];
            rs_hi += s[nt][2] + s[nt][3];
        }
        rs_lo += __shfl_xor_sync(0xffffffffu, rs_lo, 1);
        rs_lo += __shfl_xor_sync(0xffffffffu, rs_lo, 2);
        rs_hi += __shfl_xor_sync(0xffffffffu, rs_hi, 1);
        rs_hi += __shfl_xor_sync(0xffffffffu, rs_hi, 2);
        l_lo = l_lo * sc_lo + rs_lo;
        l_hi = l_hi * sc_hi + rs_hi;
#pragma unroll
        for (int dt = 0; dt < 8; ++dt) {
            o[dt][0] *= sc_lo; o[dt][1] *= sc_lo;
            o[dt][2] *= sc_hi; o[dt][3] *= sc_hi;
        }

        // O += P @ V   (P packed to bf16 in registers — no smem roundtrip)
#pragma unroll
        for (int ks = 0; ks < 4; ++ks) {
            unsigned pa[4];
            pa[0] = packbf(s[2 * ks][0], s[2 * ks][1]);
            pa[1] = packbf(s[2 * ks][2], s[2 * ks][3]);
            pa[2] = packbf(s[2 * ks + 1][0], s[2 * ks + 1][1]);
            pa[3] = packbf(s[2 * ks + 1][2], s[2 * ks + 1][3]);
#pragma unroll
            for (int dt = 0; dt < 8; ++dt) {
                unsigned bfr[2];
                bfr[0] = Vp[dt * 8 + gid][ks * 8 + tig];
                bfr[1] = Vp[dt * 8 + gid][ks * 8 + 4 + tig];
                mma_bf16(o[dt], pa, bfr);
            }
        }
    }

    // write ctx (tf32 bits, consumed by outln's mma)
    float inv_lo = 1.0f / l_lo, inv_hi = 1.0f / l_hi;
    unsigned* cbase = g_ctx + (size_t)b * Ln * Hn + h * DHn;
#pragma unroll
    for (int dt = 0; dt < 8; ++dt) {
        int dd = dt * 8 + 2 * tig;
        *(uint2*)&cbase[(size_t)rl * Hn + dd] =
            make_uint2(f2tf(o[dt][0] * inv_lo), f2tf(o[dt][1] * inv_lo));
        *(uint2*)&cbase[(size_t)rh * Hn + dd] =
            make_uint2(f2tf(o[dt][2] * inv_hi), f2tf(o[dt][3] * inv_hi));
    }
}

// ---------------- K3: output projection + residual + layernorm ------------
__global__ __launch_bounds__(512) void outln_mma(
    const float* __restrict__ x, const float* __restrict__ bd,
    const float* __restrict__ lng, const float* __restrict__ lnb,
    float* __restrict__ out)
{
    extern __shared__ unsigned dsm[];
    unsigned* As = dsm;             // 2 * 64 * 36  = 4608
    unsigned* Bs = dsm + 4608;      // 2 * 256 * 36 = 18432
    __shared__ float redS[64][4];
    __shared__ float redQ[64][4];

    const int t = threadIdx.x;
    const int lane = t & 31, warp = t >> 5;
    const int gid = lane >> 2, tig = lane & 3;
    const int m0 = blockIdx.x * 64;
    const int mg = warp >> 2;
    const int nq = warp & 3;
    const int wm = mg * 16;
    const int wn = nq * 64;
    const unsigned* Wd = g_wtf + 4 * (Hn * Hn);

    float c[8][4] = {};

    {
        int row = t >> 3, kq = (t & 7) * 4;
        cpa16(&As[row * 36 + kq], &g_ctx[(size_t)(m0 + row) * Hn + kq]);
#pragma unroll
        for (int u = 0; u < 4; ++u) {
            int f = t + 512 * u;
            int r2 = f >> 3, k2 = (f & 7) * 4;
            cpa16(&Bs[r2 * 36 + k2], &Wd[(size_t)r2 * Hn + k2]);
        }
        CP_COMMIT();
    }

    for (int i = 0; i < 8; ++i) {
        const int buf = i & 1;
        if (i < 7) {
            const int k1 = (i + 1) * 32;
            const int nb = buf ^ 1;
            int row = t >> 3, kq = (t & 7) * 4;
            cpa16(&As[nb * 2304 + row * 36 + kq], &g_ctx[(size_t)(m0 + row) * Hn + k1 + kq]);
#pragma unroll
            for (int u = 0; u < 4; ++u) {
                int f = t + 512 * u;
                int r2 = f >> 3, k2 = (f & 7) * 4;
                cpa16(&Bs[nb * 9216 + r2 * 36 + k2], &Wd[(size_t)r2 * Hn + k1 + k2]);
            }
            CP_COMMIT();
            CP_WAIT1();
        } else {
            CP_WAIT0();
        }
        __syncthreads();
#pragma unroll
        for (int ks = 0; ks < 32; ks += 8) {
            unsigned a[4];
            a[0] = As[buf * 2304 + (wm + gid) * 36 + ks + tig];
            a[1] = As[buf * 2304 + (wm + gid + 8) * 36 + ks + tig];
            a[2] = As[buf * 2304 + (wm + gid) * 36 + ks + tig + 4];
            a[3] = As[buf * 2304 + (wm + gid + 8) * 36 + ks + tig + 4];
#pragma unroll
            for (int nt = 0; nt < 8; ++nt) {
                unsigned bfr[2];
                bfr[0] = Bs[buf * 9216 + (wn + nt * 8 + gid) * 36 + ks + tig];
                bfr[1] = Bs[buf * 9216 + (wn + nt * 8 + gid) * 36 + ks + tig + 4];
                mma_tf32(c[nt], a, bfr);
            }
        }
        __syncthreads();
    }

    const int lrl = wm + gid, lrh = lrl + 8;
    const size_t rl = m0 + lrl, rh = m0 + lrh;
    float s_lo = 0.f, s_hi = 0.f, q_lo = 0.f, q_hi = 0.f;
#pragma unroll
    for (int nt = 0; nt < 8; ++nt) {
        int cc = wn + nt * 8 + 2 * tig;
        float2 bb = *(const float2*)&bd[cc];
        float2 xl = *(const float2*)&x[rl * Hn + cc];
        float2 xh = *(const float2*)&x[rh * Hn + cc];
        c[nt][0] += bb.x + xl.x; c[nt][1] += bb.y + xl.y;
        c[nt][2] += bb.x + xh.x; c[nt][3] += bb.y + xh.y;
        s_lo += c[nt][0] + c[nt][1];
        s_hi += c[nt][2] + c[nt][3];
        q_lo += c[nt][0] * c[nt][0] + c[nt][1] * c[nt][1];
        q_hi += c[nt][2] * c[nt][2] + c[nt][3] * c[nt][3];
    }
    s_lo += __shfl_xor_sync(0xffffffffu, s_lo, 1);
    s_lo += __shfl_xor_sync(0xffffffffu, s_lo, 2);
    s_hi += __shfl_xor_sync(0xffffffffu, s_hi, 1);
    s_hi += __shfl_xor_sync(0xffffffffu, s_hi, 2);
    q_lo += __shfl_xor_sync(0xffffffffu, q_lo, 1);
    q_lo += __shfl_xor_sync(0xffffffffu, q_lo, 2);
    q_hi += __shfl_xor_sync(0xffffffffu, q_hi, 1);
    q_hi += __shfl_xor_sync(0xffffffffu, q_hi, 2);
    __syncthreads();
    if (tig == 0) {
        redS[lrl][nq] = s_lo; redQ[lrl][nq] = q_lo;
        redS[lrh][nq] = s_hi; redQ[lrh][nq] = q_hi;
    }
    __syncthreads();
    float mu_lo = (redS[lrl][0] + redS[lrl][1] + redS[lrl][2] + redS[lrl][3]) * (1.0f / Hn);
    float mu_hi = (redS[lrh][0] + redS[lrh][1] + redS[lrh][2] + redS[lrh][3]) * (1.0f / Hn);
    float ex_lo = (redQ[lrl][0] + redQ[lrl][1] + redQ[lrl][2] + redQ[lrl][3]) * (1.0f / Hn);
    float ex_hi = (redQ[lrh][0] + redQ[lrh][1] + redQ[lrh][2] + redQ[lrh][3]) * (1.0f / Hn);
    float iv_lo = rsqrtf(ex_lo - mu_lo * mu_lo + 1e-12f);
    float iv_hi = rsqrtf(ex_hi - mu_hi * mu_hi + 1e-12f);

#pragma unroll
    for (int nt = 0; nt < 8; ++nt) {
        int cc = wn + nt * 8 + 2 * tig;
        float2 g = *(const float2*)&lng[cc];
        float2 be = *(const float2*)&lnb[cc];
        *(float2*)&out[rl * Hn + cc] = make_float2(
            (c[nt][0] - mu_lo) * iv_lo * g.x + be.x,
            (c[nt][1] - mu_lo) * iv_lo * g.y + be.y);
        *(float2*)&out[rh * Hn + cc] = make_float2(
            (c[nt][2] - mu_hi) * iv_hi * g.x + be.x,
            (c[nt][3] - mu_hi) * iv_hi * g.y + be.y);
    }
}

// ---------------- K4: interval prediction head ---------------------------
__global__ __launch_bounds__(256) void pred_kernel(
    const float* __restrict__ hs, const int* __restrict__ slen,
    const float* __restrict__ Wt, const float* __restrict__ bt,
    float* __restrict__ out)
{
    __shared__ float red[256];
    const int b = blockIdx.x;
    const int t = threadIdx.x;
    const int len = slen[b];
    const float* e1 = hs + ((size_t)b * Ln + (len - 1)) * Hn;
    const float* e2 = hs + ((size_t)b * Ln + (len - 2)) * Hn;
    red[t] = Wt[t] * e1[t] + Wt[Hn + t] * e2[t];
    __syncthreads();
    for (int s = 128; s > 0; s >>= 1) {
        if (t < s) red[t] += red[t + s];
        __syncthreads();
    }
    if (t == 0) out[(size_t)Bn * Ln * Hn + b] = red[0] + bt[0];
}

// ---------------- launch --------------------------------------------------
extern "C" void kernel_launch(void* const* d_in, const int* in_sizes, int n_in,
                              void* d_out, int out_size)
{
    const float* x    = (const float*)d_in[0];
    const float* tseq = (const float*)d_in[1];
    const float* mask = (const float*)d_in[2];
    const int*   slen = (const int*)d_in[3];
    const float* Wq   = (const float*)d_in[4];
    const float* bq   = (const float*)d_in[5];
    const float* Wk   = (const float*)d_in[6];
    const float* bk   = (const float*)d_in[7];
    const float* Wv   = (const float*)d_in[8];
    const float* bv   = (const float*)d_in[9];
    const float* Wd   = (const float*)d_in[10];
    const float* bd   = (const float*)d_in[11];
    const float* lng  = (const float*)d_in[12];
    const float* lnb  = (const float*)d_in[13];
    const float* Wtq  = (const float*)d_in[14];
    const float* btq  = (const float*)d_in[15];
    const float* tw1  = (const float*)d_in[16];
    const float* tb1  = (const float*)d_in[17];
    const float* tow1 = (const float*)d_in[18];
    const float* tow2 = (const float*)d_in[19];
    const float* tob  = (const float*)d_in[20];
    const float* Wt   = (const float*)d_in[21];
    const float* bt   = (const float*)d_in[22];
    float* out = (float*)d_out;

    static const int OUTLN_SMEM = (4608 + 18432) * 4;  // 92160 B dynamic
    cudaFuncSetAttribute(outln_mma, cudaFuncAttributeMaxDynamicSharedMemorySize, OUTLN_SMEM);

    cvt_all<<<(XN4 + WN4 + 255) / 256, 256>>>(
        (const float4*)x, (const float4*)Wq, (const float4*)Wk,
        (const float4*)Wv, (const float4*)Wtq, (const float4*)Wd);
    proj_tq<<<dim3(Bn * Ln / 64, 4), 128>>>(btq);
    fused_gate_qkv<<<GATE_BLKS + 3072, 128>>>(
        tseq, tw1, tb1, tow1, tow2, tob, mask, bq, bk, bv);
    attn_mma<<<dim3(Ln / 64, NHn, Bn), 128>>>();
    outln_mma<<<dim3(Bn * Ln / 64), 512, OUTLN_SMEM>>>(x, bd, lng, lnb, out);
    pred_kernel<<<dim3(Bn), 256>>>(out, slen, Wt, bt, out);
}

// round 11
// speedup vs baseline: 3.4895x; 1.1852x over previous
#include <cuda_runtime.h>
#include <cuda_bf16.h>

#define Bn 32
#define Ln 512
#define Hn 256
#define NHn 4
#define DHn 64

// ---------------- scratch (device globals; no allocation) ----------------
__device__ __align__(16) unsigned g_xtf[Bn * Ln * Hn];          // x in tf32 bits
__device__ __align__(16) unsigned g_wtf[5 * Hn * Hn];           // Wq,Wk,Wv,Wtq,Wd tf32
__device__ __align__(16) unsigned g_q16[Bn * Ln * (Hn / 2)];    // q bf16 pairs [token][128]
__device__ __align__(16) unsigned g_k16[Bn * Ln * (Hn / 2)];    // k bf16 pairs
__device__ __align__(16) __nv_bfloat16 g_vt16[Bn * NHn * DHn * Ln]; // V^T [b,h][d][token]
__device__ __align__(16) unsigned g_tq[Bn * Ln * Hn];           // tf32
__device__ __align__(16) unsigned g_gm[Bn * Ln * Ln];           // bf16x2 {gate/8, mask}
__device__ __align__(16) unsigned g_ctx[Bn * Ln * Hn];          // tf32

// ---------------- helpers --------------------------------------------
__device__ __forceinline__ unsigned f2tf(float f) {
    unsigned u;
    asm("cvt.rna.tf32.f32 %0, %1;" : "=r"(u) : "f"(f));
    return u;
}
__device__ __forceinline__ float tanh_ap(float x) {
    float y;
    asm("tanh.approx.f32 %0, %1;" : "=f"(y) : "f"(x));
    return y;
}
__device__ __forceinline__ uint4 cvt4(float4 v) {
    return make_uint4(f2tf(v.x), f2tf(v.y), f2tf(v.z), f2tf(v.w));
}
__device__ __forceinline__ unsigned packbf(float lo, float hi) {
    __nv_bfloat162 p = __floats2bfloat162_rn(lo, hi);
    return *(unsigned*)&p;
}
__device__ __forceinline__ void cpa16(void* s, const void* g) {
    unsigned sa = (unsigned)__cvta_generic_to_shared(s);
    asm volatile("cp.async.cg.shared.global [%0], [%1], 16;" :: "r"(sa), "l"(g));
}
#define CP_COMMIT()  asm volatile("cp.async.commit_group;")
#define CP_WAIT1()   asm volatile("cp.async.wait_group 1;")
#define CP_WAIT0()   asm volatile("cp.async.wait_group 0;")

__device__ __forceinline__ void mma_tf32(float* c, const unsigned* a, const unsigned* b) {
    asm volatile(
        "mma.sync.aligned.m16n8k8.row.col.f32.tf32.tf32.f32 "
        "{%0,%1,%2,%3}, {%4,%5,%6,%7}, {%8,%9}, {%0,%1,%2,%3};\n"
        : "+f"(c[0]), "+f"(c[1]), "+f"(c[2]), "+f"(c[3])
        : "r"(a[0]), "r"(a[1]), "r"(a[2]), "r"(a[3]), "r"(b[0]), "r"(b[1]));
}
__device__ __forceinline__ void mma_bf16(float* c, const unsigned* a, const unsigned* b) {
    asm volatile(
        "mma.sync.aligned.m16n8k16.row.col.f32.bf16.bf16.f32 "
        "{%0,%1,%2,%3}, {%4,%5,%6,%7}, {%8,%9}, {%0,%1,%2,%3};\n"
        : "+f"(c[0]), "+f"(c[1]), "+f"(c[2]), "+f"(c[3])
        : "r"(a[0]), "r"(a[1]), "r"(a[2]), "r"(a[3]), "r"(b[0]), "r"(b[1]));
}

// shared 64x64x256 tf32 GEMM mainloop with cp.async double buffer
__device__ __forceinline__ void gemm_mainloop(
    const unsigned* __restrict__ Ag, const unsigned* __restrict__ Bg,
    int m0, int n0, int t, int wm, int gid, int tig,
    unsigned (*As)[64][36], unsigned (*Bs)[64][36], float c[8][4])
{
#pragma unroll
    for (int u = 0; u < 4; ++u) {
        int f = t + 128 * u;
        int row = f >> 3;
        int kq = (f & 7) * 4;
        cpa16(&As[0][row][kq], &Ag[(size_t)(m0 + row) * Hn + kq]);
        cpa16(&Bs[0][row][kq], &Bg[(size_t)(n0 + row) * Hn + kq]);
    }
    CP_COMMIT();

    for (int i = 0; i < 8; ++i) {
        const int buf = i & 1;
        if (i < 7) {
            const int k1 = (i + 1) * 32;
            const int nb = buf ^ 1;
#pragma unroll
            for (int u = 0; u < 4; ++u) {
                int f = t + 128 * u;
                int row = f >> 3;
                int kq = (f & 7) * 4;
                cpa16(&As[nb][row][kq], &Ag[(size_t)(m0 + row) * Hn + k1 + kq]);
                cpa16(&Bs[nb][row][kq], &Bg[(size_t)(n0 + row) * Hn + k1 + kq]);
            }
            CP_COMMIT();
            CP_WAIT1();
        } else {
            CP_WAIT0();
        }
        __syncthreads();
#pragma unroll
        for (int ks = 0; ks < 32; ks += 8) {
            unsigned a[4];
            a[0] = As[buf][wm + gid][ks + tig];
            a[1] = As[buf][wm + gid + 8][ks + tig];
            a[2] = As[buf][wm + gid][ks + tig + 4];
            a[3] = As[buf][wm + gid + 8][ks + tig + 4];
#pragma unroll
            for (int nt = 0; nt < 8; ++nt) {
                unsigned b[2];
                b[0] = Bs[buf][nt * 8 + gid][ks + tig];
                b[1] = Bs[buf][nt * 8 + gid][ks + tig + 4];
                mma_tf32(c[nt], a, b);
            }
        }
        __syncthreads();
    }
}

// ---------------- K-1: fused pre-convert fp32 -> tf32 bits ----------------
#define XN4 (Bn * Ln * Hn / 4)     // 1048576
#define WN4 (5 * Hn * Hn / 4)      // 81920
__global__ __launch_bounds__(256) void cvt_all(
    const float4* __restrict__ x,
    const float4* __restrict__ Wq, const float4* __restrict__ Wk,
    const float4* __restrict__ Wv, const float4* __restrict__ Wtq,
    const float4* __restrict__ Wd)
{
    int i = blockIdx.x * 256 + threadIdx.x;
    if (i < XN4) {
        ((uint4*)g_xtf)[i] = cvt4(x[i]);
    } else {
        int j = i - XN4;
        if (j < WN4) {
            int m = j >> 14, r = j & 16383;
            const float4* src = m == 0 ? Wq : m == 1 ? Wk : m == 2 ? Wv : m == 3 ? Wtq : Wd;
            ((uint4*)g_wtf)[j] = cvt4(src[r]);
        }
    }
}

// ---------------- K0a: TQ projection only (critical path for gate) --------
__global__ __launch_bounds__(128) void proj_tq(const float* __restrict__ btq)
{
    __shared__ unsigned As[2][64][36];
    __shared__ unsigned Bs[2][64][36];
    const int t = threadIdx.x;
    const int lane = t & 31, warp = t >> 5;
    const int gid = lane >> 2, tig = lane & 3;
    const int m0 = blockIdx.x * 64;
    const int n0 = blockIdx.y * 64;
    const int wm = warp * 16;

    float c[8][4] = {};
    gemm_mainloop(g_xtf, g_wtf + 3 * Hn * Hn, m0, n0, t, wm, gid, tig, As, Bs, c);

#pragma unroll
    for (int nt = 0; nt < 8; ++nt) {
        int cc = n0 + nt * 8 + 2 * tig;
        float2 bb = *(const float2*)&btq[cc];
        size_t r0 = (size_t)(m0 + wm + gid) * Hn;
        size_t r1 = (size_t)(m0 + wm + gid + 8) * Hn;
        *(uint2*)&g_tq[r0 + cc] = make_uint2(f2tf(c[nt][0] + bb.x), f2tf(c[nt][1] + bb.y));
        *(uint2*)&g_tq[r1 + cc] = make_uint2(f2tf(c[nt][2] + bb.x), f2tf(c[nt][3] + bb.y));
    }
}

// ---------------- K0b: fused gate + Q/K/V projection ----------------------
#define GATE_BLKS 2048
__global__ __launch_bounds__(128) void fused_gate_qkv(
    const float* __restrict__ tseq,
    const float* __restrict__ tw1, const float* __restrict__ tb1,
    const float* __restrict__ tow1, const float* __restrict__ tow2,
    const float* __restrict__ tob, const float* __restrict__ mask,
    const float* __restrict__ bq, const float* __restrict__ bk,
    const float* __restrict__ bv)
{
    __shared__ unsigned As[2][64][36];
    __shared__ unsigned Bs[2][64][36];
    const int t = threadIdx.x;
    const int lane = t & 31, warp = t >> 5;
    const int gid = lane >> 2, tig = lane & 3;
    const int wm = warp * 16;
    const int bid = blockIdx.x;

    float c[8][4] = {};

    if (bid < GATE_BLKS) {
        // ---------------- gate path ----------------
        const int b = bid >> 6;
        const int rem = bid & 63;
        const int m0 = (rem >> 3) * 64;
        const int n0 = (rem & 7) * 64;
        gemm_mainloop(g_tq + (size_t)b * Ln * Hn, g_xtf + (size_t)b * Ln * Hn,
                      m0, n0, t, wm, gid, tig, As, Bs, c);

        const int rl = m0 + wm + gid, rh = rl + 8;
        const float t_lo = tseq[b * Ln + rl];
        const float t_hi = tseq[b * Ln + rh];
        const float* mptr = mask + (size_t)b * Ln * Ln;
        unsigned* gout = g_gm + (size_t)b * Ln * Ln;

#pragma unroll
        for (int nt = 0; nt < 8; ++nt) {
            int cc = n0 + nt * 8 + 2 * tig;
            float2 tc = *(const float2*)&tseq[b * Ln + cc];
#pragma unroll
            for (int half = 0; half < 2; ++half) {
                int r = half ? rh : rl;
                float tr = half ? t_hi : t_lo;
                size_t idx = (size_t)r * Ln + cc;
                float2 w1 = *(const float2*)&tw1[idx];
                float2 b1 = *(const float2*)&tb1[idx];
                float2 o1 = *(const float2*)&tow1[idx];
                float2 o2 = *(const float2*)&tow2[idx];
                float2 ob = *(const float2*)&tob[idx];
                float2 mm = *(const float2*)&mptr[idx];
                float s0 = c[nt][half * 2 + 0], s1 = c[nt][half * 2 + 1];
                float tqk0 = tanh_ap(s0), tqk1 = tanh_ap(s1);
                float d0 = tanh_ap(__logf(1.0f + fabsf(tr - tc.x)) * w1.x + b1.x);
                float d1 = tanh_ap(__logf(1.0f + fabsf(tr - tc.y)) * w1.y + b1.y);
                float g0 = o1.x * d0 + o2.x * tqk0 + ob.x;
                float g1 = o1.y * d1 + o2.y * tqk1 + ob.y;
                g0 = 0.125f / (1.0f + __expf(-g0));
                g1 = 0.125f / (1.0f + __expf(-g1));
                __nv_bfloat162 p0 = __floats2bfloat162_rn(g0, mm.x);
                __nv_bfloat162 p1 = __floats2bfloat162_rn(g1, mm.y);
                *(uint2*)&gout[idx] = make_uint2(*(unsigned*)&p0, *(unsigned*)&p1);
            }
        }
    } else {
        // ---------------- Q/K/V projection path ----------------
        const int pid = bid - GATE_BLKS;
        const int mt = pid / 12, combo = pid % 12;
        const int wsel = combo >> 2;
        const int m0 = mt * 64;
        const int n0 = (combo & 3) * 64;
        const float* bias = wsel == 0 ? bq : wsel == 1 ? bk : bv;

        gemm_mainloop(g_xtf, g_wtf + (size_t)wsel * Hn * Hn,
                      m0, n0, t, wm, gid, tig, As, Bs, c);

        const int r0 = m0 + wm + gid, r1 = r0 + 8;
        if (wsel < 2) {
            unsigned* out16 = wsel == 0 ? g_q16 : g_k16;
#pragma unroll
            for (int nt = 0; nt < 8; ++nt) {
                int cc = n0 + nt * 8 + 2 * tig;
                float2 bb = *(const float2*)&bias[cc];
                out16[(size_t)r0 * 128 + (cc >> 1)] = packbf(c[nt][0] + bb.x, c[nt][1] + bb.y);
                out16[(size_t)r1 * 128 + (cc >> 1)] = packbf(c[nt][2] + bb.x, c[nt][3] + bb.y);
            }
        } else {
            // V: write transposed bf16 [b,h][d][token]
            const int bb0 = r0 >> 9;              // batch
            const int tk0 = r0 & 511;             // token within batch
#pragma unroll
            for (int nt = 0; nt < 8; ++nt) {
                int cc = n0 + nt * 8 + 2 * tig;
                float2 bbv = *(const float2*)&bias[cc];
                int hh = cc >> 6, dl = cc & 63;
                size_t base = ((size_t)(bb0 * NHn + hh) * DHn + dl) * Ln + tk0;
                g_vt16[base]           = __float2bfloat16(c[nt][0] + bbv.x);
                g_vt16[base + Ln]      = __float2bfloat16(c[nt][1] + bbv.y);
                g_vt16[base + 8]       = __float2bfloat16(c[nt][2] + bbv.x);
                g_vt16[base + Ln + 8]  = __float2bfloat16(c[nt][3] + bbv.y);
            }
        }
    }
}

// ---------------- K2: fused attention (bf16 tensor, cp.async pipelined) ---
__global__ __launch_bounds__(128) void attn_mma()
{
    __shared__ unsigned Qs[64][36];      // Q bf16 pairs [q][dpair]
    __shared__ unsigned Ks[2][64][36];   // K bf16 pairs [key][dpair], double buffered
    __shared__ unsigned Vp[2][64][36];   // V^T bf16 pairs [d][keypair], double buffered
    __shared__ unsigned Gm[64][68];      // gate/mask tile [qrow][keycol], single buffer

    const int t = threadIdx.x;
    const int lane = t & 31, warp = t >> 5;
    const int gid = lane >> 2, tig = lane & 3;
    const int qt = blockIdx.x, h = blockIdx.y, b = blockIdx.z;
    const int q0 = qt * 64;
    const int wm = warp * 16;

    const unsigned* qptr = g_q16 + (size_t)b * Ln * 128 + h * 32;
    const unsigned* kptr = g_k16 + (size_t)b * Ln * 128 + h * 32;
    const unsigned* vtp = (const unsigned*)(g_vt16 + ((size_t)(b * NHn + h)) * DHn * Ln);
    const unsigned* gptr = g_gm + (size_t)b * Ln * Ln;

    // load Q tile: 64 rows x 32 pairs
#pragma unroll
    for (int u = 0; u < 4; ++u) {
        int f = t + 128 * u;
        int row = f >> 3;
        int ch = (f & 7) * 4;
        *(uint4*)&Qs[row][ch] = *(const uint4*)&qptr[(size_t)(q0 + row) * 128 + ch];
    }

    // prologue: KV tile 0 via cp.async  (group "KV(-1 -> 0)")
#pragma unroll
    for (int u = 0; u < 4; ++u) {
        int f = t + 128 * u;
        int row = f >> 3;
        int ch = (f & 7) * 4;
        cpa16(&Ks[0][row][ch], &kptr[(size_t)row * 128 + ch]);
        cpa16(&Vp[0][row][ch], &vtp[(size_t)row * 256 + ch]);
    }
    CP_COMMIT();
    __syncthreads();   // Q tile visible

    // Q A-fragments (held in regs): 4 k-steps x 4 regs
    unsigned qf[4][4];
#pragma unroll
    for (int ks = 0; ks < 4; ++ks) {
        qf[ks][0] = Qs[wm + gid][ks * 8 + tig];
        qf[ks][1] = Qs[wm + gid + 8][ks * 8 + tig];
        qf[ks][2] = Qs[wm + gid][ks * 8 + 4 + tig];
        qf[ks][3] = Qs[wm + gid + 8][ks * 8 + 4 + tig];
    }

    float o[8][4] = {};
    float m_lo = -1e30f, m_hi = -1e30f, l_lo = 0.f, l_hi = 0.f;
    const int rl = q0 + wm + gid, rh = rl + 8;
    const int lrl = wm + gid, lrh = lrl + 8;

    for (int kb = 0; kb < 8; ++kb) {
        const int c0 = kb * 64;
        const int buf = kb & 1;

        // issue gate/mask tile for THIS kb (own group)
#pragma unroll
        for (int u = 0; u < 8; ++u) {
            int f = t + 128 * u;
            int row = f >> 4;
            int seg = (f & 15) * 4;
            cpa16(&Gm[row][seg], &gptr[(size_t)(q0 + row) * Ln + c0 + seg]);
        }
        CP_COMMIT();

        // issue KV tile kb+1 (own group)
        if (kb < 7) {
            const int c1 = c0 + 64;
            const int nb = buf ^ 1;
#pragma unroll
            for (int u = 0; u < 4; ++u) {
                int f = t + 128 * u;
                int row = f >> 3;
                int ch = (f & 7) * 4;
                cpa16(&Ks[nb][row][ch], &kptr[(size_t)(c1 + row) * 128 + ch]);
                cpa16(&Vp[nb][row][ch], &vtp[(size_t)row * 256 + (c1 >> 1) + ch]);
            }
            CP_COMMIT();
            CP_WAIT1();   // KV(kb) + G(kb) done; KV(kb+1) in flight
        } else {
            CP_WAIT0();
        }
        __syncthreads();

        // S = Q @ K^T  (bf16, 4 k-steps)
        float s[8][4] = {};
#pragma unroll
        for (int ks = 0; ks < 4; ++ks) {
#pragma unroll
            for (int nt = 0; nt < 8; ++nt) {
                unsigned bfr[2];
                bfr[0] = Ks[buf][nt * 8 + gid][ks * 8 + tig];
                bfr[1] = Ks[buf][nt * 8 + gid][ks * 8 + 4 + tig];
                mma_bf16(s[nt], qf[ks], bfr);
            }
        }

        // epilogue: s*gate + mask  (from smem, bf16x2 packed)
#pragma unroll
        for (int nt = 0; nt < 8; ++nt) {
            int cl = nt * 8 + 2 * tig;
            uint2 pl = *(const uint2*)&Gm[lrl][cl];
            uint2 ph = *(const uint2*)&Gm[lrh][cl];
            float2 e0 = __bfloat1622float2(*(__nv_bfloat162*)&pl.x);
            float2 e1 = __bfloat1622float2(*(__nv_bfloat162*)&pl.y);
            float2 e2 = __bfloat1622float2(*(__nv_bfloat162*)&ph.x);
            float2 e3 = __bfloat1622float2(*(__nv_bfloat162*)&ph.y);
            s[nt][0] = s[nt][0] * e0.x + e0.y;
            s[nt][1] = s[nt][1] * e1.x + e1.y;
            s[nt][2] = s[nt][2] * e2.x + e2.y;
            s[nt][3] = s[nt][3] * e3.x + e3.y;
        }

        // online softmax
        float mx_lo = -1e30f, mx_hi = -1e30f;
#pragma unroll
        for (int nt = 0; nt < 8; ++nt) {
            mx_lo = fmaxf(mx_lo, fmaxf(s[nt][0], s[nt][1]));
            mx_hi = fmaxf(mx_hi, fmaxf(s[nt][2], s[nt][3]));
        }
        mx_lo = fmaxf(mx_lo, __shfl_xor_sync(0xffffffffu, mx_lo, 1));
        mx_lo = fmaxf(mx_lo, __shfl_xor_sync(0xffffffffu, mx_lo, 2));
        mx_hi = fmaxf(mx_hi, __shfl_xor_sync(0xffffffffu, mx_hi, 1));
        mx_hi = fmaxf(mx_hi, __shfl_xor_sync(0xffffffffu, mx_hi, 2));
        float mn_lo = fmaxf(m_lo, mx_lo), mn_hi = fmaxf(m_hi, mx_hi);
        float sc_lo = __expf(m_lo - mn_lo), sc_hi = __expf(m_hi - mn_hi);
        m_lo = mn_lo; m_hi = mn_hi;
        float rs_lo = 0.f, rs_hi = 0.f;
#pragma unroll
        for (int nt = 0; nt < 8; ++nt) {
            s[nt][0] = __expf(s[nt][0] - mn_lo);
            s[nt][1] = __expf(s[nt][1] - mn_lo);
            s[nt][2] = __expf(s[nt][2] - mn_hi);
            s[nt][3] = __expf(s[nt][3] - mn_hi);
            rs_lo += s[nt][0] + s[nt][1];
            rs_hi += s[nt][2] + s[nt][3];
        }
        rs_lo += __shfl_xor_sync(0xffffffffu, rs_lo, 1);
        rs_lo += __shfl_xor_sync(0xffffffffu, rs_lo, 2);
        rs_hi += __shfl_xor_sync(0xffffffffu, rs_hi, 1);
        rs_hi += __shfl_xor_sync(0xffffffffu, rs_hi, 2);
        l_lo = l_lo * sc_lo + rs_lo;
        l_hi = l_hi * sc_hi + rs_hi;
#pragma unroll
        for (int dt = 0; dt < 8; ++dt) {
            o[dt][0] *= sc_lo; o[dt][1] *= sc_lo;
            o[dt][2] *= sc_hi; o[dt][3] *= sc_hi;
        }

        // O += P @ V   (P packed to bf16 in registers)
#pragma unroll
        for (int ks = 0; ks < 4; ++ks) {
            unsigned pa[4];
            pa[0] = packbf(s[2 * ks][0], s[2 * ks][1]);
            pa[1] = packbf(s[2 * ks][2], s[2 * ks][3]);
            pa[2] = packbf(s[2 * ks + 1][0], s[2 * ks + 1][1]);
            pa[3] = packbf(s[2 * ks + 1][2], s[2 * ks + 1][3]);
#pragma unroll
            for (int dt = 0; dt < 8; ++dt) {
                unsigned bfr[2];
                bfr[0] = Vp[buf][dt * 8 + gid][ks * 8 + tig];
                bfr[1] = Vp[buf][dt * 8 + gid][ks * 8 + 4 + tig];
                mma_bf16(o[dt], pa, bfr);
            }
        }
        __syncthreads();   // Gm + KV[buf] fully consumed before next-iter writes
    }

    // write ctx (tf32 bits, consumed by outln's mma)
    float inv_lo = 1.0f / l_lo, inv_hi = 1.0f / l_hi;
    unsigned* cbase = g_ctx + (size_t)b * Ln * Hn + h * DHn;
#pragma unroll
    for (int dt = 0; dt < 8; ++dt) {
        int dd = dt * 8 + 2 * tig;
        *(uint2*)&cbase[(size_t)rl * Hn + dd] =
            make_uint2(f2tf(o[dt][0] * inv_lo), f2tf(o[dt][1] * inv_lo));
        *(uint2*)&cbase[(size_t)rh * Hn + dd] =
            make_uint2(f2tf(o[dt][2] * inv_hi), f2tf(o[dt][3] * inv_hi));
    }
}

// ---------------- K3: output projection + residual + layernorm ------------
__global__ __launch_bounds__(512) void outln_mma(
    const float* __restrict__ x, const float* __restrict__ bd,
    const float* __restrict__ lng, const float* __restrict__ lnb,
    float* __restrict__ out)
{
    extern __shared__ unsigned dsm[];
    unsigned* As = dsm;             // 2 * 64 * 36  = 4608
    unsigned* Bs = dsm + 4608;      // 2 * 256 * 36 = 18432
    __shared__ float redS[64][4];
    __shared__ float redQ[64][4];

    const int t = threadIdx.x;
    const int lane = t & 31, warp = t >> 5;
    const int gid = lane >> 2, tig = lane & 3;
    const int m0 = blockIdx.x * 64;
    const int mg = warp >> 2;
    const int nq = warp & 3;
    const int wm = mg * 16;
    const int wn = nq * 64;
    const unsigned* Wd = g_wtf + 4 * (Hn * Hn);

    float c[8][4] = {};

    {
        int row = t >> 3, kq = (t & 7) * 4;
        cpa16(&As[row * 36 + kq], &g_ctx[(size_t)(m0 + row) * Hn + kq]);
#pragma unroll
        for (int u = 0; u < 4; ++u) {
            int f = t + 512 * u;
            int r2 = f >> 3, k2 = (f & 7) * 4;
            cpa16(&Bs[r2 * 36 + k2], &Wd[(size_t)r2 * Hn + k2]);
        }
        CP_COMMIT();
    }

    for (int i = 0; i < 8; ++i) {
        const int buf = i & 1;
        if (i < 7) {
            const int k1 = (i + 1) * 32;
            const int nb = buf ^ 1;
            int row = t >> 3, kq = (t & 7) * 4;
            cpa16(&As[nb * 2304 + row * 36 + kq], &g_ctx[(size_t)(m0 + row) * Hn + k1 + kq]);
#pragma unroll
            for (int u = 0; u < 4; ++u) {
                int f = t + 512 * u;
                int r2 = f >> 3, k2 = (f & 7) * 4;
                cpa16(&Bs[nb * 9216 + r2 * 36 + k2], &Wd[(size_t)r2 * Hn + k1 + k2]);
            }
            CP_COMMIT();
            CP_WAIT1();
        } else {
            CP_WAIT0();
        }
        __syncthreads();
#pragma unroll
        for (int ks = 0; ks < 32; ks += 8) {
            unsigned a[4];
            a[0] = As[buf * 2304 + (wm + gid) * 36 + ks + tig];
            a[1] = As[buf * 2304 + (wm + gid + 8) * 36 + ks + tig];
            a[2] = As[buf * 2304 + (wm + gid) * 36 + ks + tig + 4];
            a[3] = As[buf * 2304 + (wm + gid + 8) * 36 + ks + tig + 4];
#pragma unroll
            for (int nt = 0; nt < 8; ++nt) {
                unsigned bfr[2];
                bfr[0] = Bs[buf * 9216 + (wn + nt * 8 + gid) * 36 + ks + tig];
                bfr[1] = Bs[buf * 9216 + (wn + nt * 8 + gid) * 36 + ks + tig + 4];
                mma_tf32(c[nt], a, bfr);
            }
        }
        __syncthreads();
    }

    const int lrl = wm + gid, lrh = lrl + 8;
    const size_t rl = m0 + lrl, rh = m0 + lrh;
    float s_lo = 0.f, s_hi = 0.f, q_lo = 0.f, q_hi = 0.f;
#pragma unroll
    for (int nt = 0; nt < 8; ++nt) {
        int cc = wn + nt * 8 + 2 * tig;
        float2 bb = *(const float2*)&bd[cc];
        float2 xl = *(const float2*)&x[rl * Hn + cc];
        float2 xh = *(const float2*)&x[rh * Hn + cc];
        c[nt][0] += bb.x + xl.x; c[nt][1] += bb.y + xl.y;
        c[nt][2] += bb.x + xh.x; c[nt][3] += bb.y + xh.y;
        s_lo += c[nt][0] + c[nt][1];
        s_hi += c[nt][2] + c[nt][3];
        q_lo += c[nt][0] * c[nt][0] + c[nt][1] * c[nt][1];
        q_hi += c[nt][2] * c[nt][2] + c[nt][3] * c[nt][3];
    }
    s_lo += __shfl_xor_sync(0xffffffffu, s_lo, 1);
    s_lo += __shfl_xor_sync(0xffffffffu, s_lo, 2);
    s_hi += __shfl_xor_sync(0xffffffffu, s_hi, 1);
    s_hi += __shfl_xor_sync(0xffffffffu, s_hi, 2);
    q_lo += __shfl_xor_sync(0xffffffffu, q_lo, 1);
    q_lo += __shfl_xor_sync(0xffffffffu, q_lo, 2);
    q_hi += __shfl_xor_sync(0xffffffffu, q_hi, 1);
    q_hi += __shfl_xor_sync(0xffffffffu, q_hi, 2);
    __syncthreads();
    if (tig == 0) {
        redS[lrl][nq] = s_lo; redQ[lrl][nq] = q_lo;
        redS[lrh][nq] = s_hi; redQ[lrh][nq] = q_hi;
    }
    __syncthreads();
    float mu_lo = (redS[lrl][0] + redS[lrl][1] + redS[lrl][2] + redS[lrl][3]) * (1.0f / Hn);
    float mu_hi = (redS[lrh][0] + redS[lrh][1] + redS[lrh][2] + redS[lrh][3]) * (1.0f / Hn);
    float ex_lo = (redQ[lrl][0] + redQ[lrl][1] + redQ[lrl][2] + redQ[lrl][3]) * (1.0f / Hn);
    float ex_hi = (redQ[lrh][0] + redQ[lrh][1] + redQ[lrh][2] + redQ[lrh][3]) * (1.0f / Hn);
    float iv_lo = rsqrtf(ex_lo - mu_lo * mu_lo + 1e-12f);
    float iv_hi = rsqrtf(ex_hi - mu_hi * mu_hi + 1e-12f);

#pragma unroll
    for (int nt = 0; nt < 8; ++nt) {
        int cc = wn + nt * 8 + 2 * tig;
        float2 g = *(const float2*)&lng[cc];
        float2 be = *(const float2*)&lnb[cc];
        *(float2*)&out[rl * Hn + cc] = make_float2(
            (c[nt][0] - mu_lo) * iv_lo * g.x + be.x,
            (c[nt][1] - mu_lo) * iv_lo * g.y + be.y);
        *(float2*)&out[rh * Hn + cc] = make_float2(
            (c[nt][2] - mu_hi) * iv_hi * g.x + be.x,
            (c[nt][3] - mu_hi) * iv_hi * g.y + be.y);
    }
}

// ---------------- K4: interval prediction head ---------------------------
__global__ __launch_bounds__(256) void pred_kernel(
    const float* __restrict__ hs, const int* __restrict__ slen,
    const float* __restrict__ Wt, const float* __restrict__ bt,
    float* __restrict__ out)
{
    __shared__ float red[256];
    const int b = blockIdx.x;
    const int t = threadIdx.x;
    const int len = slen[b];
    const float* e1 = hs + ((size_t)b * Ln + (len - 1)) * Hn;
    const float* e2 = hs + ((size_t)b * Ln + (len - 2)) * Hn;
    red[t] = Wt[t] * e1[t] + Wt[Hn + t] * e2[t];
    __syncthreads();
    for (int s = 128; s > 0; s >>= 1) {
        if (t < s) red[t] += red[t + s];
        __syncthreads();
    }
    if (t == 0) out[(size_t)Bn * Ln * Hn + b] = red[0] + bt[0];
}

// ---------------- launch --------------------------------------------------
extern "C" void kernel_launch(void* const* d_in, const int* in_sizes, int n_in,
                              void* d_out, int out_size)
{
    const float* x    = (const float*)d_in[0];
    const float* tseq = (const float*)d_in[1];
    const float* mask = (const float*)d_in[2];
    const int*   slen = (const int*)d_in[3];
    const float* Wq   = (const float*)d_in[4];
    const float* bq   = (const float*)d_in[5];
    const float* Wk   = (const float*)d_in[6];
    const float* bk   = (const float*)d_in[7];
    const float* Wv   = (const float*)d_in[8];
    const float* bv   = (const float*)d_in[9];
    const float* Wd   = (const float*)d_in[10];
    const float* bd   = (const float*)d_in[11];
    const float* lng  = (const float*)d_in[12];
    const float* lnb  = (const float*)d_in[13];
    const float* Wtq  = (const float*)d_in[14];
    const float* btq  = (const float*)d_in[15];
    const float* tw1  = (const float*)d_in[16];
    const float* tb1  = (const float*)d_in[17];
    const float* tow1 = (const float*)d_in[18];
    const float* tow2 = (const float*)d_in[19];
    const float* tob  = (const float*)d_in[20];
    const float* Wt   = (const float*)d_in[21];
    const float* bt   = (const float*)d_in[22];
    float* out = (float*)d_out;

    static const int OUTLN_SMEM = (4608 + 18432) * 4;  // 92160 B dynamic
    cudaFuncSetAttribute(outln_mma, cudaFuncAttributeMaxDynamicSharedMemorySize, OUTLN_SMEM);

    cvt_all<<<(XN4 + WN4 + 255) / 256, 256>>>(
        (const float4*)x, (const float4*)Wq, (const float4*)Wk,
        (const float4*)Wv, (const float4*)Wtq, (const float4*)Wd);
    proj_tq<<<dim3(Bn * Ln / 64, 4), 128>>>(btq);
    fused_gate_qkv<<<GATE_BLKS + 3072, 128>>>(
        tseq, tw1, tb1, tow1, tow2, tob, mask, bq, bk, bv);
    attn_mma<<<dim3(Ln / 64, NHn, Bn), 128>>>();
    outln_mma<<<dim3(Bn * Ln / 64), 512, OUTLN_SMEM>>>(x, bd, lng, lnb, out);
    pred_kernel<<<dim3(Bn), 256>>>(out, slen, Wt, bt, out);
}

// round 12
// speedup vs baseline: 4.4791x; 1.2836x over previous
#include <cuda_runtime.h>
#include <cuda_bf16.h>

#define Bn 32
#define Ln 512
#define Hn 256
#define NHn 4
#define DHn 64

// ---------------- scratch (device globals; no allocation) ----------------
// all GEMM operands stored as bf16 pairs: [row][128 pairs] (row = token or weight-row)
__device__ __align__(16) unsigned g_xbf[Bn * Ln * 128];         // x bf16 pairs
__device__ __align__(16) unsigned g_wbf[5 * Hn * 128];          // Wq,Wk,Wv,Wtq,Wd bf16 pairs
__device__ __align__(16) unsigned g_q16[Bn * Ln * 128];         // q bf16 pairs
__device__ __align__(16) unsigned g_k16[Bn * Ln * 128];         // k bf16 pairs
__device__ __align__(16) __nv_bfloat16 g_vt16[Bn * NHn * DHn * Ln]; // V^T [b,h][d][token]
__device__ __align__(16) unsigned g_tq16[Bn * Ln * 128];        // tq bf16 pairs
__device__ __align__(16) unsigned g_gm[Bn * Ln * Ln];           // bf16x2 {gate/8, mask}
__device__ __align__(16) unsigned g_ctx16[Bn * Ln * 128];       // ctx bf16 pairs

// ---------------- helpers --------------------------------------------
__device__ __forceinline__ float tanh_ap(float x) {
    float y;
    asm("tanh.approx.f32 %0, %1;" : "=f"(y) : "f"(x));
    return y;
}
__device__ __forceinline__ unsigned packbf(float lo, float hi) {
    __nv_bfloat162 p = __floats2bfloat162_rn(lo, hi);
    return *(unsigned*)&p;
}
__device__ __forceinline__ void cpa16(void* s, const void* g) {
    unsigned sa = (unsigned)__cvta_generic_to_shared(s);
    asm volatile("cp.async.cg.shared.global [%0], [%1], 16;" :: "r"(sa), "l"(g));
}
#define CP_COMMIT()  asm volatile("cp.async.commit_group;")
#define CP_WAIT1()   asm volatile("cp.async.wait_group 1;")
#define CP_WAIT0()   asm volatile("cp.async.wait_group 0;")

__device__ __forceinline__ void mma_bf16(float* c, const unsigned* a, const unsigned* b) {
    asm volatile(
        "mma.sync.aligned.m16n8k16.row.col.f32.bf16.bf16.f32 "
        "{%0,%1,%2,%3}, {%4,%5,%6,%7}, {%8,%9}, {%0,%1,%2,%3};\n"
        : "+f"(c[0]), "+f"(c[1]), "+f"(c[2]), "+f"(c[3])
        : "r"(a[0]), "r"(a[1]), "r"(a[2]), "r"(a[3]), "r"(b[0]), "r"(b[1]));
}

// 64x64x256 bf16 GEMM mainloop, cp.async double buffered.
// A/B: [row][128 pairs] layout. 4 chunks of 32 pairs (64 elements).
__device__ __forceinline__ void gemm_bf16(
    const unsigned* __restrict__ Ag, const unsigned* __restrict__ Bg,
    int m0, int n0, int t, int wm, int gid, int tig,
    unsigned (*As)[64][36], unsigned (*Bs)[64][36], float c[8][4])
{
#pragma unroll
    for (int u = 0; u < 4; ++u) {
        int f = t + 128 * u;
        int row = f >> 3;
        int ch = (f & 7) * 4;
        cpa16(&As[0][row][ch], &Ag[(size_t)(m0 + row) * 128 + ch]);
        cpa16(&Bs[0][row][ch], &Bg[(size_t)(n0 + row) * 128 + ch]);
    }
    CP_COMMIT();

    for (int i = 0; i < 4; ++i) {
        const int buf = i & 1;
        if (i < 3) {
            const int p1 = (i + 1) * 32;   // pair offset of next chunk
            const int nb = buf ^ 1;
#pragma unroll
            for (int u = 0; u < 4; ++u) {
                int f = t + 128 * u;
                int row = f >> 3;
                int ch = (f & 7) * 4;
                cpa16(&As[nb][row][ch], &Ag[(size_t)(m0 + row) * 128 + p1 + ch]);
                cpa16(&Bs[nb][row][ch], &Bg[(size_t)(n0 + row) * 128 + p1 + ch]);
            }
            CP_COMMIT();
            CP_WAIT1();
        } else {
            CP_WAIT0();
        }
        __syncthreads();
#pragma unroll
        for (int ks = 0; ks < 4; ++ks) {
            unsigned a[4];
            a[0] = As[buf][wm + gid][ks * 8 + tig];
            a[1] = As[buf][wm + gid + 8][ks * 8 + tig];
            a[2] = As[buf][wm + gid][ks * 8 + 4 + tig];
            a[3] = As[buf][wm + gid + 8][ks * 8 + 4 + tig];
#pragma unroll
            for (int nt = 0; nt < 8; ++nt) {
                unsigned b[2];
                b[0] = Bs[buf][nt * 8 + gid][ks * 8 + tig];
                b[1] = Bs[buf][nt * 8 + gid][ks * 8 + 4 + tig];
                mma_bf16(c[nt], a, b);
            }
        }
        __syncthreads();
    }
}

// ---------------- K-1: fused pre-convert fp32 -> bf16 pairs ---------------
#define XN4 (Bn * Ln * Hn / 4)     // 1048576 float4s
#define WN4 (5 * Hn * Hn / 4)      // 81920 float4s
__global__ __launch_bounds__(256) void cvt_all(
    const float4* __restrict__ x,
    const float4* __restrict__ Wq, const float4* __restrict__ Wk,
    const float4* __restrict__ Wv, const float4* __restrict__ Wtq,
    const float4* __restrict__ Wd)
{
    int i = blockIdx.x * 256 + threadIdx.x;
    if (i < XN4) {
        float4 v = x[i];
        ((uint2*)g_xbf)[i] = make_uint2(packbf(v.x, v.y), packbf(v.z, v.w));
    } else {
        int j = i - XN4;
        if (j < WN4) {
            int m = j >> 14, r = j & 16383;
            const float4* src = m == 0 ? Wq : m == 1 ? Wk : m == 2 ? Wv : m == 3 ? Wtq : Wd;
            float4 v = src[r];
            ((uint2*)g_wbf)[j] = make_uint2(packbf(v.x, v.y), packbf(v.z, v.w));
        }
    }
}

// ---------------- K0a: TQ projection (critical path for gate) -------------
__global__ __launch_bounds__(128) void proj_tq(const float* __restrict__ btq)
{
    __shared__ unsigned As[2][64][36];
    __shared__ unsigned Bs[2][64][36];
    const int t = threadIdx.x;
    const int lane = t & 31, warp = t >> 5;
    const int gid = lane >> 2, tig = lane & 3;
    const int m0 = blockIdx.x * 64;
    const int n0 = blockIdx.y * 64;
    const int wm = warp * 16;

    float c[8][4] = {};
    gemm_bf16(g_xbf, g_wbf + 3 * Hn * 128, m0, n0, t, wm, gid, tig, As, Bs, c);

    const int r0 = m0 + wm + gid, r1 = r0 + 8;
#pragma unroll
    for (int nt = 0; nt < 8; ++nt) {
        int cc = n0 + nt * 8 + 2 * tig;
        float2 bb = *(const float2*)&btq[cc];
        g_tq16[(size_t)r0 * 128 + (cc >> 1)] = packbf(c[nt][0] + bb.x, c[nt][1] + bb.y);
        g_tq16[(size_t)r1 * 128 + (cc >> 1)] = packbf(c[nt][2] + bb.x, c[nt][3] + bb.y);
    }
}

// ---------------- K0b: fused gate + Q/K/V projection ----------------------
#define GATE_BLKS 2048
__global__ __launch_bounds__(128) void fused_gate_qkv(
    const float* __restrict__ tseq,
    const float* __restrict__ tw1, const float* __restrict__ tb1,
    const float* __restrict__ tow1, const float* __restrict__ tow2,
    const float* __restrict__ tob, const float* __restrict__ mask,
    const float* __restrict__ bq, const float* __restrict__ bk,
    const float* __restrict__ bv)
{
    __shared__ unsigned As[2][64][36];
    __shared__ unsigned Bs[2][64][36];
    const int t = threadIdx.x;
    const int lane = t & 31, warp = t >> 5;
    const int gid = lane >> 2, tig = lane & 3;
    const int wm = warp * 16;
    const int bid = blockIdx.x;

    float c[8][4] = {};

    if (bid < GATE_BLKS) {
        // ---------------- gate path ----------------
        const int b = bid >> 6;
        const int rem = bid & 63;
        const int m0 = (rem >> 3) * 64;
        const int n0 = (rem & 7) * 64;
        gemm_bf16(g_tq16 + (size_t)b * Ln * 128, g_xbf + (size_t)b * Ln * 128,
                  m0, n0, t, wm, gid, tig, As, Bs, c);

        const int rl = m0 + wm + gid, rh = rl + 8;
        const float t_lo = tseq[b * Ln + rl];
        const float t_hi = tseq[b * Ln + rh];
        const float* mptr = mask + (size_t)b * Ln * Ln;
        unsigned* gout = g_gm + (size_t)b * Ln * Ln;

#pragma unroll
        for (int nt = 0; nt < 8; ++nt) {
            int cc = n0 + nt * 8 + 2 * tig;
            float2 tc = *(const float2*)&tseq[b * Ln + cc];
#pragma unroll
            for (int half = 0; half < 2; ++half) {
                int r = half ? rh : rl;
                float tr = half ? t_hi : t_lo;
                size_t idx = (size_t)r * Ln + cc;
                float2 w1 = *(const float2*)&tw1[idx];
                float2 b1 = *(const float2*)&tb1[idx];
                float2 o1 = *(const float2*)&tow1[idx];
                float2 o2 = *(const float2*)&tow2[idx];
                float2 ob = *(const float2*)&tob[idx];
                float2 mm = *(const float2*)&mptr[idx];
                float s0 = c[nt][half * 2 + 0], s1 = c[nt][half * 2 + 1];
                float tqk0 = tanh_ap(s0), tqk1 = tanh_ap(s1);
                float d0 = tanh_ap(__logf(1.0f + fabsf(tr - tc.x)) * w1.x + b1.x);
                float d1 = tanh_ap(__logf(1.0f + fabsf(tr - tc.y)) * w1.y + b1.y);
                float g0 = o1.x * d0 + o2.x * tqk0 + ob.x;
                float g1 = o1.y * d1 + o2.y * tqk1 + ob.y;
                g0 = 0.125f / (1.0f + __expf(-g0));
                g1 = 0.125f / (1.0f + __expf(-g1));
                __nv_bfloat162 p0 = __floats2bfloat162_rn(g0, mm.x);
                __nv_bfloat162 p1 = __floats2bfloat162_rn(g1, mm.y);
                *(uint2*)&gout[idx] = make_uint2(*(unsigned*)&p0, *(unsigned*)&p1);
            }
        }
    } else {
        // ---------------- Q/K/V projection path ----------------
        const int pid = bid - GATE_BLKS;
        const int mt = pid / 12, combo = pid % 12;
        const int wsel = combo >> 2;
        const int m0 = mt * 64;
        const int n0 = (combo & 3) * 64;
        const float* bias = wsel == 0 ? bq : wsel == 1 ? bk : bv;

        gemm_bf16(g_xbf, g_wbf + (size_t)wsel * Hn * 128,
                  m0, n0, t, wm, gid, tig, As, Bs, c);

        const int r0 = m0 + wm + gid, r1 = r0 + 8;
        if (wsel < 2) {
            unsigned* out16 = wsel == 0 ? g_q16 : g_k16;
#pragma unroll
            for (int nt = 0; nt < 8; ++nt) {
                int cc = n0 + nt * 8 + 2 * tig;
                float2 bb = *(const float2*)&bias[cc];
                out16[(size_t)r0 * 128 + (cc >> 1)] = packbf(c[nt][0] + bb.x, c[nt][1] + bb.y);
                out16[(size_t)r1 * 128 + (cc >> 1)] = packbf(c[nt][2] + bb.x, c[nt][3] + bb.y);
            }
        } else {
            // V: write transposed bf16 [b,h][d][token]
            const int bb0 = r0 >> 9;              // batch
            const int tk0 = r0 & 511;             // token within batch
#pragma unroll
            for (int nt = 0; nt < 8; ++nt) {
                int cc = n0 + nt * 8 + 2 * tig;
                float2 bbv = *(const float2*)&bias[cc];
                int hh = cc >> 6, dl = cc & 63;
                size_t base = ((size_t)(bb0 * NHn + hh) * DHn + dl) * Ln + tk0;
                g_vt16[base]           = __float2bfloat16(c[nt][0] + bbv.x);
                g_vt16[base + Ln]      = __float2bfloat16(c[nt][1] + bbv.y);
                g_vt16[base + 8]       = __float2bfloat16(c[nt][2] + bbv.x);
                g_vt16[base + Ln + 8]  = __float2bfloat16(c[nt][3] + bbv.y);
            }
        }
    }
}

// ---------------- K2: fused attention (bf16 tensor, cp.async pipelined) ---
__global__ __launch_bounds__(128) void attn_mma()
{
    __shared__ unsigned Qs[64][36];      // Q bf16 pairs [q][dpair]
    __shared__ unsigned Ks[2][64][36];   // K bf16 pairs, double buffered
    __shared__ unsigned Vp[2][64][36];   // V^T bf16 pairs, double buffered
    __shared__ unsigned Gm[64][68];      // gate/mask tile, single buffer

    const int t = threadIdx.x;
    const int lane = t & 31, warp = t >> 5;
    const int gid = lane >> 2, tig = lane & 3;
    const int qt = blockIdx.x, h = blockIdx.y, b = blockIdx.z;
    const int q0 = qt * 64;
    const int wm = warp * 16;

    const unsigned* qptr = g_q16 + (size_t)b * Ln * 128 + h * 32;
    const unsigned* kptr = g_k16 + (size_t)b * Ln * 128 + h * 32;
    const unsigned* vtp = (const unsigned*)(g_vt16 + ((size_t)(b * NHn + h)) * DHn * Ln);
    const unsigned* gptr = g_gm + (size_t)b * Ln * Ln;

    // load Q tile: 64 rows x 32 pairs
#pragma unroll
    for (int u = 0; u < 4; ++u) {
        int f = t + 128 * u;
        int row = f >> 3;
        int ch = (f & 7) * 4;
        *(uint4*)&Qs[row][ch] = *(const uint4*)&qptr[(size_t)(q0 + row) * 128 + ch];
    }

    // prologue: KV tile 0 via cp.async
#pragma unroll
    for (int u = 0; u < 4; ++u) {
        int f = t + 128 * u;
        int row = f >> 3;
        int ch = (f & 7) * 4;
        cpa16(&Ks[0][row][ch], &kptr[(size_t)row * 128 + ch]);
        cpa16(&Vp[0][row][ch], &vtp[(size_t)row * 256 + ch]);
    }
    CP_COMMIT();
    __syncthreads();

    unsigned qf[4][4];
#pragma unroll
    for (int ks = 0; ks < 4; ++ks) {
        qf[ks][0] = Qs[wm + gid][ks * 8 + tig];
        qf[ks][1] = Qs[wm + gid + 8][ks * 8 + tig];
        qf[ks][2] = Qs[wm + gid][ks * 8 + 4 + tig];
        qf[ks][3] = Qs[wm + gid + 8][ks * 8 + 4 + tig];
    }

    float o[8][4] = {};
    float m_lo = -1e30f, m_hi = -1e30f, l_lo = 0.f, l_hi = 0.f;
    const int rl = q0 + wm + gid, rh = rl + 8;
    const int lrl = wm + gid, lrh = lrl + 8;

    for (int kb = 0; kb < 8; ++kb) {
        const int c0 = kb * 64;
        const int buf = kb & 1;

        // gate/mask tile for THIS kb (own group)
#pragma unroll
        for (int u = 0; u < 8; ++u) {
            int f = t + 128 * u;
            int row = f >> 4;
            int seg = (f & 15) * 4;
            cpa16(&Gm[row][seg], &gptr[(size_t)(q0 + row) * Ln + c0 + seg]);
        }
        CP_COMMIT();

        if (kb < 7) {
            const int c1 = c0 + 64;
            const int nb = buf ^ 1;
#pragma unroll
            for (int u = 0; u < 4; ++u) {
                int f = t + 128 * u;
                int row = f >> 3;
                int ch = (f & 7) * 4;
                cpa16(&Ks[nb][row][ch], &kptr[(size_t)(c1 + row) * 128 + ch]);
                cpa16(&Vp[nb][row][ch], &vtp[(size_t)row * 256 + (c1 >> 1) + ch]);
            }
            CP_COMMIT();
            CP_WAIT1();
        } else {
            CP_WAIT0();
        }
        __syncthreads();

        // S = Q @ K^T
        float s[8][4] = {};
#pragma unroll
        for (int ks = 0; ks < 4; ++ks) {
#pragma unroll
            for (int nt = 0; nt < 8; ++nt) {
                unsigned bfr[2];
                bfr[0] = Ks[buf][nt * 8 + gid][ks * 8 + tig];
                bfr[1] = Ks[buf][nt * 8 + gid][ks * 8 + 4 + tig];
                mma_bf16(s[nt], qf[ks], bfr);
            }
        }

        // epilogue: s*gate + mask (from smem)
#pragma unroll
        for (int nt = 0; nt < 8; ++nt) {
            int cl = nt * 8 + 2 * tig;
            uint2 pl = *(const uint2*)&Gm[lrl][cl];
            uint2 ph = *(const uint2*)&Gm[lrh][cl];
            float2 e0 = __bfloat1622float2(*(__nv_bfloat162*)&pl.x);
            float2 e1 = __bfloat1622float2(*(__nv_bfloat162*)&pl.y);
            float2 e2 = __bfloat1622float2(*(__nv_bfloat162*)&ph.x);
            float2 e3 = __bfloat1622float2(*(__nv_bfloat162*)&ph.y);
            s[nt][0] = s[nt][0] * e0.x + e0.y;
            s[nt][1] = s[nt][1] * e1.x + e1.y;
            s[nt][2] = s[nt][2] * e2.x + e2.y;
            s[nt][3] = s[nt][3] * e3.x + e3.y;
        }

        // online softmax
        float mx_lo = -1e30f, mx_hi = -1e30f;
#pragma unroll
        for (int nt = 0; nt < 8; ++nt) {
            mx_lo = fmaxf(mx_lo, fmaxf(s[nt][0], s[nt][1]));
            mx_hi = fmaxf(mx_hi, fmaxf(s[nt][2], s[nt][3]));
        }
        mx_lo = fmaxf(mx_lo, __shfl_xor_sync(0xffffffffu, mx_lo, 1));
        mx_lo = fmaxf(mx_lo, __shfl_xor_sync(0xffffffffu, mx_lo, 2));
        mx_hi = fmaxf(mx_hi, __shfl_xor_sync(0xffffffffu, mx_hi, 1));
        mx_hi = fmaxf(mx_hi, __shfl_xor_sync(0xffffffffu, mx_hi, 2));
        float mn_lo = fmaxf(m_lo, mx_lo), mn_hi = fmaxf(m_hi, mx_hi);
        float sc_lo = __expf(m_lo - mn_lo), sc_hi = __expf(m_hi - mn_hi);
        m_lo = mn_lo; m_hi = mn_hi;
        float rs_lo = 0.f, rs_hi = 0.f;
#pragma unroll
        for (int nt = 0; nt < 8; ++nt) {
            s[nt][0] = __expf(s[nt][0] - mn_lo);
            s[nt][1] = __expf(s[nt][1] - mn_lo);
            s[nt][2] = __expf(s[nt][2] - mn_hi);
            s[nt][3] = __expf(s[nt][3] - mn_hi);
            rs_lo += s[nt][0] + s[nt][1];
            rs_hi += s[nt][2] + s[nt][3];
        }
        rs_lo += __shfl_xor_sync(0xffffffffu, rs_lo, 1);
        rs_lo += __shfl_xor_sync(0xffffffffu, rs_lo, 2);
        rs_hi += __shfl_xor_sync(0xffffffffu, rs_hi, 1);
        rs_hi += __shfl_xor_sync(0xffffffffu, rs_hi, 2);
        l_lo = l_lo * sc_lo + rs_lo;
        l_hi = l_hi * sc_hi + rs_hi;
#pragma unroll
        for (int dt = 0; dt < 8; ++dt) {
            o[dt][0] *= sc_lo; o[dt][1] *= sc_lo;
            o[dt][2] *= sc_hi; o[dt][3] *= sc_hi;
        }

        // O += P @ V
#pragma unroll
        for (int ks = 0; ks < 4; ++ks) {
            unsigned pa[4];
            pa[0] = packbf(s[2 * ks][0], s[2 * ks][1]);
            pa[1] = packbf(s[2 * ks][2], s[2 * ks][3]);
            pa[2] = packbf(s[2 * ks + 1][0], s[2 * ks + 1][1]);
            pa[3] = packbf(s[2 * ks + 1][2], s[2 * ks + 1][3]);
#pragma unroll
            for (int dt = 0; dt < 8; ++dt) {
                unsigned bfr[2];
                bfr[0] = Vp[buf][dt * 8 + gid][ks * 8 + tig];
                bfr[1] = Vp[buf][dt * 8 + gid][ks * 8 + 4 + tig];
                mma_bf16(o[dt], pa, bfr);
            }
        }
        __syncthreads();
    }

    // write ctx as bf16 pairs (consumed by outln's bf16 mma)
    float inv_lo = 1.0f / l_lo, inv_hi = 1.0f / l_hi;
    unsigned* cbase = g_ctx16 + (size_t)b * Ln * 128;
#pragma unroll
    for (int dt = 0; dt < 8; ++dt) {
        int pcol = h * 32 + dt * 4 + tig;
        cbase[(size_t)rl * 128 + pcol] = packbf(o[dt][0] * inv_lo, o[dt][1] * inv_lo);
        cbase[(size_t)rh * 128 + pcol] = packbf(o[dt][2] * inv_hi, o[dt][3] * inv_hi);
    }
}

// ---------------- K3: output projection + residual + layernorm ------------
__global__ __launch_bounds__(512) void outln_mma(
    const float* __restrict__ x, const float* __restrict__ bd,
    const float* __restrict__ lng, const float* __restrict__ lnb,
    float* __restrict__ out)
{
    extern __shared__ unsigned dsm[];
    unsigned* As = dsm;             // 2 * 64 * 36  = 4608
    unsigned* Bs = dsm + 4608;      // 2 * 256 * 36 = 18432
    __shared__ float redS[64][4];
    __shared__ float redQ[64][4];

    const int t = threadIdx.x;
    const int lane = t & 31, warp = t >> 5;
    const int gid = lane >> 2, tig = lane & 3;
    const int m0 = blockIdx.x * 64;
    const int mg = warp >> 2;
    const int nq = warp & 3;
    const int wm = mg * 16;
    const int wn = nq * 64;
    const unsigned* Wd = g_wbf + 4 * Hn * 128;

    float c[8][4] = {};

    {
        int row = t >> 3, ch = (t & 7) * 4;
        cpa16(&As[row * 36 + ch], &g_ctx16[(size_t)(m0 + row) * 128 + ch]);
#pragma unroll
        for (int u = 0; u < 4; ++u) {
            int f = t + 512 * u;
            int r2 = f >> 3, c2 = (f & 7) * 4;
            cpa16(&Bs[r2 * 36 + c2], &Wd[(size_t)r2 * 128 + c2]);
        }
        CP_COMMIT();
    }

    for (int i = 0; i < 4; ++i) {
        const int buf = i & 1;
        if (i < 3) {
            const int p1 = (i + 1) * 32;
            const int nb = buf ^ 1;
            int row = t >> 3, ch = (t & 7) * 4;
            cpa16(&As[nb * 2304 + row * 36 + ch], &g_ctx16[(size_t)(m0 + row) * 128 + p1 + ch]);
#pragma unroll
            for (int u = 0; u < 4; ++u) {
                int f = t + 512 * u;
                int r2 = f >> 3, c2 = (f & 7) * 4;
                cpa16(&Bs[nb * 9216 + r2 * 36 + c2], &Wd[(size_t)r2 * 128 + p1 + c2]);
            }
            CP_COMMIT();
            CP_WAIT1();
        } else {
            CP_WAIT0();
        }
        __syncthreads();
#pragma unroll
        for (int ks = 0; ks < 4; ++ks) {
            unsigned a[4];
            a[0] = As[buf * 2304 + (wm + gid) * 36 + ks * 8 + tig];
            a[1] = As[buf * 2304 + (wm + gid + 8) * 36 + ks * 8 + tig];
            a[2] = As[buf * 2304 + (wm + gid) * 36 + ks * 8 + 4 + tig];
            a[3] = As[buf * 2304 + (wm + gid + 8) * 36 + ks * 8 + 4 + tig];
#pragma unroll
            for (int nt = 0; nt < 8; ++nt) {
                unsigned bfr[2];
                bfr[0] = Bs[buf * 9216 + (wn + nt * 8 + gid) * 36 + ks * 8 + tig];
                bfr[1] = Bs[buf * 9216 + (wn + nt * 8 + gid) * 36 + ks * 8 + 4 + tig];
                mma_bf16(c[nt], a, bfr);
            }
        }
        __syncthreads();
    }

    const int lrl = wm + gid, lrh = lrl + 8;
    const size_t rl = m0 + lrl, rh = m0 + lrh;
    float s_lo = 0.f, s_hi = 0.f, q_lo = 0.f, q_hi = 0.f;
#pragma unroll
    for (int nt = 0; nt < 8; ++nt) {
        int cc = wn + nt * 8 + 2 * tig;
        float2 bb = *(const float2*)&bd[cc];
        float2 xl = *(const float2*)&x[rl * Hn + cc];
        float2 xh = *(const float2*)&x[rh * Hn + cc];
        c[nt][0] += bb.x + xl.x; c[nt][1] += bb.y + xl.y;
        c[nt][2] += bb.x + xh.x; c[nt][3] += bb.y + xh.y;
        s_lo += c[nt][0] + c[nt][1];
        s_hi += c[nt][2] + c[nt][3];
        q_lo += c[nt][0] * c[nt][0] + c[nt][1] * c[nt][1];
        q_hi += c[nt][2] * c[nt][2] + c[nt][3] * c[nt][3];
    }
    s_lo += __shfl_xor_sync(0xffffffffu, s_lo, 1);
    s_lo += __shfl_xor_sync(0xffffffffu, s_lo, 2);
    s_hi += __shfl_xor_sync(0xffffffffu, s_hi, 1);
    s_hi += __shfl_xor_sync(0xffffffffu, s_hi, 2);
    q_lo += __shfl_xor_sync(0xffffffffu, q_lo, 1);
    q_lo += __shfl_xor_sync(0xffffffffu, q_lo, 2);
    q_hi += __shfl_xor_sync(0xffffffffu, q_hi, 1);
    q_hi += __shfl_xor_sync(0xffffffffu, q_hi, 2);
    __syncthreads();
    if (tig == 0) {
        redS[lrl][nq] = s_lo; redQ[lrl][nq] = q_lo;
        redS[lrh][nq] = s_hi; redQ[lrh][nq] = q_hi;
    }
    __syncthreads();
    float mu_lo = (redS[lrl][0] + redS[lrl][1] + redS[lrl][2] + redS[lrl][3]) * (1.0f / Hn);
    float mu_hi = (redS[lrh][0] + redS[lrh][1] + redS[lrh][2] + redS[lrh][3]) * (1.0f / Hn);
    float ex_lo = (redQ[lrl][0] + redQ[lrl][1] + redQ[lrl][2] + redQ[lrl][3]) * (1.0f / Hn);
    float ex_hi = (redQ[lrh][0] + redQ[lrh][1] + redQ[lrh][2] + redQ[lrh][3]) * (1.0f / Hn);
    float iv_lo = rsqrtf(ex_lo - mu_lo * mu_lo + 1e-12f);
    float iv_hi = rsqrtf(ex_hi - mu_hi * mu_hi + 1e-12f);

#pragma unroll
    for (int nt = 0; nt < 8; ++nt) {
        int cc = wn + nt * 8 + 2 * tig;
        float2 g = *(const float2*)&lng[cc];
        float2 be = *(const float2*)&lnb[cc];
        *(float2*)&out[rl * Hn + cc] = make_float2(
            (c[nt][0] - mu_lo) * iv_lo * g.x + be.x,
            (c[nt][1] - mu_lo) * iv_lo * g.y + be.y);
        *(float2*)&out[rh * Hn + cc] = make_float2(
            (c[nt][2] - mu_hi) * iv_hi * g.x + be.x,
            (c[nt][3] - mu_hi) * iv_hi * g.y + be.y);
    }
}

// ---------------- K4: interval prediction head ---------------------------
__global__ __launch_bounds__(256) void pred_kernel(
    const float* __restrict__ hs, const int* __restrict__ slen,
    const float* __restrict__ Wt, const float* __restrict__ bt,
    float* __restrict__ out)
{
    __shared__ float red[256];
    const int b = blockIdx.x;
    const int t = threadIdx.x;
    const int len = slen[b];
    const float* e1 = hs + ((size_t)b * Ln + (len - 1)) * Hn;
    const float* e2 = hs + ((size_t)b * Ln + (len - 2)) * Hn;
    red[t] = Wt[t] * e1[t] + Wt[Hn + t] * e2[t];
    __syncthreads();
    for (int s = 128; s > 0; s >>= 1) {
        if (t < s) red[t] += red[t + s];
        __syncthreads();
    }
    if (t == 0) out[(size_t)Bn * Ln * Hn + b] = red[0] + bt[0];
}

// ---------------- launch --------------------------------------------------
extern "C" void kernel_launch(void* const* d_in, const int* in_sizes, int n_in,
                              void* d_out, int out_size)
{
    const float* x    = (const float*)d_in[0];
    const float* tseq = (const float*)d_in[1];
    const float* mask = (const float*)d_in[2];
    const int*   slen = (const int*)d_in[3];
    const float* Wq   = (const float*)d_in[4];
    const float* bq   = (const float*)d_in[5];
    const float* Wk   = (const float*)d_in[6];
    const float* bk   = (const float*)d_in[7];
    const float* Wv   = (const float*)d_in[8];
    const float* bv   = (const float*)d_in[9];
    const float* Wd   = (const float*)d_in[10];
    const float* bd   = (const float*)d_in[11];
    const float* lng  = (const float*)d_in[12];
    const float* lnb  = (const float*)d_in[13];
    const float* Wtq  = (const float*)d_in[14];
    const float* btq  = (const float*)d_in[15];
    const float* tw1  = (const float*)d_in[16];
    const float* tb1  = (const float*)d_in[17];
    const float* tow1 = (const float*)d_in[18];
    const float* tow2 = (const float*)d_in[19];
    const float* tob  = (const float*)d_in[20];
    const float* Wt   = (const float*)d_in[21];
    const float* bt   = (const float*)d_in[22];
    float* out = (float*)d_out;

    static const int OUTLN_SMEM = (4608 + 18432) * 4;  // 92160 B dynamic
    cudaFuncSetAttribute(outln_mma, cudaFuncAttributeMaxDynamicSharedMemorySize, OUTLN_SMEM);

    cvt_all<<<(XN4 + WN4 + 255) / 256, 256>>>(
        (const float4*)x, (const float4*)Wq, (const float4*)Wk,
        (const float4*)Wv, (const float4*)Wtq, (const float4*)Wd);
    proj_tq<<<dim3(Bn * Ln / 64, 4), 128>>>(btq);
    fused_gate_qkv<<<GATE_BLKS + 3072, 128>>>(
        tseq, tw1, tb1, tow1, tow2, tob, mask, bq, bk, bv);
    attn_mma<<<dim3(Ln / 64, NHn, Bn), 128>>>();
    outln_mma<<<dim3(Bn * Ln / 64), 512, OUTLN_SMEM>>>(x, bd, lng, lnb, out);
    pred_kernel<<<dim3(Bn), 256>>>(out, slen, Wt, bt, out);
}